// round 11
// baseline (speedup 1.0000x reference)
#include <cuda_runtime.h>
#include <cstdint>

// ---------------------------------------------------------------------------
// Problem constants
// ---------------------------------------------------------------------------
#define TT     16
#define NN     20000
#define NP     20096            // NN padded to multiple of 128 (157*128)
#define NG     32               // 32 (t, graph) pairs total
#define NGP    16               // graph-instances per SAGE pass
#define EE     320000
#define PP     4096
#define DIN    128
#define HH     256
#define NHEAD  8
#define NLAY   2
#define FF     2048
#define DM     512
#define HD     64
#define NTOK   (TT * PP)     // 65536
#define HB     (NGP * NP)    // 321536 rows per SAGE pass

// ---------------------------------------------------------------------------
// Scratch blobs (no allocations; keep total .bss < 4GB for aarch64 ADRP).
// ---------------------------------------------------------------------------
constexpr size_t S_H1   = 0;
constexpr size_t S_BUFB = (size_t)HB * 256;
constexpr size_t S_BUFA = S_BUFB;                       // alias (disjoint lifetime)
constexpr size_t S_H2   = 0;                            // alias (disjoint lifetime)
constexpr size_t S_TOTAL= (size_t)HB * 768;             // ~0.99 GB
__device__ float g_sage[S_TOTAL];

// weights region
constexpr size_t W_WC1   = 0;                          // [256,256] stacked fp32
constexpr size_t W_WC2   = W_WC1  + 256ull * 256;      // [512,256]
constexpr size_t W_WQKV  = W_WC2  + 512ull * 256;      // [2,512,1536] tf32-rounded
constexpr size_t W_BQKV  = W_WQKV + 2ull * 512 * 1536; // [2,1536] fp32
constexpr size_t W_WO    = W_BQKV + 2ull * 1536;       // [2,512,512] tf32-rounded
constexpr size_t W_WF1   = W_WO   + 2ull * 512 * 512;  // [2,512,2048] tf32-rounded
constexpr size_t W_WF2   = W_WF1  + 2ull * 512 * 2048; // [2,2048,512] tf32-rounded
constexpr size_t W_TOTAL = W_WF2  + 2ull * 2048 * 512;
__device__ float g_w[W_TOTAL];

// activations region (~1.34 GB)
constexpr size_t A_H    = 0;                           // [NTOK,512]  fp32 hidden
constexpr size_t A_HT   = A_H   + (size_t)NTOK * 512;  // [NTOK,512]  tf32-rounded hidden
constexpr size_t A_QKV  = A_HT  + (size_t)NTOK * 512;  // [NTOK,1536]
constexpr size_t A_TMP  = A_QKV + (size_t)NTOK * 1536; // [NTOK,512]
constexpr size_t A_FF   = A_TMP + (size_t)NTOK * 512;  // [NTOK,2048]
constexpr size_t A_TOTAL= A_FF  + (size_t)NTOK * 2048;
__device__ float g_act[A_TOTAL];

// CSR int region, batched over all NG graphs (~49 MB)
constexpr size_t I_DEG = 0;
constexpr size_t I_CUR = I_DEG + (size_t)NG * NN;
constexpr size_t I_OFF = I_CUR + (size_t)NG * NN;
constexpr size_t I_CSR = I_OFF + (size_t)NG * (NN + 1);
constexpr size_t I_TOTAL = I_CSR + (size_t)NG * EE;
__device__ int g_iblob[I_TOTAL];

// ---------------------------------------------------------------------------
// numeric helpers
// ---------------------------------------------------------------------------
__device__ __forceinline__ uint32_t f2tf(float f) {
    uint32_t r;
    asm("cvt.rna.tf32.f32 %0, %1;" : "=r"(r) : "f"(f));
    return r;
}

// pack (v0 -> low bf16, v1 -> high bf16) and the bf16 split remainders
__device__ __forceinline__ void bf16_split_pack(float v0, float v1,
                                                uint32_t& hi, uint32_t& lo) {
    uint32_t h;
    asm("cvt.rn.bf16x2.f32 %0, %1, %2;" : "=r"(h) : "f"(v1), "f"(v0));
    float h0 = __uint_as_float(h << 16);
    float h1 = __uint_as_float(h & 0xFFFF0000u);
    hi = h;
    asm("cvt.rn.bf16x2.f32 %0, %1, %2;" : "=r"(lo) : "f"(v1 - h1), "f"(v0 - h0));
}

__device__ __forceinline__ void cp16(uint32_t daddr, const void* src) {
    asm volatile("cp.async.cg.shared.global [%0], [%1], 16;" :: "r"(daddr), "l"(src));
}

// ---------------------------------------------------------------------------
// Batched CSR construction (all NG graphs at once).
// ---------------------------------------------------------------------------
__global__ void hist_b_kernel(const int* __restrict__ dst_i, const int* __restrict__ dst_j,
                              int* __restrict__ deg) {
    int gi = blockIdx.y;
    int t = gi & 15, g = gi >> 4;
    const int* dst = (g == 0 ? dst_i : dst_j) + (size_t)t * EE;
    int* d = deg + (size_t)gi * NN;
    int e = blockIdx.x * blockDim.x + threadIdx.x;
    if (e < EE) atomicAdd(&d[dst[e]], 1);
}

__global__ void __launch_bounds__(1024)
scan_b_kernel(const int* __restrict__ deg_all, int* __restrict__ off_all) {
    __shared__ int wsum[32];
    const int CH = 20;
    int gi = blockIdx.x;
    const int* deg = deg_all + (size_t)gi * NN;
    int* off = off_all + (size_t)gi * (NN + 1);
    int tid = threadIdx.x;
    int lane = tid & 31, warp = tid >> 5;
    int base = tid * CH;
    int loc[CH];
    int s = 0;
#pragma unroll
    for (int i = 0; i < CH; i++) {
        int idx = base + i;
        int v = (idx < NN) ? deg[idx] : 0;
        s += v;
        loc[i] = s;
    }
    int ssum = s;
#pragma unroll
    for (int o = 1; o < 32; o <<= 1) {
        int t = __shfl_up_sync(0xffffffffu, ssum, o);
        if (lane >= o) ssum += t;
    }
    if (lane == 31) wsum[warp] = ssum;
    __syncthreads();
    if (warp == 0) {
        int w = wsum[lane];
#pragma unroll
        for (int o = 1; o < 32; o <<= 1) {
            int t = __shfl_up_sync(0xffffffffu, w, o);
            if (lane >= o) w += t;
        }
        wsum[lane] = w;
    }
    __syncthreads();
    int offset = ssum - s + (warp ? wsum[warp - 1] : 0);
    if (tid == 0) off[0] = 0;
#pragma unroll
    for (int i = 0; i < CH; i++) {
        int idx = base + i;
        if (idx < NN) off[idx + 1] = offset + loc[i];
    }
}

__global__ void fill_b_kernel(const int* __restrict__ src_i, const int* __restrict__ src_j,
                              const int* __restrict__ dst_i, const int* __restrict__ dst_j,
                              const int* __restrict__ off_all, int* __restrict__ cur_all,
                              int* __restrict__ csrc_all) {
    int gi = blockIdx.y;
    int t = gi & 15, g = gi >> 4;
    const int* src = (g == 0 ? src_i : src_j) + (size_t)t * EE;
    const int* dst = (g == 0 ? dst_i : dst_j) + (size_t)t * EE;
    const int* off = off_all + (size_t)gi * (NN + 1);
    int* cur = cur_all + (size_t)gi * NN;
    int* csrc = csrc_all + (size_t)gi * EE;
    int e = blockIdx.x * blockDim.x + threadIdx.x;
    if (e < EE) {
        int d = dst[e];
        int p = atomicAdd(&cur[d], 1);
        csrc[off[d] + p] = src[e];
    }
}

// ---------------------------------------------------------------------------
// Per-pass batched build A = [self | mean_agg].  grid (NN, NGP), blockDim = F.
// ---------------------------------------------------------------------------
template <int LAYER>
__global__ void build_A_b_kernel(const float* __restrict__ x, const float* __restrict__ h1,
                                 int F,
                                 const int* __restrict__ off_all, const int* __restrict__ csrc_all,
                                 float* __restrict__ out_all, int gi0) {
    int tl = blockIdx.y;
    int gi = gi0 + tl;
    const float* feat = (LAYER == 1)
        ? (x + (size_t)tl * NN * DIN)
        : (h1 + (size_t)tl * NP * 256);
    const int* off = off_all + (size_t)gi * (NN + 1);
    const int* csrc = csrc_all + (size_t)gi * EE;
    float* out = out_all + (size_t)tl * NP * (2 * F);

    int n = blockIdx.x;
    int f = threadIdx.x;
    float self = feat[(size_t)n * F + f];
    int s = off[n], e = off[n + 1];
    float acc = 0.f;
    int i = s;
    for (; i + 4 <= e; i += 4) {
        int a0 = csrc[i], a1 = csrc[i + 1], a2 = csrc[i + 2], a3 = csrc[i + 3];
        float v0 = feat[(size_t)a0 * F + f];
        float v1 = feat[(size_t)a1 * F + f];
        float v2 = feat[(size_t)a2 * F + f];
        float v3 = feat[(size_t)a3 * F + f];
        acc += v0 + v1 + v2 + v3;
    }
    for (; i < e; i++) acc += feat[(size_t)csrc[i] * F + f];
    int d = e - s; if (d < 1) d = 1;
    size_t ob = (size_t)n * (2 * F);
    out[ob + f]     = self;
    out[ob + F + f] = acc / (float)d;
}

// ---------------------------------------------------------------------------
// Tensor-core GEMM.  C = A@B + bias (+relu).  128x128x16 block tile,
// 256 threads = 8 warps as 2(m) x 4(n), warp tile 64x32, cp.async dbl-buffered.
// BF16S : bf16 2-way-split (hi/lo) path, 3x m16n8k16 per chunk — SAGE
//         (fp32-comparable accuracy, half the tensor cycles of 3xTF32).
// PRE   : operands already tf32-rounded in gmem — m16n8k8 tf32, no cvt.
// OROUND: round C store to tf32 bits (feeds a later PRE GEMM).
// M,N multiples of 128, K multiple of 16.
// ---------------------------------------------------------------------------
#define AS_STRIDE 20
#define BS_STRIDE 136

#define MMA_TF32(d, a, b)                                                            \
    asm volatile(                                                                    \
        "mma.sync.aligned.m16n8k8.row.col.f32.tf32.tf32.f32 "                        \
        "{%0,%1,%2,%3},{%4,%5,%6,%7},{%8,%9},{%0,%1,%2,%3};"                         \
        : "+f"(d[0]), "+f"(d[1]), "+f"(d[2]), "+f"(d[3])                             \
        : "r"(a[0]), "r"(a[1]), "r"(a[2]), "r"(a[3]), "r"(b[0]), "r"(b[1]))

#define MMA_BF16(d, a, b)                                                            \
    asm volatile(                                                                    \
        "mma.sync.aligned.m16n8k16.row.col.f32.bf16.bf16.f32 "                       \
        "{%0,%1,%2,%3},{%4,%5,%6,%7},{%8,%9},{%0,%1,%2,%3};"                         \
        : "+f"(d[0]), "+f"(d[1]), "+f"(d[2]), "+f"(d[3])                             \
        : "r"(a[0]), "r"(a[1]), "r"(a[2]), "r"(a[3]), "r"(b[0]), "r"(b[1]))

template <int RELU, int BF16S, int PRE, int OROUND>
__global__ void __launch_bounds__(256)
tf32_gemm_kernel(const float* __restrict__ A, const float* __restrict__ B,
                 const float* __restrict__ bias, float* __restrict__ C,
                 int M, int K, int N) {
    __shared__ __align__(16) float As[2][128][AS_STRIDE];
    __shared__ __align__(16) float Bs[2][16][BS_STRIDE];

    int tid  = threadIdx.x;
    int warp = tid >> 5;
    int lane = tid & 31;
    int gid  = lane >> 2;
    int tq   = lane & 3;
    int wm   = warp >> 2;   // 0..1 -> 64-row slice
    int wn   = warp & 3;    // 0..3 -> 32-col slice

    int bm = blockIdx.y * 128;
    int bn = blockIdx.x * 128;

    float acc[4][4][4];
#pragma unroll
    for (int i = 0; i < 4; i++)
#pragma unroll
        for (int j = 0; j < 4; j++)
#pragma unroll
            for (int r = 0; r < 4; r++) acc[i][j][r] = 0.f;

    int nk = K >> 4;

    const float* Abase = A + (size_t)bm * K;
    const float* Bbase = B + bn;

    auto load_stage = [&](int stage, int k0) {
#pragma unroll
        for (int it = 0; it < 2; it++) {
            int i = tid + it * 256;
            int row = i >> 2, c4 = (i & 3) << 2;
            uint32_t d = (uint32_t)__cvta_generic_to_shared(&As[stage][row][c4]);
            cp16(d, Abase + (size_t)row * K + k0 + c4);
        }
#pragma unroll
        for (int it = 0; it < 2; it++) {
            int i = tid + it * 256;
            int row = i >> 5, c4 = (i & 31) << 2;
            uint32_t d = (uint32_t)__cvta_generic_to_shared(&Bs[stage][row][c4]);
            cp16(d, Bbase + (size_t)(k0 + row) * N + c4);
        }
    };

    load_stage(0, 0);
    asm volatile("cp.async.commit_group;");

    for (int kc = 0; kc < nk; kc++) {
        int cur = kc & 1;
        if (kc + 1 < nk) {
            load_stage(cur ^ 1, (kc + 1) << 4);
            asm volatile("cp.async.commit_group;");
            asm volatile("cp.async.wait_group 1;");
        } else {
            asm volatile("cp.async.wait_group 0;");
        }
        __syncthreads();

        if (BF16S) {
            // ---- bf16 split path: one 16-deep chunk, 3 MMAs per subtile ----
            uint32_t ahi[4][4], alo[4][4], bhi[4][2], blo[4][2];
#pragma unroll
            for (int mt = 0; mt < 4; mt++) {
                int m = wm * 64 + mt * 16;
                float2 q0 = *(const float2*)&As[cur][m + gid][tq * 2];
                float2 q1 = *(const float2*)&As[cur][m + gid + 8][tq * 2];
                float2 q2 = *(const float2*)&As[cur][m + gid][tq * 2 + 8];
                float2 q3 = *(const float2*)&As[cur][m + gid + 8][tq * 2 + 8];
                bf16_split_pack(q0.x, q0.y, ahi[mt][0], alo[mt][0]);
                bf16_split_pack(q1.x, q1.y, ahi[mt][1], alo[mt][1]);
                bf16_split_pack(q2.x, q2.y, ahi[mt][2], alo[mt][2]);
                bf16_split_pack(q3.x, q3.y, ahi[mt][3], alo[mt][3]);
            }
#pragma unroll
            for (int nt = 0; nt < 4; nt++) {
                int n = wn * 32 + nt * 8;
                float u0 = Bs[cur][tq * 2][n + gid];
                float u1 = Bs[cur][tq * 2 + 1][n + gid];
                float u2 = Bs[cur][tq * 2 + 8][n + gid];
                float u3 = Bs[cur][tq * 2 + 9][n + gid];
                bf16_split_pack(u0, u1, bhi[nt][0], blo[nt][0]);
                bf16_split_pack(u2, u3, bhi[nt][1], blo[nt][1]);
            }
#pragma unroll
            for (int mt = 0; mt < 4; mt++)
#pragma unroll
                for (int nt = 0; nt < 4; nt++) {
                    MMA_BF16(acc[mt][nt], ahi[mt], bhi[nt]);
                    MMA_BF16(acc[mt][nt], ahi[mt], blo[nt]);
                    MMA_BF16(acc[mt][nt], alo[mt], bhi[nt]);
                }
        } else {
            // ---- tf32 path (PRE or cvt), two 8-deep halves ----
#pragma unroll
            for (int ks = 0; ks < 16; ks += 8) {
                uint32_t af[4][4], bf[4][2];
#pragma unroll
                for (int mt = 0; mt < 4; mt++) {
                    int m = wm * 64 + mt * 16;
                    float v0 = As[cur][m + gid][ks + tq];
                    float v1 = As[cur][m + gid + 8][ks + tq];
                    float v2 = As[cur][m + gid][ks + tq + 4];
                    float v3 = As[cur][m + gid + 8][ks + tq + 4];
                    if (PRE) {
                        af[mt][0] = __float_as_uint(v0); af[mt][1] = __float_as_uint(v1);
                        af[mt][2] = __float_as_uint(v2); af[mt][3] = __float_as_uint(v3);
                    } else {
                        af[mt][0] = f2tf(v0); af[mt][1] = f2tf(v1);
                        af[mt][2] = f2tf(v2); af[mt][3] = f2tf(v3);
                    }
                }
#pragma unroll
                for (int nt = 0; nt < 4; nt++) {
                    int n = wn * 32 + nt * 8;
                    float u0 = Bs[cur][ks + tq][n + gid];
                    float u1 = Bs[cur][ks + tq + 4][n + gid];
                    if (PRE) {
                        bf[nt][0] = __float_as_uint(u0); bf[nt][1] = __float_as_uint(u1);
                    } else {
                        bf[nt][0] = f2tf(u0); bf[nt][1] = f2tf(u1);
                    }
                }
#pragma unroll
                for (int mt = 0; mt < 4; mt++)
#pragma unroll
                    for (int nt = 0; nt < 4; nt++)
                        MMA_TF32(acc[mt][nt], af[mt], bf[nt]);
            }
        }
        __syncthreads();
    }

    // ---- epilogue: bias (+relu) (+oround), float2 stores ----
#pragma unroll
    for (int mt = 0; mt < 4; mt++) {
        int gr = bm + wm * 64 + mt * 16 + gid;
#pragma unroll
        for (int nt = 0; nt < 4; nt++) {
            int gc = bn + wn * 32 + nt * 8 + tq * 2;
            float2 bv = *(const float2*)&bias[gc];
            float v0 = acc[mt][nt][0] + bv.x;
            float v1 = acc[mt][nt][1] + bv.y;
            float v2 = acc[mt][nt][2] + bv.x;
            float v3 = acc[mt][nt][3] + bv.y;
            if (RELU) {
                v0 = fmaxf(v0, 0.f); v1 = fmaxf(v1, 0.f);
                v2 = fmaxf(v2, 0.f); v3 = fmaxf(v3, 0.f);
            }
            if (OROUND) {
                v0 = __uint_as_float(f2tf(v0)); v1 = __uint_as_float(f2tf(v1));
                v2 = __uint_as_float(f2tf(v2)); v3 = __uint_as_float(f2tf(v3));
            }
            *(float2*)&C[(size_t)gr * N + gc]       = make_float2(v0, v1);
            *(float2*)&C[(size_t)(gr + 8) * N + gc] = make_float2(v2, v3);
        }
    }
}

// ---------------------------------------------------------------------------
// Per-pass gather + L2-normalize.  grid (PP, NGP), block 256.
// ---------------------------------------------------------------------------
__global__ void gather_norm_b_kernel(const float* __restrict__ h2_all,
                                     const int* __restrict__ idx_base,
                                     float* __restrict__ att_out, float* __restrict__ h,
                                     float* __restrict__ h_t, int g) {
    int t = blockIdx.y;
    const int* idx = idx_base + (size_t)t * PP;
    const float* h2 = h2_all + (size_t)t * NP * 256;

    int p = blockIdx.x;
    int f = threadIdx.x;
    int n = idx[p];
    float v = h2[(size_t)n * 256 + f];
    float s = v * v;
    __shared__ float red[8];
    for (int o = 16; o; o >>= 1) s += __shfl_xor_sync(0xffffffffu, s, o);
    if ((f & 31) == 0) red[f >> 5] = s;
    __syncthreads();
    float tot = red[0] + red[1] + red[2] + red[3] + red[4] + red[5] + red[6] + red[7];
    float norm = fmaxf(sqrtf(tot), 1e-12f);
    v /= norm;
    size_t o = ((size_t)(t * PP + p)) * DM + g * 256 + f;
    att_out[o] = v;
    h[o]       = v;
    h_t[o]     = __uint_as_float(f2tf(v));
}

// ---------------------------------------------------------------------------
// Banded attention: window 4, T=16.  One block per (p, head), 128 threads.
// float4 smem fill; output tf32-rounded (feeds PRE Wo GEMM).
// ---------------------------------------------------------------------------
__global__ void attn_kernel(const float* __restrict__ qkv, float* __restrict__ out) {
    int ph = blockIdx.x;
    int p = ph >> 3;
    int h = ph & 7;
    __shared__ float qs[16][64], ks[16][64], vs[16][64];
    int tid = threadIdx.x;
    for (int i = tid; i < 256; i += 128) {
        int t = i >> 4, d4 = (i & 15) << 2;
        const float4* b = (const float4*)(qkv + ((size_t)(t * PP + p)) * 1536 + h * 64 + d4);
        *(float4*)&qs[t][d4] = b[0];
        *(float4*)&ks[t][d4] = b[128];   // +512 floats
        *(float4*)&vs[t][d4] = b[256];   // +1024 floats
    }
    __syncthreads();
    int warp = tid >> 5, lane = tid & 31;
    for (int t = warp; t < 16; t += 4) {
        int s0 = t - 3; if (s0 < 0) s0 = 0;
        int ns = t - s0 + 1;
        float sc[4];
        float mx = -1e30f;
        for (int si = 0; si < ns; si++) {
            int s = s0 + si;
            float d0 = qs[t][lane] * ks[s][lane] + qs[t][lane + 32] * ks[s][lane + 32];
            for (int o = 16; o; o >>= 1) d0 += __shfl_xor_sync(0xffffffffu, d0, o);
            d0 *= 0.125f;
            sc[si] = d0;
            mx = fmaxf(mx, d0);
        }
        float sum = 0.f;
        for (int si = 0; si < ns; si++) { sc[si] = expf(sc[si] - mx); sum += sc[si]; }
        float inv = 1.f / sum;
        float o0 = 0.f, o1 = 0.f;
        for (int si = 0; si < ns; si++) {
            int s = s0 + si;
            o0 += sc[si] * vs[s][lane];
            o1 += sc[si] * vs[s][lane + 32];
        }
        size_t ob = ((size_t)(t * PP + p)) * DM + h * 64;
        out[ob + lane]      = __uint_as_float(f2tf(o0 * inv));
        out[ob + lane + 32] = __uint_as_float(f2tf(o1 * inv));
    }
}

// ---------------------------------------------------------------------------
// h = LayerNorm(h + delta) * g + b; also emits tf32-rounded copy h_t.
// ---------------------------------------------------------------------------
__global__ void resid_ln_kernel(float* __restrict__ h, const float* __restrict__ delta,
                                const float* __restrict__ g, const float* __restrict__ b,
                                float* __restrict__ h_t) {
    int row = blockIdx.x;
    int tid = threadIdx.x;
    size_t base = (size_t)row * DM;
    float v[4];
    float s = 0.f;
#pragma unroll
    for (int i = 0; i < 4; i++) {
        int c = tid + i * 128;
        float x = h[base + c] + delta[base + c];
        v[i] = x; s += x;
    }
    __shared__ float red[4];
    for (int o = 16; o; o >>= 1) s += __shfl_xor_sync(0xffffffffu, s, o);
    if ((tid & 31) == 0) red[tid >> 5] = s;
    __syncthreads();
    float mean = (red[0] + red[1] + red[2] + red[3]) * (1.f / 512.f);
    __syncthreads();
    float s2 = 0.f;
#pragma unroll
    for (int i = 0; i < 4; i++) { float d = v[i] - mean; s2 += d * d; }
    for (int o = 16; o; o >>= 1) s2 += __shfl_xor_sync(0xffffffffu, s2, o);
    if ((tid & 31) == 0) red[tid >> 5] = s2;
    __syncthreads();
    float var = (red[0] + red[1] + red[2] + red[3]) * (1.f / 512.f);
    float rstd = rsqrtf(var + 1e-5f);
#pragma unroll
    for (int i = 0; i < 4; i++) {
        int c = tid + i * 128;
        float o = (v[i] - mean) * rstd * g[c] + b[c];
        h[base + c]   = o;
        h_t[base + c] = __uint_as_float(f2tf(o));
    }
}

// Final projection: out[tok] = h[tok,:] . Wout.  Warp per token.
__global__ void out_kernel(const float* __restrict__ h, const float* __restrict__ W,
                           float* __restrict__ out) {
    int tok = blockIdx.x * 8 + (threadIdx.x >> 5);
    int lane = threadIdx.x & 31;
    const float* r = h + (size_t)tok * DM;
    float s = 0.f;
#pragma unroll
    for (int i = 0; i < 16; i++) s += r[lane + i * 32] * W[lane + i * 32];
    for (int o = 16; o; o >>= 1) s += __shfl_xor_sync(0xffffffffu, s, o);
    if (lane == 0) out[tok] = s;
}

// ---------------------------------------------------------------------------
// Weight prep
// ---------------------------------------------------------------------------
__global__ void prep_wc_kernel(const float* __restrict__ W1s, const float* __restrict__ W1n,
                               const float* __restrict__ W2s, const float* __restrict__ W2n,
                               float* __restrict__ wc1, float* __restrict__ wc2) {
    int i = blockIdx.x * blockDim.x + threadIdx.x;
    if (i < 256 * 256) {
        int k = i >> 8, c = i & 255;
        wc1[i] = (k < 128) ? W1s[k * 256 + c] : W1n[(k - 128) * 256 + c];
    }
    if (i < 512 * 256) {
        int k = i >> 8, c = i & 255;
        wc2[i] = (k < 256) ? W2s[k * 256 + c] : W2n[(k - 256) * 256 + c];
    }
}

__global__ void prep_wqkv_kernel(const float* __restrict__ Wq, const float* __restrict__ Wk,
                                 const float* __restrict__ Wv,
                                 const float* __restrict__ bq, const float* __restrict__ bk,
                                 const float* __restrict__ bv,
                                 float* __restrict__ Wqkv, float* __restrict__ bqkv) {
    int i = blockIdx.x * blockDim.x + threadIdx.x;
    const int tot = 2 * 512 * 1536;
    if (i < tot) {
        int l = i / (512 * 1536);
        int rem = i % (512 * 1536);
        int r = rem / 1536, c = rem % 1536;
        float v;
        size_t wb = (size_t)l * 512 * 512 + (size_t)r * 512;
        if (c < 512)       v = Wq[wb + c];
        else if (c < 1024) v = Wk[wb + (c - 512)];
        else               v = Wv[wb + (c - 1024)];
        Wqkv[i] = __uint_as_float(f2tf(v));
    }
    if (i < 2 * 1536) {
        int l = i / 1536, c = i % 1536;
        float v;
        if (c < 512)       v = bq[l * 512 + c];
        else if (c < 1024) v = bk[l * 512 + c - 512];
        else               v = bv[l * 512 + c - 1024];
        bqkv[i] = v;
    }
}

__global__ void prep_round_kernel(const float* __restrict__ Wo, const float* __restrict__ Wf1,
                                  const float* __restrict__ Wf2,
                                  float* __restrict__ wo_t, float* __restrict__ wf1_t,
                                  float* __restrict__ wf2_t) {
    const int NWO  = 2 * 512 * 512;
    const int NWF1 = 2 * 512 * 2048;
    const int NWF2 = 2 * 2048 * 512;
    int i = blockIdx.x * blockDim.x + threadIdx.x;
    if (i < NWO)  wo_t[i]  = __uint_as_float(f2tf(Wo[i]));
    if (i < NWF1) wf1_t[i] = __uint_as_float(f2tf(Wf1[i]));
    if (i < NWF2) wf2_t[i] = __uint_as_float(f2tf(Wf2[i]));
}

// ---------------------------------------------------------------------------
// Host driver
// ---------------------------------------------------------------------------
extern "C" void kernel_launch(void* const* d_in, const int* in_sizes, int n_in,
                              void* d_out, int out_size) {
    const float* x_i   = (const float*)d_in[0];
    const float* x_j   = (const float*)d_in[1];
    const int*   src_i = (const int*)d_in[2];
    const int*   dst_i = (const int*)d_in[3];
    const int*   src_j = (const int*)d_in[4];
    const int*   dst_j = (const int*)d_in[5];
    const int*   idx_i = (const int*)d_in[6];
    const int*   idx_j = (const int*)d_in[7];
    const float* W1s = (const float*)d_in[8];
    const float* W1n = (const float*)d_in[9];
    const float* b1  = (const float*)d_in[10];
    const float* W2s = (const float*)d_in[11];
    const float* W2n = (const float*)d_in[12];
    const float* b2  = (const float*)d_in[13];
    const float* Wq  = (const float*)d_in[14];
    const float* Wk  = (const float*)d_in[15];
    const float* Wv  = (const float*)d_in[16];
    const float* bq  = (const float*)d_in[17];
    const float* bk  = (const float*)d_in[18];
    const float* bv  = (const float*)d_in[19];
    const float* Wo  = (const float*)d_in[20];
    const float* bo  = (const float*)d_in[21];
    const float* Wf1 = (const float*)d_in[22];
    const float* bf1 = (const float*)d_in[23];
    const float* Wf2 = (const float*)d_in[24];
    const float* bf2 = (const float*)d_in[25];
    const float* g1  = (const float*)d_in[26];
    const float* bg1 = (const float*)d_in[27];
    const float* g2  = (const float*)d_in[28];
    const float* bg2 = (const float*)d_in[29];
    const float* Wout= (const float*)d_in[30];

    void* p;
    cudaGetSymbolAddress(&p, g_sage);  float* SB = (float*)p;
    cudaGetSymbolAddress(&p, g_w);     float* WB = (float*)p;
    cudaGetSymbolAddress(&p, g_act);   float* AB = (float*)p;
    cudaGetSymbolAddress(&p, g_iblob); int*   IB = (int*)p;

    float* h1   = SB + S_H1;
    float* bufB = SB + S_BUFB;
    float* bufA = SB + S_BUFA;
    float* h2   = SB + S_H2;

    float* wc1   = WB + W_WC1;
    float* wc2   = WB + W_WC2;
    float* wqkv  = WB + W_WQKV;
    float* bqkv  = WB + W_BQKV;
    float* wo_t  = WB + W_WO;
    float* wf1_t = WB + W_WF1;
    float* wf2_t = WB + W_WF2;

    float* hbuf = AB + A_H;
    float* h_t  = AB + A_HT;
    float* qkv  = AB + A_QKV;
    float* tmp  = AB + A_TMP;
    float* ffb  = AB + A_FF;

    int* deg  = IB + I_DEG;
    int* cur  = IB + I_CUR;
    int* off  = IB + I_OFF;
    int* csrc = IB + I_CSR;

    float* att_out  = (float*)d_out;
    float* scal_out = att_out + (size_t)NTOK * DM;

    // ---- weight prep ----
    prep_wc_kernel<<<(512 * 256 + 255) / 256, 256>>>(W1s, W1n, W2s, W2n, wc1, wc2);
    prep_wqkv_kernel<<<(2 * 512 * 1536 + 255) / 256, 256>>>(Wq, Wk, Wv, bq, bk, bv, wqkv, bqkv);
    prep_round_kernel<<<(2 * 512 * 2048 + 255) / 256, 256>>>(Wo, Wf1, Wf2, wo_t, wf1_t, wf2_t);

    // ---- batched CSR for all NG graphs ----
    cudaMemsetAsync(IB, 0, (size_t)2 * NG * NN * sizeof(int));   // deg + cur
    hist_b_kernel<<<dim3((EE + 255) / 256, NG), 256>>>(dst_i, dst_j, deg);
    scan_b_kernel<<<NG, 1024>>>(deg, off);
    fill_b_kernel<<<dim3((EE + 255) / 256, NG), 256>>>(src_i, src_j, dst_i, dst_j, off, cur, csrc);

    // ---- batched GraphSAGE, 2 passes (bf16-split tensor GEMMs) ----
    for (int g = 0; g < 2; g++) {
        const float* x   = (g == 0) ? x_i : x_j;
        const int*   idx = (g == 0) ? idx_i : idx_j;
        int gi0 = g * NGP;
        build_A_b_kernel<1><<<dim3(NN, NGP), 128>>>(x, nullptr, 128, off, csrc, bufA, gi0);
        tf32_gemm_kernel<1, 1, 0, 0><<<dim3(2, HB / 128), 256>>>(bufA, wc1, b1, h1, HB, 256, 256);
        build_A_b_kernel<2><<<dim3(NN, NGP), 256>>>(nullptr, h1, 256, off, csrc, bufB, gi0);
        tf32_gemm_kernel<0, 1, 0, 0><<<dim3(2, HB / 128), 256>>>(bufB, wc2, b2, h2, HB, 512, 256);
        gather_norm_b_kernel<<<dim3(PP, NGP), 256>>>(h2, idx, att_out, hbuf, h_t, g);
    }

    // ---- Transformer (PRE tf32 tensor-core GEMMs) ----
    for (int l = 0; l < NLAY; l++) {
        tf32_gemm_kernel<0, 0, 1, 0><<<dim3(12, NTOK / 128), 256>>>(
            h_t, wqkv + (size_t)l * 512 * 1536, bqkv + l * 1536, qkv, NTOK, 512, 1536);
        attn_kernel<<<PP * NHEAD, 128>>>(qkv, tmp);
        tf32_gemm_kernel<0, 0, 1, 0><<<dim3(4, NTOK / 128), 256>>>(
            tmp, wo_t + (size_t)l * 512 * 512, bo + l * 512, ffb, NTOK, 512, 512);
        resid_ln_kernel<<<NTOK, 128>>>(hbuf, ffb, g1 + l * 512, bg1 + l * 512, h_t);
        tf32_gemm_kernel<1, 0, 1, 1><<<dim3(16, NTOK / 128), 256>>>(
            h_t, wf1_t + (size_t)l * 512 * 2048, bf1 + l * 2048, ffb, NTOK, 512, 2048);
        tf32_gemm_kernel<0, 0, 1, 0><<<dim3(4, NTOK / 128), 256>>>(
            ffb, wf2_t + (size_t)l * 2048 * 512, bf2 + l * 512, tmp, NTOK, 2048, 512);
        resid_ln_kernel<<<NTOK, 128>>>(hbuf, tmp, g2 + l * 512, bg2 + l * 512, h_t);
    }

    out_kernel<<<NTOK / 8, 256>>>(hbuf, Wout, scal_out);
}

// round 13
// speedup vs baseline: 1.3042x; 1.3042x over previous
#include <cuda_runtime.h>
#include <cstdint>

// ---------------------------------------------------------------------------
// Problem constants
// ---------------------------------------------------------------------------
#define TT     16
#define NN     20000
#define NP     20096            // NN padded to multiple of 128
#define NG     32               // 32 (t, graph) pairs total
#define NGP    16               // graph-instances per SAGE pass
#define EE     320000
#define PP     4096
#define DIN    128
#define NHEAD  8
#define NLAY   2
#define DM     512
#define NTOK   (TT * PP)     // 65536
#define HB     (NGP * NP)    // 321536 rows (layer-1 GEMM)
#define HB2    (NGP * PP)    // 65536 rows (layer-2 GEMM, selected only)

// ---------------------------------------------------------------------------
// Scratch blobs (total .bss < 4GB for aarch64 ADRP)
// ---------------------------------------------------------------------------
constexpr size_t S_H1   = 0;
constexpr size_t S_BUFB = (size_t)HB * 256;
constexpr size_t S_BUFA = S_BUFB;                       // alias (disjoint lifetime)
constexpr size_t S_H2   = 0;                            // alias of h1 (disjoint lifetime)
constexpr size_t S_TOTAL= (size_t)HB * 768;             // ~0.99 GB
__device__ float g_sage[S_TOTAL];

// weights region
constexpr size_t W_WC1   = 0;                          // [256,256] stacked fp32
constexpr size_t W_WC2   = W_WC1  + 256ull * 256;      // [512,256]
constexpr size_t W_WQKV  = W_WC2  + 512ull * 256;      // [2,512,1536] tf32-rounded
constexpr size_t W_BQKV  = W_WQKV + 2ull * 512 * 1536; // [2,1536] fp32
constexpr size_t W_WO    = W_BQKV + 2ull * 1536;       // [2,512,512] tf32-rounded
constexpr size_t W_WF1   = W_WO   + 2ull * 512 * 512;  // [2,512,2048] tf32-rounded
constexpr size_t W_WF2   = W_WF1  + 2ull * 512 * 2048; // [2,2048,512] tf32-rounded
constexpr size_t W_TOTAL = W_WF2  + 2ull * 2048 * 512;
__device__ float g_w[W_TOTAL];

// activations region (~1.34 GB)
constexpr size_t A_H    = 0;                           // [NTOK,512]  fp32 hidden
constexpr size_t A_HT   = A_H   + (size_t)NTOK * 512;  // [NTOK,512]  tf32-rounded hidden
constexpr size_t A_QKV  = A_HT  + (size_t)NTOK * 512;  // [NTOK,1536]
constexpr size_t A_TMP  = A_QKV + (size_t)NTOK * 1536; // [NTOK,512]
constexpr size_t A_FF   = A_TMP + (size_t)NTOK * 512;  // [NTOK,2048]
constexpr size_t A_TOTAL= A_FF  + (size_t)NTOK * 2048;
__device__ float g_act[A_TOTAL];

// CSR int region (~49 MB)
constexpr size_t I_DEG = 0;
constexpr size_t I_CUR = I_DEG + (size_t)NG * NN;
constexpr size_t I_OFF = I_CUR + (size_t)NG * NN;
constexpr size_t I_CSR = I_OFF + (size_t)NG * (NN + 1);
constexpr size_t I_TOTAL = I_CSR + (size_t)NG * EE;
__device__ int g_iblob[I_TOTAL];

// ---------------------------------------------------------------------------
// numeric helpers
// ---------------------------------------------------------------------------
__device__ __forceinline__ uint32_t f2tf(float f) {
    uint32_t r;
    asm("cvt.rna.tf32.f32 %0, %1;" : "=r"(r) : "f"(f));
    return r;
}

__device__ __forceinline__ void bf16_split_pack(float v0, float v1,
                                                uint32_t& hi, uint32_t& lo) {
    uint32_t h;
    asm("cvt.rn.bf16x2.f32 %0, %1, %2;" : "=r"(h) : "f"(v1), "f"(v0));
    float h0 = __uint_as_float(h << 16);
    float h1 = __uint_as_float(h & 0xFFFF0000u);
    hi = h;
    asm("cvt.rn.bf16x2.f32 %0, %1, %2;" : "=r"(lo) : "f"(v1 - h1), "f"(v0 - h0));
}

__device__ __forceinline__ void cp16(uint32_t daddr, const void* src) {
    asm volatile("cp.async.cg.shared.global [%0], [%1], 16;" :: "r"(daddr), "l"(src));
}

// ---------------------------------------------------------------------------
// Batched CSR construction
// ---------------------------------------------------------------------------
__global__ void hist_b_kernel(const int* __restrict__ dst_i, const int* __restrict__ dst_j,
                              int* __restrict__ deg) {
    int gi = blockIdx.y;
    int t = gi & 15, g = gi >> 4;
    const int* dst = (g == 0 ? dst_i : dst_j) + (size_t)t * EE;
    int* d = deg + (size_t)gi * NN;
    int e = blockIdx.x * blockDim.x + threadIdx.x;
    if (e < EE) atomicAdd(&d[dst[e]], 1);
}

__global__ void __launch_bounds__(1024)
scan_b_kernel(const int* __restrict__ deg_all, int* __restrict__ off_all) {
    __shared__ int wsum[32];
    const int CH = 20;
    int gi = blockIdx.x;
    const int* deg = deg_all + (size_t)gi * NN;
    int* off = off_all + (size_t)gi * (NN + 1);
    int tid = threadIdx.x;
    int lane = tid & 31, warp = tid >> 5;
    int base = tid * CH;
    int loc[CH];
    int s = 0;
#pragma unroll
    for (int i = 0; i < CH; i++) {
        int idx = base + i;
        int v = (idx < NN) ? deg[idx] : 0;
        s += v;
        loc[i] = s;
    }
    int ssum = s;
#pragma unroll
    for (int o = 1; o < 32; o <<= 1) {
        int t = __shfl_up_sync(0xffffffffu, ssum, o);
        if (lane >= o) ssum += t;
    }
    if (lane == 31) wsum[warp] = ssum;
    __syncthreads();
    if (warp == 0) {
        int w = wsum[lane];
#pragma unroll
        for (int o = 1; o < 32; o <<= 1) {
            int t = __shfl_up_sync(0xffffffffu, w, o);
            if (lane >= o) w += t;
        }
        wsum[lane] = w;
    }
    __syncthreads();
    int offset = ssum - s + (warp ? wsum[warp - 1] : 0);
    if (tid == 0) off[0] = 0;
#pragma unroll
    for (int i = 0; i < CH; i++) {
        int idx = base + i;
        if (idx < NN) off[idx + 1] = offset + loc[i];
    }
}

__global__ void fill_b_kernel(const int* __restrict__ src_i, const int* __restrict__ src_j,
                              const int* __restrict__ dst_i, const int* __restrict__ dst_j,
                              const int* __restrict__ off_all, int* __restrict__ cur_all,
                              int* __restrict__ csrc_all) {
    int gi = blockIdx.y;
    int t = gi & 15, g = gi >> 4;
    const int* src = (g == 0 ? src_i : src_j) + (size_t)t * EE;
    const int* dst = (g == 0 ? dst_i : dst_j) + (size_t)t * EE;
    const int* off = off_all + (size_t)gi * (NN + 1);
    int* cur = cur_all + (size_t)gi * NN;
    int* csrc = csrc_all + (size_t)gi * EE;
    int e = blockIdx.x * blockDim.x + threadIdx.x;
    if (e < EE) {
        int d = dst[e];
        int p = atomicAdd(&cur[d], 1);
        csrc[off[d] + p] = src[e];
    }
}

// ---------------------------------------------------------------------------
// Layer-1 build A = [self | mean_agg] for ALL nodes.  grid (NN, NGP), block 128.
// ---------------------------------------------------------------------------
__global__ void build_A1_kernel(const float* __restrict__ x,
                                const int* __restrict__ off_all, const int* __restrict__ csrc_all,
                                float* __restrict__ out_all, int gi0) {
    int tl = blockIdx.y;
    int gi = gi0 + tl;
    const float* feat = x + (size_t)tl * NN * DIN;
    const int* off = off_all + (size_t)gi * (NN + 1);
    const int* csrc = csrc_all + (size_t)gi * EE;
    float* out = out_all + (size_t)tl * NP * 256;

    int n = blockIdx.x;
    int f = threadIdx.x;
    float self = feat[(size_t)n * DIN + f];
    int s = off[n], e = off[n + 1];
    float acc = 0.f;
    int i = s;
    for (; i + 4 <= e; i += 4) {
        int a0 = csrc[i], a1 = csrc[i + 1], a2 = csrc[i + 2], a3 = csrc[i + 3];
        float v0 = feat[(size_t)a0 * DIN + f];
        float v1 = feat[(size_t)a1 * DIN + f];
        float v2 = feat[(size_t)a2 * DIN + f];
        float v3 = feat[(size_t)a3 * DIN + f];
        acc += v0 + v1 + v2 + v3;
    }
    for (; i < e; i++) acc += feat[(size_t)csrc[i] * DIN + f];
    int d = e - s; if (d < 1) d = 1;
    size_t ob = (size_t)n * 256;
    out[ob + f]       = self;
    out[ob + 128 + f] = acc / (float)d;
}

// ---------------------------------------------------------------------------
// Layer-2 build A for SELECTED nodes only.  grid (PP, NGP), block 256.
// Row p of the compact output corresponds to node idx[p].
// ---------------------------------------------------------------------------
__global__ void build_A2_kernel(const float* __restrict__ h1_all,
                                const int* __restrict__ idx_base,
                                const int* __restrict__ off_all, const int* __restrict__ csrc_all,
                                float* __restrict__ out_all, int gi0) {
    int tl = blockIdx.y;
    int gi = gi0 + tl;
    const float* feat = h1_all + (size_t)tl * NP * 256;
    const int* off = off_all + (size_t)gi * (NN + 1);
    const int* csrc = csrc_all + (size_t)gi * EE;
    const int* idx = idx_base + (size_t)tl * PP;
    float* out = out_all + (size_t)tl * PP * 512;

    int p = blockIdx.x;
    int n = idx[p];
    int f = threadIdx.x;
    float self = feat[(size_t)n * 256 + f];
    int s = off[n], e = off[n + 1];
    float acc = 0.f;
    int i = s;
    for (; i + 4 <= e; i += 4) {
        int a0 = csrc[i], a1 = csrc[i + 1], a2 = csrc[i + 2], a3 = csrc[i + 3];
        float v0 = feat[(size_t)a0 * 256 + f];
        float v1 = feat[(size_t)a1 * 256 + f];
        float v2 = feat[(size_t)a2 * 256 + f];
        float v3 = feat[(size_t)a3 * 256 + f];
        acc += v0 + v1 + v2 + v3;
    }
    for (; i < e; i++) acc += feat[(size_t)csrc[i] * 256 + f];
    int d = e - s; if (d < 1) d = 1;
    size_t ob = (size_t)p * 512;
    out[ob + f]       = self;
    out[ob + 256 + f] = acc / (float)d;
}

// ---------------------------------------------------------------------------
// Tensor-core GEMM.  C = A@B + bias (+relu).  128x128x16 block tile,
// 256 threads = 8 warps as 2(m) x 4(n), warp tile 64x32, cp.async dbl-buffered.
// BF16S : bf16 2-way-split (hi/lo), 3x m16n8k16 per chunk — SAGE path.
// PRE   : operands already tf32-rounded in gmem — m16n8k8 tf32, no cvt.
// OROUND: round C store to tf32 bits (feeds a later PRE GEMM).
// ---------------------------------------------------------------------------
#define AS_STRIDE 20
#define BS_STRIDE 136

#define MMA_TF32(d, a, b)                                                            \
    asm volatile(                                                                    \
        "mma.sync.aligned.m16n8k8.row.col.f32.tf32.tf32.f32 "                        \
        "{%0,%1,%2,%3},{%4,%5,%6,%7},{%8,%9},{%0,%1,%2,%3};"                         \
        : "+f"(d[0]), "+f"(d[1]), "+f"(d[2]), "+f"(d[3])                             \
        : "r"(a[0]), "r"(a[1]), "r"(a[2]), "r"(a[3]), "r"(b[0]), "r"(b[1]))

#define MMA_BF16(d, a, b)                                                            \
    asm volatile(                                                                    \
        "mma.sync.aligned.m16n8k16.row.col.f32.bf16.bf16.f32 "                       \
        "{%0,%1,%2,%3},{%4,%5,%6,%7},{%8,%9},{%0,%1,%2,%3};"                         \
        : "+f"(d[0]), "+f"(d[1]), "+f"(d[2]), "+f"(d[3])                             \
        : "r"(a[0]), "r"(a[1]), "r"(a[2]), "r"(a[3]), "r"(b[0]), "r"(b[1]))

template <int RELU, int BF16S, int PRE, int OROUND>
__global__ void __launch_bounds__(256)
tf32_gemm_kernel(const float* __restrict__ A, const float* __restrict__ B,
                 const float* __restrict__ bias, float* __restrict__ C,
                 int M, int K, int N) {
    __shared__ __align__(16) float As[2][128][AS_STRIDE];
    __shared__ __align__(16) float Bs[2][16][BS_STRIDE];

    int tid  = threadIdx.x;
    int warp = tid >> 5;
    int lane = tid & 31;
    int gid  = lane >> 2;
    int tq   = lane & 3;
    int wm   = warp >> 2;
    int wn   = warp & 3;

    int bm = blockIdx.y * 128;
    int bn = blockIdx.x * 128;

    float acc[4][4][4];
#pragma unroll
    for (int i = 0; i < 4; i++)
#pragma unroll
        for (int j = 0; j < 4; j++)
#pragma unroll
            for (int r = 0; r < 4; r++) acc[i][j][r] = 0.f;

    int nk = K >> 4;
    const float* Abase = A + (size_t)bm * K;
    const float* Bbase = B + bn;

    auto load_stage = [&](int stage, int k0) {
#pragma unroll
        for (int it = 0; it < 2; it++) {
            int i = tid + it * 256;
            int row = i >> 2, c4 = (i & 3) << 2;
            uint32_t d = (uint32_t)__cvta_generic_to_shared(&As[stage][row][c4]);
            cp16(d, Abase + (size_t)row * K + k0 + c4);
        }
#pragma unroll
        for (int it = 0; it < 2; it++) {
            int i = tid + it * 256;
            int row = i >> 5, c4 = (i & 31) << 2;
            uint32_t d = (uint32_t)__cvta_generic_to_shared(&Bs[stage][row][c4]);
            cp16(d, Bbase + (size_t)(k0 + row) * N + c4);
        }
    };

    load_stage(0, 0);
    asm volatile("cp.async.commit_group;");

    for (int kc = 0; kc < nk; kc++) {
        int cur = kc & 1;
        if (kc + 1 < nk) {
            load_stage(cur ^ 1, (kc + 1) << 4);
            asm volatile("cp.async.commit_group;");
            asm volatile("cp.async.wait_group 1;");
        } else {
            asm volatile("cp.async.wait_group 0;");
        }
        __syncthreads();

        if (BF16S) {
            uint32_t ahi[4][4], alo[4][4], bhi[4][2], blo[4][2];
#pragma unroll
            for (int mt = 0; mt < 4; mt++) {
                int m = wm * 64 + mt * 16;
                float2 q0 = *(const float2*)&As[cur][m + gid][tq * 2];
                float2 q1 = *(const float2*)&As[cur][m + gid + 8][tq * 2];
                float2 q2 = *(const float2*)&As[cur][m + gid][tq * 2 + 8];
                float2 q3 = *(const float2*)&As[cur][m + gid + 8][tq * 2 + 8];
                bf16_split_pack(q0.x, q0.y, ahi[mt][0], alo[mt][0]);
                bf16_split_pack(q1.x, q1.y, ahi[mt][1], alo[mt][1]);
                bf16_split_pack(q2.x, q2.y, ahi[mt][2], alo[mt][2]);
                bf16_split_pack(q3.x, q3.y, ahi[mt][3], alo[mt][3]);
            }
#pragma unroll
            for (int nt = 0; nt < 4; nt++) {
                int n = wn * 32 + nt * 8;
                float u0 = Bs[cur][tq * 2][n + gid];
                float u1 = Bs[cur][tq * 2 + 1][n + gid];
                float u2 = Bs[cur][tq * 2 + 8][n + gid];
                float u3 = Bs[cur][tq * 2 + 9][n + gid];
                bf16_split_pack(u0, u1, bhi[nt][0], blo[nt][0]);
                bf16_split_pack(u2, u3, bhi[nt][1], blo[nt][1]);
            }
#pragma unroll
            for (int mt = 0; mt < 4; mt++)
#pragma unroll
                for (int nt = 0; nt < 4; nt++) {
                    MMA_BF16(acc[mt][nt], ahi[mt], bhi[nt]);
                    MMA_BF16(acc[mt][nt], ahi[mt], blo[nt]);
                    MMA_BF16(acc[mt][nt], alo[mt], bhi[nt]);
                }
        } else {
#pragma unroll
            for (int ks = 0; ks < 16; ks += 8) {
                uint32_t af[4][4], bf[4][2];
#pragma unroll
                for (int mt = 0; mt < 4; mt++) {
                    int m = wm * 64 + mt * 16;
                    float v0 = As[cur][m + gid][ks + tq];
                    float v1 = As[cur][m + gid + 8][ks + tq];
                    float v2 = As[cur][m + gid][ks + tq + 4];
                    float v3 = As[cur][m + gid + 8][ks + tq + 4];
                    if (PRE) {
                        af[mt][0] = __float_as_uint(v0); af[mt][1] = __float_as_uint(v1);
                        af[mt][2] = __float_as_uint(v2); af[mt][3] = __float_as_uint(v3);
                    } else {
                        af[mt][0] = f2tf(v0); af[mt][1] = f2tf(v1);
                        af[mt][2] = f2tf(v2); af[mt][3] = f2tf(v3);
                    }
                }
#pragma unroll
                for (int nt = 0; nt < 4; nt++) {
                    int n = wn * 32 + nt * 8;
                    float u0 = Bs[cur][ks + tq][n + gid];
                    float u1 = Bs[cur][ks + tq + 4][n + gid];
                    if (PRE) {
                        bf[nt][0] = __float_as_uint(u0); bf[nt][1] = __float_as_uint(u1);
                    } else {
                        bf[nt][0] = f2tf(u0); bf[nt][1] = f2tf(u1);
                    }
                }
#pragma unroll
                for (int mt = 0; mt < 4; mt++)
#pragma unroll
                    for (int nt = 0; nt < 4; nt++)
                        MMA_TF32(acc[mt][nt], af[mt], bf[nt]);
            }
        }
        __syncthreads();
    }

#pragma unroll
    for (int mt = 0; mt < 4; mt++) {
        int gr = bm + wm * 64 + mt * 16 + gid;
#pragma unroll
        for (int nt = 0; nt < 4; nt++) {
            int gc = bn + wn * 32 + nt * 8 + tq * 2;
            float2 bv = *(const float2*)&bias[gc];
            float v0 = acc[mt][nt][0] + bv.x;
            float v1 = acc[mt][nt][1] + bv.y;
            float v2 = acc[mt][nt][2] + bv.x;
            float v3 = acc[mt][nt][3] + bv.y;
            if (RELU) {
                v0 = fmaxf(v0, 0.f); v1 = fmaxf(v1, 0.f);
                v2 = fmaxf(v2, 0.f); v3 = fmaxf(v3, 0.f);
            }
            if (OROUND) {
                v0 = __uint_as_float(f2tf(v0)); v1 = __uint_as_float(f2tf(v1));
                v2 = __uint_as_float(f2tf(v2)); v3 = __uint_as_float(f2tf(v3));
            }
            *(float2*)&C[(size_t)gr * N + gc]       = make_float2(v0, v1);
            *(float2*)&C[(size_t)(gr + 8) * N + gc] = make_float2(v2, v3);
        }
    }
}

// ---------------------------------------------------------------------------
// Gather (compact rows) + L2-normalize.  grid (PP, NGP), block 256.
// Row (t*PP + p) of h2c is exactly the selected node's layer-2 output.
// ---------------------------------------------------------------------------
__global__ void gather_norm2_kernel(const float* __restrict__ h2c,
                                    float* __restrict__ att_out, float* __restrict__ h,
                                    float* __restrict__ h_t, int g) {
    int t = blockIdx.y;
    int p = blockIdx.x;
    int f = threadIdx.x;
    float v = h2c[((size_t)t * PP + p) * 256 + f];
    float s = v * v;
    __shared__ float red[8];
    for (int o = 16; o; o >>= 1) s += __shfl_xor_sync(0xffffffffu, s, o);
    if ((f & 31) == 0) red[f >> 5] = s;
    __syncthreads();
    float tot = red[0] + red[1] + red[2] + red[3] + red[4] + red[5] + red[6] + red[7];
    float norm = fmaxf(sqrtf(tot), 1e-12f);
    v /= norm;
    size_t o = ((size_t)(t * PP + p)) * DM + g * 256 + f;
    att_out[o] = v;
    h[o]       = v;
    h_t[o]     = __uint_as_float(f2tf(v));
}

// ---------------------------------------------------------------------------
// Banded attention: window 4, T=16.  One block per (p, head), 128 threads.
// ---------------------------------------------------------------------------
__global__ void attn_kernel(const float* __restrict__ qkv, float* __restrict__ out) {
    int ph = blockIdx.x;
    int p = ph >> 3;
    int h = ph & 7;
    __shared__ float qs[16][64], ks[16][64], vs[16][64];
    int tid = threadIdx.x;
    for (int i = tid; i < 256; i += 128) {
        int t = i >> 4, d4 = (i & 15) << 2;
        const float4* b = (const float4*)(qkv + ((size_t)(t * PP + p)) * 1536 + h * 64 + d4);
        *(float4*)&qs[t][d4] = b[0];
        *(float4*)&ks[t][d4] = b[128];
        *(float4*)&vs[t][d4] = b[256];
    }
    __syncthreads();
    int warp = tid >> 5, lane = tid & 31;
    for (int t = warp; t < 16; t += 4) {
        int s0 = t - 3; if (s0 < 0) s0 = 0;
        int ns = t - s0 + 1;
        float sc[4];
        float mx = -1e30f;
        for (int si = 0; si < ns; si++) {
            int s = s0 + si;
            float d0 = qs[t][lane] * ks[s][lane] + qs[t][lane + 32] * ks[s][lane + 32];
            for (int o = 16; o; o >>= 1) d0 += __shfl_xor_sync(0xffffffffu, d0, o);
            d0 *= 0.125f;
            sc[si] = d0;
            mx = fmaxf(mx, d0);
        }
        float sum = 0.f;
        for (int si = 0; si < ns; si++) { sc[si] = expf(sc[si] - mx); sum += sc[si]; }
        float inv = 1.f / sum;
        float o0 = 0.f, o1 = 0.f;
        for (int si = 0; si < ns; si++) {
            int s = s0 + si;
            o0 += sc[si] * vs[s][lane];
            o1 += sc[si] * vs[s][lane + 32];
        }
        size_t ob = ((size_t)(t * PP + p)) * DM + h * 64;
        out[ob + lane]      = __uint_as_float(f2tf(o0 * inv));
        out[ob + lane + 32] = __uint_as_float(f2tf(o1 * inv));
    }
}

// ---------------------------------------------------------------------------
// h = LayerNorm(h + delta) * g + b; also emits tf32-rounded copy h_t.
// ---------------------------------------------------------------------------
__global__ void resid_ln_kernel(float* __restrict__ h, const float* __restrict__ delta,
                                const float* __restrict__ g, const float* __restrict__ b,
                                float* __restrict__ h_t) {
    int row = blockIdx.x;
    int tid = threadIdx.x;
    size_t base = (size_t)row * DM;
    float v[4];
    float s = 0.f;
#pragma unroll
    for (int i = 0; i < 4; i++) {
        int c = tid + i * 128;
        float x = h[base + c] + delta[base + c];
        v[i] = x; s += x;
    }
    __shared__ float red[4];
    for (int o = 16; o; o >>= 1) s += __shfl_xor_sync(0xffffffffu, s, o);
    if ((tid & 31) == 0) red[tid >> 5] = s;
    __syncthreads();
    float mean = (red[0] + red[1] + red[2] + red[3]) * (1.f / 512.f);
    __syncthreads();
    float s2 = 0.f;
#pragma unroll
    for (int i = 0; i < 4; i++) { float d = v[i] - mean; s2 += d * d; }
    for (int o = 16; o; o >>= 1) s2 += __shfl_xor_sync(0xffffffffu, s2, o);
    if ((tid & 31) == 0) red[tid >> 5] = s2;
    __syncthreads();
    float var = (red[0] + red[1] + red[2] + red[3]) * (1.f / 512.f);
    float rstd = rsqrtf(var + 1e-5f);
#pragma unroll
    for (int i = 0; i < 4; i++) {
        int c = tid + i * 128;
        float o = (v[i] - mean) * rstd * g[c] + b[c];
        h[base + c]   = o;
        h_t[base + c] = __uint_as_float(f2tf(o));
    }
}

// Final projection: out[tok] = h[tok,:] . Wout.  Warp per token.
__global__ void out_kernel(const float* __restrict__ h, const float* __restrict__ W,
                           float* __restrict__ out) {
    int tok = blockIdx.x * 8 + (threadIdx.x >> 5);
    int lane = threadIdx.x & 31;
    const float* r = h + (size_t)tok * DM;
    float s = 0.f;
#pragma unroll
    for (int i = 0; i < 16; i++) s += r[lane + i * 32] * W[lane + i * 32];
    for (int o = 16; o; o >>= 1) s += __shfl_xor_sync(0xffffffffu, s, o);
    if (lane == 0) out[tok] = s;
}

// ---------------------------------------------------------------------------
// Weight prep
// ---------------------------------------------------------------------------
__global__ void prep_wc_kernel(const float* __restrict__ W1s, const float* __restrict__ W1n,
                               const float* __restrict__ W2s, const float* __restrict__ W2n,
                               float* __restrict__ wc1, float* __restrict__ wc2) {
    int i = blockIdx.x * blockDim.x + threadIdx.x;
    if (i < 256 * 256) {
        int k = i >> 8, c = i & 255;
        wc1[i] = (k < 128) ? W1s[k * 256 + c] : W1n[(k - 128) * 256 + c];
    }
    if (i < 512 * 256) {
        int k = i >> 8, c = i & 255;
        wc2[i] = (k < 256) ? W2s[k * 256 + c] : W2n[(k - 256) * 256 + c];
    }
}

__global__ void prep_wqkv_kernel(const float* __restrict__ Wq, const float* __restrict__ Wk,
                                 const float* __restrict__ Wv,
                                 const float* __restrict__ bq, const float* __restrict__ bk,
                                 const float* __restrict__ bv,
                                 float* __restrict__ Wqkv, float* __restrict__ bqkv) {
    int i = blockIdx.x * blockDim.x + threadIdx.x;
    const int tot = 2 * 512 * 1536;
    if (i < tot) {
        int l = i / (512 * 1536);
        int rem = i % (512 * 1536);
        int r = rem / 1536, c = rem % 1536;
        float v;
        size_t wb = (size_t)l * 512 * 512 + (size_t)r * 512;
        if (c < 512)       v = Wq[wb + c];
        else if (c < 1024) v = Wk[wb + (c - 512)];
        else               v = Wv[wb + (c - 1024)];
        Wqkv[i] = __uint_as_float(f2tf(v));
    }
    if (i < 2 * 1536) {
        int l = i / 1536, c = i % 1536;
        float v;
        if (c < 512)       v = bq[l * 512 + c];
        else if (c < 1024) v = bk[l * 512 + c - 512];
        else               v = bv[l * 512 + c - 1024];
        bqkv[i] = v;
    }
}

__global__ void prep_round_kernel(const float* __restrict__ Wo, const float* __restrict__ Wf1,
                                  const float* __restrict__ Wf2,
                                  float* __restrict__ wo_t, float* __restrict__ wf1_t,
                                  float* __restrict__ wf2_t) {
    const int NWO  = 2 * 512 * 512;
    const int NWF1 = 2 * 512 * 2048;
    const int NWF2 = 2 * 2048 * 512;
    int i = blockIdx.x * blockDim.x + threadIdx.x;
    if (i < NWO)  wo_t[i]  = __uint_as_float(f2tf(Wo[i]));
    if (i < NWF1) wf1_t[i] = __uint_as_float(f2tf(Wf1[i]));
    if (i < NWF2) wf2_t[i] = __uint_as_float(f2tf(Wf2[i]));
}

// ---------------------------------------------------------------------------
// Host driver
// ---------------------------------------------------------------------------
extern "C" void kernel_launch(void* const* d_in, const int* in_sizes, int n_in,
                              void* d_out, int out_size) {
    const float* x_i   = (const float*)d_in[0];
    const float* x_j   = (const float*)d_in[1];
    const int*   src_i = (const int*)d_in[2];
    const int*   dst_i = (const int*)d_in[3];
    const int*   src_j = (const int*)d_in[4];
    const int*   dst_j = (const int*)d_in[5];
    const int*   idx_i = (const int*)d_in[6];
    const int*   idx_j = (const int*)d_in[7];
    const float* W1s = (const float*)d_in[8];
    const float* W1n = (const float*)d_in[9];
    const float* b1  = (const float*)d_in[10];
    const float* W2s = (const float*)d_in[11];
    const float* W2n = (const float*)d_in[12];
    const float* b2  = (const float*)d_in[13];
    const float* Wq  = (const float*)d_in[14];
    const float* Wk  = (const float*)d_in[15];
    const float* Wv  = (const float*)d_in[16];
    const float* bq  = (const float*)d_in[17];
    const float* bk  = (const float*)d_in[18];
    const float* bv  = (const float*)d_in[19];
    const float* Wo  = (const float*)d_in[20];
    const float* bo  = (const float*)d_in[21];
    const float* Wf1 = (const float*)d_in[22];
    const float* bf1 = (const float*)d_in[23];
    const float* Wf2 = (const float*)d_in[24];
    const float* bf2 = (const float*)d_in[25];
    const float* g1  = (const float*)d_in[26];
    const float* bg1 = (const float*)d_in[27];
    const float* g2  = (const float*)d_in[28];
    const float* bg2 = (const float*)d_in[29];
    const float* Wout= (const float*)d_in[30];

    void* p;
    cudaGetSymbolAddress(&p, g_sage);  float* SB = (float*)p;
    cudaGetSymbolAddress(&p, g_w);     float* WB = (float*)p;
    cudaGetSymbolAddress(&p, g_act);   float* AB = (float*)p;
    cudaGetSymbolAddress(&p, g_iblob); int*   IB = (int*)p;

    float* h1   = SB + S_H1;
    float* bufB = SB + S_BUFB;   // layer-2 compact input [HB2, 512]
    float* bufA = SB + S_BUFA;   // alias (disjoint lifetime)
    float* h2   = SB + S_H2;     // alias of h1 (disjoint lifetime), [HB2, 256]

    float* wc1   = WB + W_WC1;
    float* wc2   = WB + W_WC2;
    float* wqkv  = WB + W_WQKV;
    float* bqkv  = WB + W_BQKV;
    float* wo_t  = WB + W_WO;
    float* wf1_t = WB + W_WF1;
    float* wf2_t = WB + W_WF2;

    float* hbuf = AB + A_H;
    float* h_t  = AB + A_HT;
    float* qkv  = AB + A_QKV;
    float* tmp  = AB + A_TMP;
    float* ffb  = AB + A_FF;

    int* deg  = IB + I_DEG;
    int* cur  = IB + I_CUR;
    int* off  = IB + I_OFF;
    int* csrc = IB + I_CSR;

    float* att_out  = (float*)d_out;
    float* scal_out = att_out + (size_t)NTOK * DM;

    // ---- weight prep ----
    prep_wc_kernel<<<(512 * 256 + 255) / 256, 256>>>(W1s, W1n, W2s, W2n, wc1, wc2);
    prep_wqkv_kernel<<<(2 * 512 * 1536 + 255) / 256, 256>>>(Wq, Wk, Wv, bq, bk, bv, wqkv, bqkv);
    prep_round_kernel<<<(2 * 512 * 2048 + 255) / 256, 256>>>(Wo, Wf1, Wf2, wo_t, wf1_t, wf2_t);

    // ---- batched CSR for all NG graphs ----
    cudaMemsetAsync(IB, 0, (size_t)2 * NG * NN * sizeof(int));   // deg + cur
    hist_b_kernel<<<dim3((EE + 255) / 256, NG), 256>>>(dst_i, dst_j, deg);
    scan_b_kernel<<<NG, 1024>>>(deg, off);
    fill_b_kernel<<<dim3((EE + 255) / 256, NG), 256>>>(src_i, src_j, dst_i, dst_j, off, cur, csrc);

    // ---- batched GraphSAGE, 2 passes; layer 2 computed only for selected ----
    for (int g = 0; g < 2; g++) {
        const float* x   = (g == 0) ? x_i : x_j;
        const int*   idx = (g == 0) ? idx_i : idx_j;
        int gi0 = g * NGP;
        build_A1_kernel<<<dim3(NN, NGP), 128>>>(x, off, csrc, bufA, gi0);
        tf32_gemm_kernel<1, 1, 0, 0><<<dim3(2, HB / 128), 256>>>(bufA, wc1, b1, h1, HB, 256, 256);
        build_A2_kernel<<<dim3(PP, NGP), 256>>>(h1, idx, off, csrc, bufB, gi0);
        tf32_gemm_kernel<0, 1, 0, 0><<<dim3(2, HB2 / 128), 256>>>(bufB, wc2, b2, h2, HB2, 512, 256);
        gather_norm2_kernel<<<dim3(PP, NGP), 256>>>(h2, att_out, hbuf, h_t, g);
    }

    // ---- Transformer (PRE tf32 tensor-core GEMMs) ----
    for (int l = 0; l < NLAY; l++) {
        tf32_gemm_kernel<0, 0, 1, 0><<<dim3(12, NTOK / 128), 256>>>(
            h_t, wqkv + (size_t)l * 512 * 1536, bqkv + l * 1536, qkv, NTOK, 512, 1536);
        attn_kernel<<<PP * NHEAD, 128>>>(qkv, tmp);
        tf32_gemm_kernel<0, 0, 1, 0><<<dim3(4, NTOK / 128), 256>>>(
            tmp, wo_t + (size_t)l * 512 * 512, bo + l * 512, ffb, NTOK, 512, 512);
        resid_ln_kernel<<<NTOK, 128>>>(hbuf, ffb, g1 + l * 512, bg1 + l * 512, h_t);
        tf32_gemm_kernel<1, 0, 1, 1><<<dim3(16, NTOK / 128), 256>>>(
            h_t, wf1_t + (size_t)l * 512 * 2048, bf1 + l * 2048, ffb, NTOK, 512, 2048);
        tf32_gemm_kernel<0, 0, 1, 0><<<dim3(4, NTOK / 128), 256>>>(
            ffb, wf2_t + (size_t)l * 2048 * 512, bf2 + l * 512, tmp, NTOK, 2048, 512);
        resid_ln_kernel<<<NTOK, 128>>>(hbuf, tmp, g2 + l * 512, bg2 + l * 512, h_t);
    }

    out_kernel<<<NTOK / 8, 256>>>(hbuf, Wout, scal_out);
}

// round 14
// speedup vs baseline: 1.3170x; 1.0098x over previous
#include <cuda_runtime.h>
#include <cstdint>

// ---------------------------------------------------------------------------
// Problem constants
// ---------------------------------------------------------------------------
#define TT     16
#define NN     20000
#define NP     20096            // NN padded to multiple of 128
#define NG     32               // 32 (t, graph) instances, gi = g*16 + t
#define EE     320000
#define PP     4096
#define DIN    128
#define NHEAD  8
#define NLAY   2
#define DM     512
#define NTOK   (TT * PP)     // 65536
#define HB1    (NG * NP)     // 643072 rows (layer-1 GEMM)
#define HB2    (NG * PP)     // 131072 rows (layer-2 GEMM, selected only)

// ---------------------------------------------------------------------------
// Scratch blobs (total .bss ~2.76 GB < 4GB aarch64 ADRP limit)
// Aliasing: h1 and bufA coexist; bufB and h2 alias dead bufA.
// ---------------------------------------------------------------------------
constexpr size_t S_H1   = 0;                             // [HB1, 256]
constexpr size_t S_BUFA = (size_t)HB1 * 256;             // [HB1, 256]
constexpr size_t S_BUFB = S_BUFA;                        // [HB2, 512] alias
constexpr size_t S_H2   = S_BUFA + (size_t)HB2 * 512;    // [HB2, 256] alias (disjoint)
constexpr size_t S_TOTAL= (size_t)HB1 * 512;             // ~1.32 GB
__device__ float g_sage[S_TOTAL];

// weights region
constexpr size_t W_WC1   = 0;                          // [256,256] stacked fp32
constexpr size_t W_WC2   = W_WC1  + 256ull * 256;      // [512,256]
constexpr size_t W_WQKV  = W_WC2  + 512ull * 256;      // [2,512,1536] tf32-rounded
constexpr size_t W_BQKV  = W_WQKV + 2ull * 512 * 1536; // [2,1536] fp32
constexpr size_t W_WO    = W_BQKV + 2ull * 1536;       // [2,512,512] tf32-rounded
constexpr size_t W_WF1   = W_WO   + 2ull * 512 * 512;  // [2,512,2048] tf32-rounded
constexpr size_t W_WF2   = W_WF1  + 2ull * 512 * 2048; // [2,2048,512] tf32-rounded
constexpr size_t W_TOTAL = W_WF2  + 2ull * 2048 * 512;
__device__ float g_w[W_TOTAL];

// activations region (~1.34 GB)
constexpr size_t A_H    = 0;                           // [NTOK,512]  fp32 hidden
constexpr size_t A_HT   = A_H   + (size_t)NTOK * 512;  // [NTOK,512]  tf32-rounded hidden
constexpr size_t A_QKV  = A_HT  + (size_t)NTOK * 512;  // [NTOK,1536]
constexpr size_t A_TMP  = A_QKV + (size_t)NTOK * 1536; // [NTOK,512]
constexpr size_t A_FF   = A_TMP + (size_t)NTOK * 512;  // [NTOK,2048]
constexpr size_t A_TOTAL= A_FF  + (size_t)NTOK * 2048;
__device__ float g_act[A_TOTAL];

// CSR int region (~49 MB)
constexpr size_t I_DEG = 0;
constexpr size_t I_CUR = I_DEG + (size_t)NG * NN;
constexpr size_t I_OFF = I_CUR + (size_t)NG * NN;
constexpr size_t I_CSR = I_OFF + (size_t)NG * (NN + 1);
constexpr size_t I_TOTAL = I_CSR + (size_t)NG * EE;
__device__ int g_iblob[I_TOTAL];

// ---------------------------------------------------------------------------
// numeric helpers
// ---------------------------------------------------------------------------
__device__ __forceinline__ uint32_t f2tf(float f) {
    uint32_t r;
    asm("cvt.rna.tf32.f32 %0, %1;" : "=r"(r) : "f"(f));
    return r;
}

__device__ __forceinline__ void bf16_split_pack(float v0, float v1,
                                                uint32_t& hi, uint32_t& lo) {
    uint32_t h;
    asm("cvt.rn.bf16x2.f32 %0, %1, %2;" : "=r"(h) : "f"(v1), "f"(v0));
    float h0 = __uint_as_float(h << 16);
    float h1 = __uint_as_float(h & 0xFFFF0000u);
    hi = h;
    asm("cvt.rn.bf16x2.f32 %0, %1, %2;" : "=r"(lo) : "f"(v1 - h1), "f"(v0 - h0));
}

__device__ __forceinline__ void cp16(uint32_t daddr, const void* src) {
    asm volatile("cp.async.cg.shared.global [%0], [%1], 16;" :: "r"(daddr), "l"(src));
}

// ---------------------------------------------------------------------------
// Batched CSR construction
// ---------------------------------------------------------------------------
__global__ void hist_b_kernel(const int* __restrict__ dst_i, const int* __restrict__ dst_j,
                              int* __restrict__ deg) {
    int gi = blockIdx.y;
    int t = gi & 15, g = gi >> 4;
    const int* dst = (g == 0 ? dst_i : dst_j) + (size_t)t * EE;
    int* d = deg + (size_t)gi * NN;
    int e = blockIdx.x * blockDim.x + threadIdx.x;
    if (e < EE) atomicAdd(&d[dst[e]], 1);
}

__global__ void __launch_bounds__(1024)
scan_b_kernel(const int* __restrict__ deg_all, int* __restrict__ off_all) {
    __shared__ int wsum[32];
    const int CH = 20;
    int gi = blockIdx.x;
    const int* deg = deg_all + (size_t)gi * NN;
    int* off = off_all + (size_t)gi * (NN + 1);
    int tid = threadIdx.x;
    int lane = tid & 31, warp = tid >> 5;
    int base = tid * CH;
    int loc[CH];
    int s = 0;
#pragma unroll
    for (int i = 0; i < CH; i++) {
        int idx = base + i;
        int v = (idx < NN) ? deg[idx] : 0;
        s += v;
        loc[i] = s;
    }
    int ssum = s;
#pragma unroll
    for (int o = 1; o < 32; o <<= 1) {
        int t = __shfl_up_sync(0xffffffffu, ssum, o);
        if (lane >= o) ssum += t;
    }
    if (lane == 31) wsum[warp] = ssum;
    __syncthreads();
    if (warp == 0) {
        int w = wsum[lane];
#pragma unroll
        for (int o = 1; o < 32; o <<= 1) {
            int t = __shfl_up_sync(0xffffffffu, w, o);
            if (lane >= o) w += t;
        }
        wsum[lane] = w;
    }
    __syncthreads();
    int offset = ssum - s + (warp ? wsum[warp - 1] : 0);
    if (tid == 0) off[0] = 0;
#pragma unroll
    for (int i = 0; i < CH; i++) {
        int idx = base + i;
        if (idx < NN) off[idx + 1] = offset + loc[i];
    }
}

__global__ void fill_b_kernel(const int* __restrict__ src_i, const int* __restrict__ src_j,
                              const int* __restrict__ dst_i, const int* __restrict__ dst_j,
                              const int* __restrict__ off_all, int* __restrict__ cur_all,
                              int* __restrict__ csrc_all) {
    int gi = blockIdx.y;
    int t = gi & 15, g = gi >> 4;
    const int* src = (g == 0 ? src_i : src_j) + (size_t)t * EE;
    const int* dst = (g == 0 ? dst_i : dst_j) + (size_t)t * EE;
    const int* off = off_all + (size_t)gi * (NN + 1);
    int* cur = cur_all + (size_t)gi * NN;
    int* csrc = csrc_all + (size_t)gi * EE;
    int e = blockIdx.x * blockDim.x + threadIdx.x;
    if (e < EE) {
        int d = dst[e];
        int p = atomicAdd(&cur[d], 1);
        csrc[off[d] + p] = src[e];
    }
}

// ---------------------------------------------------------------------------
// Layer-1 build A = [self | mean_agg] for ALL nodes.  grid (NN, NG), block 128.
// ---------------------------------------------------------------------------
__global__ void build_A1_kernel(const float* __restrict__ x_i, const float* __restrict__ x_j,
                                const int* __restrict__ off_all, const int* __restrict__ csrc_all,
                                float* __restrict__ out_all) {
    int gi = blockIdx.y;
    int t = gi & 15, g = gi >> 4;
    const float* feat = (g == 0 ? x_i : x_j) + (size_t)t * NN * DIN;
    const int* off = off_all + (size_t)gi * (NN + 1);
    const int* csrc = csrc_all + (size_t)gi * EE;
    float* out = out_all + (size_t)gi * NP * 256;

    int n = blockIdx.x;
    int f = threadIdx.x;
    float self = feat[(size_t)n * DIN + f];
    int s = off[n], e = off[n + 1];
    float acc = 0.f;
    int i = s;
    for (; i + 4 <= e; i += 4) {
        int a0 = csrc[i], a1 = csrc[i + 1], a2 = csrc[i + 2], a3 = csrc[i + 3];
        float v0 = feat[(size_t)a0 * DIN + f];
        float v1 = feat[(size_t)a1 * DIN + f];
        float v2 = feat[(size_t)a2 * DIN + f];
        float v3 = feat[(size_t)a3 * DIN + f];
        acc += v0 + v1 + v2 + v3;
    }
    for (; i < e; i++) acc += feat[(size_t)csrc[i] * DIN + f];
    int d = e - s; if (d < 1) d = 1;
    size_t ob = (size_t)n * 256;
    out[ob + f]       = self;
    out[ob + 128 + f] = acc / (float)d;
}

// ---------------------------------------------------------------------------
// Layer-2 build A for SELECTED nodes only.  grid (PP, NG), block 256.
// ---------------------------------------------------------------------------
__global__ void build_A2_kernel(const float* __restrict__ h1_all,
                                const int* __restrict__ idx_i, const int* __restrict__ idx_j,
                                const int* __restrict__ off_all, const int* __restrict__ csrc_all,
                                float* __restrict__ out_all) {
    int gi = blockIdx.y;
    int t = gi & 15, g = gi >> 4;
    const float* feat = h1_all + (size_t)gi * NP * 256;
    const int* off = off_all + (size_t)gi * (NN + 1);
    const int* csrc = csrc_all + (size_t)gi * EE;
    const int* idx = ((g == 0) ? idx_i : idx_j) + (size_t)t * PP;
    float* out = out_all + (size_t)gi * PP * 512;

    int p = blockIdx.x;
    int n = idx[p];
    int f = threadIdx.x;
    float self = feat[(size_t)n * 256 + f];
    int s = off[n], e = off[n + 1];
    float acc = 0.f;
    int i = s;
    for (; i + 4 <= e; i += 4) {
        int a0 = csrc[i], a1 = csrc[i + 1], a2 = csrc[i + 2], a3 = csrc[i + 3];
        float v0 = feat[(size_t)a0 * 256 + f];
        float v1 = feat[(size_t)a1 * 256 + f];
        float v2 = feat[(size_t)a2 * 256 + f];
        float v3 = feat[(size_t)a3 * 256 + f];
        acc += v0 + v1 + v2 + v3;
    }
    for (; i < e; i++) acc += feat[(size_t)csrc[i] * 256 + f];
    int d = e - s; if (d < 1) d = 1;
    size_t ob = (size_t)p * 512;
    out[ob + f]       = self;
    out[ob + 256 + f] = acc / (float)d;
}

// ---------------------------------------------------------------------------
// Tensor-core GEMM.  C = A@B + bias (+relu).  128x128x16 block tile,
// 256 threads = 8 warps as 2(m) x 4(n), warp tile 64x32, cp.async dbl-buffered.
// BF16S : bf16 2-way-split (hi/lo), 3x m16n8k16 per chunk — SAGE path.
// PRE   : operands already tf32-rounded in gmem — m16n8k8 tf32, no cvt.
// OROUND: round C store to tf32 bits (feeds a later PRE GEMM).
// ---------------------------------------------------------------------------
#define AS_STRIDE 20
#define BS_STRIDE 136

#define MMA_TF32(d, a, b)                                                            \
    asm volatile(                                                                    \
        "mma.sync.aligned.m16n8k8.row.col.f32.tf32.tf32.f32 "                        \
        "{%0,%1,%2,%3},{%4,%5,%6,%7},{%8,%9},{%0,%1,%2,%3};"                         \
        : "+f"(d[0]), "+f"(d[1]), "+f"(d[2]), "+f"(d[3])                             \
        : "r"(a[0]), "r"(a[1]), "r"(a[2]), "r"(a[3]), "r"(b[0]), "r"(b[1]))

#define MMA_BF16(d, a, b)                                                            \
    asm volatile(                                                                    \
        "mma.sync.aligned.m16n8k16.row.col.f32.bf16.bf16.f32 "                       \
        "{%0,%1,%2,%3},{%4,%5,%6,%7},{%8,%9},{%0,%1,%2,%3};"                         \
        : "+f"(d[0]), "+f"(d[1]), "+f"(d[2]), "+f"(d[3])                             \
        : "r"(a[0]), "r"(a[1]), "r"(a[2]), "r"(a[3]), "r"(b[0]), "r"(b[1]))

template <int RELU, int BF16S, int PRE, int OROUND>
__global__ void __launch_bounds__(256)
tf32_gemm_kernel(const float* __restrict__ A, const float* __restrict__ B,
                 const float* __restrict__ bias, float* __restrict__ C,
                 int M, int K, int N) {
    __shared__ __align__(16) float As[2][128][AS_STRIDE];
    __shared__ __align__(16) float Bs[2][16][BS_STRIDE];

    int tid  = threadIdx.x;
    int warp = tid >> 5;
    int lane = tid & 31;
    int gid  = lane >> 2;
    int tq   = lane & 3;
    int wm   = warp >> 2;
    int wn   = warp & 3;

    int bm = blockIdx.y * 128;
    int bn = blockIdx.x * 128;

    float acc[4][4][4];
#pragma unroll
    for (int i = 0; i < 4; i++)
#pragma unroll
        for (int j = 0; j < 4; j++)
#pragma unroll
            for (int r = 0; r < 4; r++) acc[i][j][r] = 0.f;

    int nk = K >> 4;
    const float* Abase = A + (size_t)bm * K;
    const float* Bbase = B + bn;

    auto load_stage = [&](int stage, int k0) {
#pragma unroll
        for (int it = 0; it < 2; it++) {
            int i = tid + it * 256;
            int row = i >> 2, c4 = (i & 3) << 2;
            uint32_t d = (uint32_t)__cvta_generic_to_shared(&As[stage][row][c4]);
            cp16(d, Abase + (size_t)row * K + k0 + c4);
        }
#pragma unroll
        for (int it = 0; it < 2; it++) {
            int i = tid + it * 256;
            int row = i >> 5, c4 = (i & 31) << 2;
            uint32_t d = (uint32_t)__cvta_generic_to_shared(&Bs[stage][row][c4]);
            cp16(d, Bbase + (size_t)(k0 + row) * N + c4);
        }
    };

    load_stage(0, 0);
    asm volatile("cp.async.commit_group;");

    for (int kc = 0; kc < nk; kc++) {
        int cur = kc & 1;
        if (kc + 1 < nk) {
            load_stage(cur ^ 1, (kc + 1) << 4);
            asm volatile("cp.async.commit_group;");
            asm volatile("cp.async.wait_group 1;");
        } else {
            asm volatile("cp.async.wait_group 0;");
        }
        __syncthreads();

        if (BF16S) {
            uint32_t ahi[4][4], alo[4][4], bhi[4][2], blo[4][2];
#pragma unroll
            for (int mt = 0; mt < 4; mt++) {
                int m = wm * 64 + mt * 16;
                float2 q0 = *(const float2*)&As[cur][m + gid][tq * 2];
                float2 q1 = *(const float2*)&As[cur][m + gid + 8][tq * 2];
                float2 q2 = *(const float2*)&As[cur][m + gid][tq * 2 + 8];
                float2 q3 = *(const float2*)&As[cur][m + gid + 8][tq * 2 + 8];
                bf16_split_pack(q0.x, q0.y, ahi[mt][0], alo[mt][0]);
                bf16_split_pack(q1.x, q1.y, ahi[mt][1], alo[mt][1]);
                bf16_split_pack(q2.x, q2.y, ahi[mt][2], alo[mt][2]);
                bf16_split_pack(q3.x, q3.y, ahi[mt][3], alo[mt][3]);
            }
#pragma unroll
            for (int nt = 0; nt < 4; nt++) {
                int n = wn * 32 + nt * 8;
                float u0 = Bs[cur][tq * 2][n + gid];
                float u1 = Bs[cur][tq * 2 + 1][n + gid];
                float u2 = Bs[cur][tq * 2 + 8][n + gid];
                float u3 = Bs[cur][tq * 2 + 9][n + gid];
                bf16_split_pack(u0, u1, bhi[nt][0], blo[nt][0]);
                bf16_split_pack(u2, u3, bhi[nt][1], blo[nt][1]);
            }
#pragma unroll
            for (int mt = 0; mt < 4; mt++)
#pragma unroll
                for (int nt = 0; nt < 4; nt++) {
                    MMA_BF16(acc[mt][nt], ahi[mt], bhi[nt]);
                    MMA_BF16(acc[mt][nt], ahi[mt], blo[nt]);
                    MMA_BF16(acc[mt][nt], alo[mt], bhi[nt]);
                }
        } else {
#pragma unroll
            for (int ks = 0; ks < 16; ks += 8) {
                uint32_t af[4][4], bf[4][2];
#pragma unroll
                for (int mt = 0; mt < 4; mt++) {
                    int m = wm * 64 + mt * 16;
                    float v0 = As[cur][m + gid][ks + tq];
                    float v1 = As[cur][m + gid + 8][ks + tq];
                    float v2 = As[cur][m + gid][ks + tq + 4];
                    float v3 = As[cur][m + gid + 8][ks + tq + 4];
                    if (PRE) {
                        af[mt][0] = __float_as_uint(v0); af[mt][1] = __float_as_uint(v1);
                        af[mt][2] = __float_as_uint(v2); af[mt][3] = __float_as_uint(v3);
                    } else {
                        af[mt][0] = f2tf(v0); af[mt][1] = f2tf(v1);
                        af[mt][2] = f2tf(v2); af[mt][3] = f2tf(v3);
                    }
                }
#pragma unroll
                for (int nt = 0; nt < 4; nt++) {
                    int n = wn * 32 + nt * 8;
                    float u0 = Bs[cur][ks + tq][n + gid];
                    float u1 = Bs[cur][ks + tq + 4][n + gid];
                    if (PRE) {
                        bf[nt][0] = __float_as_uint(u0); bf[nt][1] = __float_as_uint(u1);
                    } else {
                        bf[nt][0] = f2tf(u0); bf[nt][1] = f2tf(u1);
                    }
                }
#pragma unroll
                for (int mt = 0; mt < 4; mt++)
#pragma unroll
                    for (int nt = 0; nt < 4; nt++)
                        MMA_TF32(acc[mt][nt], af[mt], bf[nt]);
            }
        }
        __syncthreads();
    }

#pragma unroll
    for (int mt = 0; mt < 4; mt++) {
        int gr = bm + wm * 64 + mt * 16 + gid;
#pragma unroll
        for (int nt = 0; nt < 4; nt++) {
            int gc = bn + wn * 32 + nt * 8 + tq * 2;
            float2 bv = *(const float2*)&bias[gc];
            float v0 = acc[mt][nt][0] + bv.x;
            float v1 = acc[mt][nt][1] + bv.y;
            float v2 = acc[mt][nt][2] + bv.x;
            float v3 = acc[mt][nt][3] + bv.y;
            if (RELU) {
                v0 = fmaxf(v0, 0.f); v1 = fmaxf(v1, 0.f);
                v2 = fmaxf(v2, 0.f); v3 = fmaxf(v3, 0.f);
            }
            if (OROUND) {
                v0 = __uint_as_float(f2tf(v0)); v1 = __uint_as_float(f2tf(v1));
                v2 = __uint_as_float(f2tf(v2)); v3 = __uint_as_float(f2tf(v3));
            }
            *(float2*)&C[(size_t)gr * N + gc]       = make_float2(v0, v1);
            *(float2*)&C[(size_t)(gr + 8) * N + gc] = make_float2(v2, v3);
        }
    }
}

// ---------------------------------------------------------------------------
// Gather (compact rows) + L2-normalize.  grid (PP, NG), block 256.
// ---------------------------------------------------------------------------
__global__ void gather_norm2_kernel(const float* __restrict__ h2c,
                                    float* __restrict__ att_out, float* __restrict__ h,
                                    float* __restrict__ h_t) {
    int gi = blockIdx.y;
    int t = gi & 15, g = gi >> 4;
    int p = blockIdx.x;
    int f = threadIdx.x;
    float v = h2c[((size_t)gi * PP + p) * 256 + f];
    float s = v * v;
    __shared__ float red[8];
    for (int o = 16; o; o >>= 1) s += __shfl_xor_sync(0xffffffffu, s, o);
    if ((f & 31) == 0) red[f >> 5] = s;
    __syncthreads();
    float tot = red[0] + red[1] + red[2] + red[3] + red[4] + red[5] + red[6] + red[7];
    float norm = fmaxf(sqrtf(tot), 1e-12f);
    v /= norm;
    size_t o = ((size_t)(t * PP + p)) * DM + g * 256 + f;
    att_out[o] = v;
    h[o]       = v;
    h_t[o]     = __uint_as_float(f2tf(v));
}

// ---------------------------------------------------------------------------
// Banded attention: window 4, T=16.  One block per (p, head), 128 threads.
// ---------------------------------------------------------------------------
__global__ void attn_kernel(const float* __restrict__ qkv, float* __restrict__ out) {
    int ph = blockIdx.x;
    int p = ph >> 3;
    int h = ph & 7;
    __shared__ float qs[16][64], ks[16][64], vs[16][64];
    int tid = threadIdx.x;
    for (int i = tid; i < 256; i += 128) {
        int t = i >> 4, d4 = (i & 15) << 2;
        const float4* b = (const float4*)(qkv + ((size_t)(t * PP + p)) * 1536 + h * 64 + d4);
        *(float4*)&qs[t][d4] = b[0];
        *(float4*)&ks[t][d4] = b[128];
        *(float4*)&vs[t][d4] = b[256];
    }
    __syncthreads();
    int warp = tid >> 5, lane = tid & 31;
    for (int t = warp; t < 16; t += 4) {
        int s0 = t - 3; if (s0 < 0) s0 = 0;
        int ns = t - s0 + 1;
        float sc[4];
        float mx = -1e30f;
        for (int si = 0; si < ns; si++) {
            int s = s0 + si;
            float d0 = qs[t][lane] * ks[s][lane] + qs[t][lane + 32] * ks[s][lane + 32];
            for (int o = 16; o; o >>= 1) d0 += __shfl_xor_sync(0xffffffffu, d0, o);
            d0 *= 0.125f;
            sc[si] = d0;
            mx = fmaxf(mx, d0);
        }
        float sum = 0.f;
        for (int si = 0; si < ns; si++) { sc[si] = expf(sc[si] - mx); sum += sc[si]; }
        float inv = 1.f / sum;
        float o0 = 0.f, o1 = 0.f;
        for (int si = 0; si < ns; si++) {
            int s = s0 + si;
            o0 += sc[si] * vs[s][lane];
            o1 += sc[si] * vs[s][lane + 32];
        }
        size_t ob = ((size_t)(t * PP + p)) * DM + h * 64;
        out[ob + lane]      = __uint_as_float(f2tf(o0 * inv));
        out[ob + lane + 32] = __uint_as_float(f2tf(o1 * inv));
    }
}

// ---------------------------------------------------------------------------
// h = LayerNorm(h + delta) * g + b; emits tf32-rounded copy h_t.
// ---------------------------------------------------------------------------
__global__ void resid_ln_kernel(float* __restrict__ h, const float* __restrict__ delta,
                                const float* __restrict__ g, const float* __restrict__ b,
                                float* __restrict__ h_t) {
    int row = blockIdx.x;
    int tid = threadIdx.x;
    size_t base = (size_t)row * DM;
    float v[4];
    float s = 0.f;
#pragma unroll
    for (int i = 0; i < 4; i++) {
        int c = tid + i * 128;
        float x = h[base + c] + delta[base + c];
        v[i] = x; s += x;
    }
    __shared__ float red[4];
    for (int o = 16; o; o >>= 1) s += __shfl_xor_sync(0xffffffffu, s, o);
    if ((tid & 31) == 0) red[tid >> 5] = s;
    __syncthreads();
    float mean = (red[0] + red[1] + red[2] + red[3]) * (1.f / 512.f);
    __syncthreads();
    float s2 = 0.f;
#pragma unroll
    for (int i = 0; i < 4; i++) { float d = v[i] - mean; s2 += d * d; }
    for (int o = 16; o; o >>= 1) s2 += __shfl_xor_sync(0xffffffffu, s2, o);
    if ((tid & 31) == 0) red[tid >> 5] = s2;
    __syncthreads();
    float var = (red[0] + red[1] + red[2] + red[3]) * (1.f / 512.f);
    float rstd = rsqrtf(var + 1e-5f);
#pragma unroll
    for (int i = 0; i < 4; i++) {
        int c = tid + i * 128;
        float o = (v[i] - mean) * rstd * g[c] + b[c];
        h[base + c]   = o;
        h_t[base + c] = __uint_as_float(f2tf(o));
    }
}

// ---------------------------------------------------------------------------
// FINAL layer: LayerNorm(h + delta)*g + b, then dot with Wout -> scal_out.
// No h / h_t stores.  grid = NTOK, block = 128.
// ---------------------------------------------------------------------------
__global__ void resid_ln_out_kernel(const float* __restrict__ h, const float* __restrict__ delta,
                                    const float* __restrict__ g, const float* __restrict__ b,
                                    const float* __restrict__ Wout, float* __restrict__ out) {
    int row = blockIdx.x;
    int tid = threadIdx.x;
    size_t base = (size_t)row * DM;
    float v[4];
    float s = 0.f;
#pragma unroll
    for (int i = 0; i < 4; i++) {
        int c = tid + i * 128;
        float x = h[base + c] + delta[base + c];
        v[i] = x; s += x;
    }
    __shared__ float red[4];
    for (int o = 16; o; o >>= 1) s += __shfl_xor_sync(0xffffffffu, s, o);
    if ((tid & 31) == 0) red[tid >> 5] = s;
    __syncthreads();
    float mean = (red[0] + red[1] + red[2] + red[3]) * (1.f / 512.f);
    __syncthreads();
    float s2 = 0.f;
#pragma unroll
    for (int i = 0; i < 4; i++) { float d = v[i] - mean; s2 += d * d; }
    for (int o = 16; o; o >>= 1) s2 += __shfl_xor_sync(0xffffffffu, s2, o);
    if ((tid & 31) == 0) red[tid >> 5] = s2;
    __syncthreads();
    float var = (red[0] + red[1] + red[2] + red[3]) * (1.f / 512.f);
    float rstd = rsqrtf(var + 1e-5f);
    float dot = 0.f;
#pragma unroll
    for (int i = 0; i < 4; i++) {
        int c = tid + i * 128;
        float o = (v[i] - mean) * rstd * g[c] + b[c];
        dot += o * Wout[c];
    }
    __syncthreads();
    for (int o = 16; o; o >>= 1) dot += __shfl_xor_sync(0xffffffffu, dot, o);
    if ((tid & 31) == 0) red[tid >> 5] = dot;
    __syncthreads();
    if (tid == 0) out[row] = red[0] + red[1] + red[2] + red[3];
}

// ---------------------------------------------------------------------------
// Weight prep
// ---------------------------------------------------------------------------
__global__ void prep_wc_kernel(const float* __restrict__ W1s, const float* __restrict__ W1n,
                               const float* __restrict__ W2s, const float* __restrict__ W2n,
                               float* __restrict__ wc1, float* __restrict__ wc2) {
    int i = blockIdx.x * blockDim.x + threadIdx.x;
    if (i < 256 * 256) {
        int k = i >> 8, c = i & 255;
        wc1[i] = (k < 128) ? W1s[k * 256 + c] : W1n[(k - 128) * 256 + c];
    }
    if (i < 512 * 256) {
        int k = i >> 8, c = i & 255;
        wc2[i] = (k < 256) ? W2s[k * 256 + c] : W2n[(k - 256) * 256 + c];
    }
}

__global__ void prep_wqkv_kernel(const float* __restrict__ Wq, const float* __restrict__ Wk,
                                 const float* __restrict__ Wv,
                                 const float* __restrict__ bq, const float* __restrict__ bk,
                                 const float* __restrict__ bv,
                                 float* __restrict__ Wqkv, float* __restrict__ bqkv) {
    int i = blockIdx.x * blockDim.x + threadIdx.x;
    const int tot = 2 * 512 * 1536;
    if (i < tot) {
        int l = i / (512 * 1536);
        int rem = i % (512 * 1536);
        int r = rem / 1536, c = rem % 1536;
        float v;
        size_t wb = (size_t)l * 512 * 512 + (size_t)r * 512;
        if (c < 512)       v = Wq[wb + c];
        else if (c < 1024) v = Wk[wb + (c - 512)];
        else               v = Wv[wb + (c - 1024)];
        Wqkv[i] = __uint_as_float(f2tf(v));
    }
    if (i < 2 * 1536) {
        int l = i / 1536, c = i % 1536;
        float v;
        if (c < 512)       v = bq[l * 512 + c];
        else if (c < 1024) v = bk[l * 512 + c - 512];
        else               v = bv[l * 512 + c - 1024];
        bqkv[i] = v;
    }
}

__global__ void prep_round_kernel(const float* __restrict__ Wo, const float* __restrict__ Wf1,
                                  const float* __restrict__ Wf2,
                                  float* __restrict__ wo_t, float* __restrict__ wf1_t,
                                  float* __restrict__ wf2_t) {
    const int NWO  = 2 * 512 * 512;
    const int NWF1 = 2 * 512 * 2048;
    const int NWF2 = 2 * 2048 * 512;
    int i = blockIdx.x * blockDim.x + threadIdx.x;
    if (i < NWO)  wo_t[i]  = __uint_as_float(f2tf(Wo[i]));
    if (i < NWF1) wf1_t[i] = __uint_as_float(f2tf(Wf1[i]));
    if (i < NWF2) wf2_t[i] = __uint_as_float(f2tf(Wf2[i]));
}

// ---------------------------------------------------------------------------
// Host driver
// ---------------------------------------------------------------------------
extern "C" void kernel_launch(void* const* d_in, const int* in_sizes, int n_in,
                              void* d_out, int out_size) {
    const float* x_i   = (const float*)d_in[0];
    const float* x_j   = (const float*)d_in[1];
    const int*   src_i = (const int*)d_in[2];
    const int*   dst_i = (const int*)d_in[3];
    const int*   src_j = (const int*)d_in[4];
    const int*   dst_j = (const int*)d_in[5];
    const int*   idx_i = (const int*)d_in[6];
    const int*   idx_j = (const int*)d_in[7];
    const float* W1s = (const float*)d_in[8];
    const float* W1n = (const float*)d_in[9];
    const float* b1  = (const float*)d_in[10];
    const float* W2s = (const float*)d_in[11];
    const float* W2n = (const float*)d_in[12];
    const float* b2  = (const float*)d_in[13];
    const float* Wq  = (const float*)d_in[14];
    const float* Wk  = (const float*)d_in[15];
    const float* Wv  = (const float*)d_in[16];
    const float* bq  = (const float*)d_in[17];
    const float* bk  = (const float*)d_in[18];
    const float* bv  = (const float*)d_in[19];
    const float* Wo  = (const float*)d_in[20];
    const float* bo  = (const float*)d_in[21];
    const float* Wf1 = (const float*)d_in[22];
    const float* bf1 = (const float*)d_in[23];
    const float* Wf2 = (const float*)d_in[24];
    const float* bf2 = (const float*)d_in[25];
    const float* g1  = (const float*)d_in[26];
    const float* bg1 = (const float*)d_in[27];
    const float* g2  = (const float*)d_in[28];
    const float* bg2 = (const float*)d_in[29];
    const float* Wout= (const float*)d_in[30];

    void* p;
    cudaGetSymbolAddress(&p, g_sage);  float* SB = (float*)p;
    cudaGetSymbolAddress(&p, g_w);     float* WB = (float*)p;
    cudaGetSymbolAddress(&p, g_act);   float* AB = (float*)p;
    cudaGetSymbolAddress(&p, g_iblob); int*   IB = (int*)p;

    float* h1   = SB + S_H1;
    float* bufA = SB + S_BUFA;
    float* bufB = SB + S_BUFB;   // alias of bufA (disjoint lifetime)
    float* h2   = SB + S_H2;     // alias inside bufA region (disjoint lifetime)

    float* wc1   = WB + W_WC1;
    float* wc2   = WB + W_WC2;
    float* wqkv  = WB + W_WQKV;
    float* bqkv  = WB + W_BQKV;
    float* wo_t  = WB + W_WO;
    float* wf1_t = WB + W_WF1;
    float* wf2_t = WB + W_WF2;

    float* hbuf = AB + A_H;
    float* h_t  = AB + A_HT;
    float* qkv  = AB + A_QKV;
    float* tmp  = AB + A_TMP;
    float* ffb  = AB + A_FF;

    int* deg  = IB + I_DEG;
    int* cur  = IB + I_CUR;
    int* off  = IB + I_OFF;
    int* csrc = IB + I_CSR;

    float* att_out  = (float*)d_out;
    float* scal_out = att_out + (size_t)NTOK * DM;

    // ---- weight prep ----
    prep_wc_kernel<<<(512 * 256 + 255) / 256, 256>>>(W1s, W1n, W2s, W2n, wc1, wc2);
    prep_wqkv_kernel<<<(2 * 512 * 1536 + 255) / 256, 256>>>(Wq, Wk, Wv, bq, bk, bv, wqkv, bqkv);
    prep_round_kernel<<<(2 * 512 * 2048 + 255) / 256, 256>>>(Wo, Wf1, Wf2, wo_t, wf1_t, wf2_t);

    // ---- batched CSR for all NG graphs ----
    cudaMemsetAsync(IB, 0, (size_t)2 * NG * NN * sizeof(int));   // deg + cur
    hist_b_kernel<<<dim3((EE + 255) / 256, NG), 256>>>(dst_i, dst_j, deg);
    scan_b_kernel<<<NG, 1024>>>(deg, off);
    fill_b_kernel<<<dim3((EE + 255) / 256, NG), 256>>>(src_i, src_j, dst_i, dst_j, off, cur, csrc);

    // ---- GraphSAGE, single batched pass over all 32 instances ----
    build_A1_kernel<<<dim3(NN, NG), 128>>>(x_i, x_j, off, csrc, bufA);
    tf32_gemm_kernel<1, 1, 0, 0><<<dim3(2, HB1 / 128), 256>>>(bufA, wc1, b1, h1, HB1, 256, 256);
    build_A2_kernel<<<dim3(PP, NG), 256>>>(h1, idx_i, idx_j, off, csrc, bufB);
    tf32_gemm_kernel<0, 1, 0, 0><<<dim3(2, HB2 / 128), 256>>>(bufB, wc2, b2, h2, HB2, 512, 256);
    gather_norm2_kernel<<<dim3(PP, NG), 256>>>(h2, att_out, hbuf, h_t);

    // ---- Transformer (PRE tf32 tensor-core GEMMs) ----
    for (int l = 0; l < NLAY; l++) {
        tf32_gemm_kernel<0, 0, 1, 0><<<dim3(12, NTOK / 128), 256>>>(
            h_t, wqkv + (size_t)l * 512 * 1536, bqkv + l * 1536, qkv, NTOK, 512, 1536);
        attn_kernel<<<PP * NHEAD, 128>>>(qkv, tmp);
        tf32_gemm_kernel<0, 0, 1, 0><<<dim3(4, NTOK / 128), 256>>>(
            tmp, wo_t + (size_t)l * 512 * 512, bo + l * 512, ffb, NTOK, 512, 512);
        resid_ln_kernel<<<NTOK, 128>>>(hbuf, ffb, g1 + l * 512, bg1 + l * 512, h_t);
        tf32_gemm_kernel<1, 0, 1, 1><<<dim3(16, NTOK / 128), 256>>>(
            h_t, wf1_t + (size_t)l * 512 * 2048, bf1 + l * 2048, ffb, NTOK, 512, 2048);
        tf32_gemm_kernel<0, 0, 1, 0><<<dim3(4, NTOK / 128), 256>>>(
            ffb, wf2_t + (size_t)l * 2048 * 512, bf2 + l * 512, tmp, NTOK, 2048, 512);
        if (l < NLAY - 1) {
            resid_ln_kernel<<<NTOK, 128>>>(hbuf, tmp, g2 + l * 512, bg2 + l * 512, h_t);
        } else {
            resid_ln_out_kernel<<<NTOK, 128>>>(hbuf, tmp, g2 + l * 512, bg2 + l * 512,
                                               Wout, scal_out);
        }
    }
}

// round 15
// speedup vs baseline: 1.6118x; 1.2239x over previous
#include <cuda_runtime.h>
#include <cuda_fp16.h>
#include <cstdint>

// ---------------------------------------------------------------------------
// Problem constants
// ---------------------------------------------------------------------------
#define TT     16
#define NN     20000
#define NP     20096            // NN padded to multiple of 128
#define NG     32               // 32 (t, graph) instances, gi = g*16 + t
#define EE     320000
#define PP     4096
#define DIN    128
#define NHEAD  8
#define NLAY   2
#define DM     512
#define NTOK   (TT * PP)     // 65536
#define HB1    (NG * NP)     // 643072 rows (layer-1 GEMM)
#define HB2    (NG * PP)     // 131072 rows (layer-2 GEMM, selected only)

// ---------------------------------------------------------------------------
// Scratch blobs (total .bss ~2.5 GB < 4GB aarch64 ADRP limit)
// ---------------------------------------------------------------------------
constexpr size_t S_H1   = 0;                             // [HB1, 256]
constexpr size_t S_BUFA = (size_t)HB1 * 256;             // [HB1, 256]
constexpr size_t S_BUFB = S_BUFA;                        // [HB2, 512] alias
constexpr size_t S_H2   = S_BUFA + (size_t)HB2 * 512;    // [HB2, 256] alias (disjoint)
constexpr size_t S_TOTAL= (size_t)HB1 * 512;             // ~1.32 GB
__device__ float g_sage[S_TOTAL];

// fp32 weights (SAGE stacked) + transformer biases
constexpr size_t W_WC1   = 0;                          // [256,256]
constexpr size_t W_WC2   = W_WC1  + 256ull * 256;      // [512,256]
constexpr size_t W_BQKV  = W_WC2  + 512ull * 256;      // [2,1536]
constexpr size_t W_TOTAL = W_BQKV + 2ull * 1536;
__device__ float g_w[W_TOTAL];

// fp32 activations (~0.27 GB)
constexpr size_t A_H    = 0;                           // [NTOK,512]  hidden
constexpr size_t A_DELTA= A_H   + (size_t)NTOK * 512;  // [NTOK,512]  GEMM fp32 out
constexpr size_t A_TOTAL= A_DELTA + (size_t)NTOK * 512;
__device__ float g_act[A_TOTAL];

// fp16 operand arrays (u16 raw bits, ~0.62 GB)
constexpr size_t H_HH   = 0;                              // [NTOK,512]  hidden fp16
constexpr size_t H_QKV  = H_HH  + (size_t)NTOK * 512;     // [NTOK,1536]
constexpr size_t H_TMP  = H_QKV + (size_t)NTOK * 1536;    // [NTOK,512]  attn out
constexpr size_t H_FFB  = H_TMP + (size_t)NTOK * 512;     // [NTOK,2048]
constexpr size_t H_WQKV = H_FFB + (size_t)NTOK * 2048;    // [2,1536,512] (transposed)
constexpr size_t H_WO   = H_WQKV + 2ull * 1536 * 512;     // [2,512,512]
constexpr size_t H_WF1  = H_WO   + 2ull * 512 * 512;      // [2,2048,512]
constexpr size_t H_WF2  = H_WF1  + 2ull * 2048 * 512;     // [2,512,2048]
constexpr size_t H_TOTAL= H_WF2  + 2ull * 512 * 2048;
__device__ uint16_t g_h16[H_TOTAL];

// CSR int region (~49 MB)
constexpr size_t I_DEG = 0;
constexpr size_t I_CUR = I_DEG + (size_t)NG * NN;
constexpr size_t I_OFF = I_CUR + (size_t)NG * NN;
constexpr size_t I_CSR = I_OFF + (size_t)NG * (NN + 1);
constexpr size_t I_TOTAL = I_CSR + (size_t)NG * EE;
__device__ int g_iblob[I_TOTAL];

// ---------------------------------------------------------------------------
// numeric helpers
// ---------------------------------------------------------------------------
__device__ __forceinline__ void bf16_split_pack(float v0, float v1,
                                                uint32_t& hi, uint32_t& lo) {
    uint32_t h;
    asm("cvt.rn.bf16x2.f32 %0, %1, %2;" : "=r"(h) : "f"(v1), "f"(v0));
    float h0 = __uint_as_float(h << 16);
    float h1 = __uint_as_float(h & 0xFFFF0000u);
    hi = h;
    asm("cvt.rn.bf16x2.f32 %0, %1, %2;" : "=r"(lo) : "f"(v1 - h1), "f"(v0 - h0));
}

__device__ __forceinline__ uint16_t f2h(float v) {
    uint16_t r;
    asm("cvt.rn.f16.f32 %0, %1;" : "=h"(r) : "f"(v));
    return r;
}

__device__ __forceinline__ uint32_t f2h2(float v0, float v1) {   // low = v0
    uint32_t r;
    asm("cvt.rn.f16x2.f32 %0, %1, %2;" : "=r"(r) : "f"(v1), "f"(v0));
    return r;
}

__device__ __forceinline__ void cp16(uint32_t daddr, const void* src) {
    asm volatile("cp.async.cg.shared.global [%0], [%1], 16;" :: "r"(daddr), "l"(src));
}

// ---------------------------------------------------------------------------
// Batched CSR construction
// ---------------------------------------------------------------------------
__global__ void hist_b_kernel(const int* __restrict__ dst_i, const int* __restrict__ dst_j,
                              int* __restrict__ deg) {
    int gi = blockIdx.y;
    int t = gi & 15, g = gi >> 4;
    const int* dst = (g == 0 ? dst_i : dst_j) + (size_t)t * EE;
    int* d = deg + (size_t)gi * NN;
    int e = blockIdx.x * blockDim.x + threadIdx.x;
    if (e < EE) atomicAdd(&d[dst[e]], 1);
}

__global__ void __launch_bounds__(1024)
scan_b_kernel(const int* __restrict__ deg_all, int* __restrict__ off_all) {
    __shared__ int wsum[32];
    const int CH = 20;
    int gi = blockIdx.x;
    const int* deg = deg_all + (size_t)gi * NN;
    int* off = off_all + (size_t)gi * (NN + 1);
    int tid = threadIdx.x;
    int lane = tid & 31, warp = tid >> 5;
    int base = tid * CH;
    int loc[CH];
    int s = 0;
#pragma unroll
    for (int i = 0; i < CH; i++) {
        int idx = base + i;
        int v = (idx < NN) ? deg[idx] : 0;
        s += v;
        loc[i] = s;
    }
    int ssum = s;
#pragma unroll
    for (int o = 1; o < 32; o <<= 1) {
        int t = __shfl_up_sync(0xffffffffu, ssum, o);
        if (lane >= o) ssum += t;
    }
    if (lane == 31) wsum[warp] = ssum;
    __syncthreads();
    if (warp == 0) {
        int w = wsum[lane];
#pragma unroll
        for (int o = 1; o < 32; o <<= 1) {
            int t = __shfl_up_sync(0xffffffffu, w, o);
            if (lane >= o) w += t;
        }
        wsum[lane] = w;
    }
    __syncthreads();
    int offset = ssum - s + (warp ? wsum[warp - 1] : 0);
    if (tid == 0) off[0] = 0;
#pragma unroll
    for (int i = 0; i < CH; i++) {
        int idx = base + i;
        if (idx < NN) off[idx + 1] = offset + loc[i];
    }
}

__global__ void fill_b_kernel(const int* __restrict__ src_i, const int* __restrict__ src_j,
                              const int* __restrict__ dst_i, const int* __restrict__ dst_j,
                              const int* __restrict__ off_all, int* __restrict__ cur_all,
                              int* __restrict__ csrc_all) {
    int gi = blockIdx.y;
    int t = gi & 15, g = gi >> 4;
    const int* src = (g == 0 ? src_i : src_j) + (size_t)t * EE;
    const int* dst = (g == 0 ? dst_i : dst_j) + (size_t)t * EE;
    const int* off = off_all + (size_t)gi * (NN + 1);
    int* cur = cur_all + (size_t)gi * NN;
    int* csrc = csrc_all + (size_t)gi * EE;
    int e = blockIdx.x * blockDim.x + threadIdx.x;
    if (e < EE) {
        int d = dst[e];
        int p = atomicAdd(&cur[d], 1);
        csrc[off[d] + p] = src[e];
    }
}

// ---------------------------------------------------------------------------
// Layer-1 build A = [self | mean_agg] for ALL nodes.  grid (NN, NG), block 128.
// ---------------------------------------------------------------------------
__global__ void build_A1_kernel(const float* __restrict__ x_i, const float* __restrict__ x_j,
                                const int* __restrict__ off_all, const int* __restrict__ csrc_all,
                                float* __restrict__ out_all) {
    int gi = blockIdx.y;
    int t = gi & 15, g = gi >> 4;
    const float* feat = (g == 0 ? x_i : x_j) + (size_t)t * NN * DIN;
    const int* off = off_all + (size_t)gi * (NN + 1);
    const int* csrc = csrc_all + (size_t)gi * EE;
    float* out = out_all + (size_t)gi * NP * 256;

    int n = blockIdx.x;
    int f = threadIdx.x;
    float self = feat[(size_t)n * DIN + f];
    int s = off[n], e = off[n + 1];
    float acc = 0.f;
    int i = s;
    for (; i + 4 <= e; i += 4) {
        int a0 = csrc[i], a1 = csrc[i + 1], a2 = csrc[i + 2], a3 = csrc[i + 3];
        float v0 = feat[(size_t)a0 * DIN + f];
        float v1 = feat[(size_t)a1 * DIN + f];
        float v2 = feat[(size_t)a2 * DIN + f];
        float v3 = feat[(size_t)a3 * DIN + f];
        acc += v0 + v1 + v2 + v3;
    }
    for (; i < e; i++) acc += feat[(size_t)csrc[i] * DIN + f];
    int d = e - s; if (d < 1) d = 1;
    size_t ob = (size_t)n * 256;
    out[ob + f]       = self;
    out[ob + 128 + f] = acc / (float)d;
}

// ---------------------------------------------------------------------------
// Layer-2 build A for SELECTED nodes only.  grid (PP, NG), block 256.
// ---------------------------------------------------------------------------
__global__ void build_A2_kernel(const float* __restrict__ h1_all,
                                const int* __restrict__ idx_i, const int* __restrict__ idx_j,
                                const int* __restrict__ off_all, const int* __restrict__ csrc_all,
                                float* __restrict__ out_all) {
    int gi = blockIdx.y;
    int t = gi & 15, g = gi >> 4;
    const float* feat = h1_all + (size_t)gi * NP * 256;
    const int* off = off_all + (size_t)gi * (NN + 1);
    const int* csrc = csrc_all + (size_t)gi * EE;
    const int* idx = ((g == 0) ? idx_i : idx_j) + (size_t)t * PP;
    float* out = out_all + (size_t)gi * PP * 512;

    int p = blockIdx.x;
    int n = idx[p];
    int f = threadIdx.x;
    float self = feat[(size_t)n * 256 + f];
    int s = off[n], e = off[n + 1];
    float acc = 0.f;
    int i = s;
    for (; i + 4 <= e; i += 4) {
        int a0 = csrc[i], a1 = csrc[i + 1], a2 = csrc[i + 2], a3 = csrc[i + 3];
        float v0 = feat[(size_t)a0 * 256 + f];
        float v1 = feat[(size_t)a1 * 256 + f];
        float v2 = feat[(size_t)a2 * 256 + f];
        float v3 = feat[(size_t)a3 * 256 + f];
        acc += v0 + v1 + v2 + v3;
    }
    for (; i < e; i++) acc += feat[(size_t)csrc[i] * 256 + f];
    int d = e - s; if (d < 1) d = 1;
    size_t ob = (size_t)p * 512;
    out[ob + f]       = self;
    out[ob + 256 + f] = acc / (float)d;
}

// ---------------------------------------------------------------------------
// SAGE GEMM (bf16 2-way-split, fp32-quality).  128x128x16 tile, dbl-buffered.
// ---------------------------------------------------------------------------
#define AS_STRIDE 20
#define BS_STRIDE 136

#define MMA_BF16(d, a, b)                                                            \
    asm volatile(                                                                    \
        "mma.sync.aligned.m16n8k16.row.col.f32.bf16.bf16.f32 "                       \
        "{%0,%1,%2,%3},{%4,%5,%6,%7},{%8,%9},{%0,%1,%2,%3};"                         \
        : "+f"(d[0]), "+f"(d[1]), "+f"(d[2]), "+f"(d[3])                             \
        : "r"(a[0]), "r"(a[1]), "r"(a[2]), "r"(a[3]), "r"(b[0]), "r"(b[1]))

#define MMA_F16(d, a, b)                                                             \
    asm volatile(                                                                    \
        "mma.sync.aligned.m16n8k16.row.col.f32.f16.f16.f32 "                         \
        "{%0,%1,%2,%3},{%4,%5,%6,%7},{%8,%9},{%0,%1,%2,%3};"                         \
        : "+f"(d[0]), "+f"(d[1]), "+f"(d[2]), "+f"(d[3])                             \
        : "r"(a[0]), "r"(a[1]), "r"(a[2]), "r"(a[3]), "r"(b[0]), "r"(b[1]))

template <int RELU>
__global__ void __launch_bounds__(256)
sage_gemm_kernel(const float* __restrict__ A, const float* __restrict__ B,
                 const float* __restrict__ bias, float* __restrict__ C,
                 int M, int K, int N) {
    __shared__ __align__(16) float As[2][128][AS_STRIDE];
    __shared__ __align__(16) float Bs[2][16][BS_STRIDE];

    int tid  = threadIdx.x;
    int warp = tid >> 5;
    int lane = tid & 31;
    int gid  = lane >> 2;
    int tq   = lane & 3;
    int wm   = warp >> 2;
    int wn   = warp & 3;

    int bm = blockIdx.y * 128;
    int bn = blockIdx.x * 128;

    float acc[4][4][4];
#pragma unroll
    for (int i = 0; i < 4; i++)
#pragma unroll
        for (int j = 0; j < 4; j++)
#pragma unroll
            for (int r = 0; r < 4; r++) acc[i][j][r] = 0.f;

    int nk = K >> 4;
    const float* Abase = A + (size_t)bm * K;
    const float* Bbase = B + bn;

    auto load_stage = [&](int stage, int k0) {
#pragma unroll
        for (int it = 0; it < 2; it++) {
            int i = tid + it * 256;
            int row = i >> 2, c4 = (i & 3) << 2;
            uint32_t d = (uint32_t)__cvta_generic_to_shared(&As[stage][row][c4]);
            cp16(d, Abase + (size_t)row * K + k0 + c4);
        }
#pragma unroll
        for (int it = 0; it < 2; it++) {
            int i = tid + it * 256;
            int row = i >> 5, c4 = (i & 31) << 2;
            uint32_t d = (uint32_t)__cvta_generic_to_shared(&Bs[stage][row][c4]);
            cp16(d, Bbase + (size_t)(k0 + row) * N + c4);
        }
    };

    load_stage(0, 0);
    asm volatile("cp.async.commit_group;");

    for (int kc = 0; kc < nk; kc++) {
        int cur = kc & 1;
        if (kc + 1 < nk) {
            load_stage(cur ^ 1, (kc + 1) << 4);
            asm volatile("cp.async.commit_group;");
            asm volatile("cp.async.wait_group 1;");
        } else {
            asm volatile("cp.async.wait_group 0;");
        }
        __syncthreads();

        uint32_t ahi[4][4], alo[4][4], bhi[4][2], blo[4][2];
#pragma unroll
        for (int mt = 0; mt < 4; mt++) {
            int m = wm * 64 + mt * 16;
            float2 q0 = *(const float2*)&As[cur][m + gid][tq * 2];
            float2 q1 = *(const float2*)&As[cur][m + gid + 8][tq * 2];
            float2 q2 = *(const float2*)&As[cur][m + gid][tq * 2 + 8];
            float2 q3 = *(const float2*)&As[cur][m + gid + 8][tq * 2 + 8];
            bf16_split_pack(q0.x, q0.y, ahi[mt][0], alo[mt][0]);
            bf16_split_pack(q1.x, q1.y, ahi[mt][1], alo[mt][1]);
            bf16_split_pack(q2.x, q2.y, ahi[mt][2], alo[mt][2]);
            bf16_split_pack(q3.x, q3.y, ahi[mt][3], alo[mt][3]);
        }
#pragma unroll
        for (int nt = 0; nt < 4; nt++) {
            int n = wn * 32 + nt * 8;
            float u0 = Bs[cur][tq * 2][n + gid];
            float u1 = Bs[cur][tq * 2 + 1][n + gid];
            float u2 = Bs[cur][tq * 2 + 8][n + gid];
            float u3 = Bs[cur][tq * 2 + 9][n + gid];
            bf16_split_pack(u0, u1, bhi[nt][0], blo[nt][0]);
            bf16_split_pack(u2, u3, bhi[nt][1], blo[nt][1]);
        }
#pragma unroll
        for (int mt = 0; mt < 4; mt++)
#pragma unroll
            for (int nt = 0; nt < 4; nt++) {
                MMA_BF16(acc[mt][nt], ahi[mt], bhi[nt]);
                MMA_BF16(acc[mt][nt], ahi[mt], blo[nt]);
                MMA_BF16(acc[mt][nt], alo[mt], bhi[nt]);
            }
        __syncthreads();
    }

#pragma unroll
    for (int mt = 0; mt < 4; mt++) {
        int gr = bm + wm * 64 + mt * 16 + gid;
#pragma unroll
        for (int nt = 0; nt < 4; nt++) {
            int gc = bn + wn * 32 + nt * 8 + tq * 2;
            float2 bv = *(const float2*)&bias[gc];
            float v0 = acc[mt][nt][0] + bv.x;
            float v1 = acc[mt][nt][1] + bv.y;
            float v2 = acc[mt][nt][2] + bv.x;
            float v3 = acc[mt][nt][3] + bv.y;
            if (RELU) {
                v0 = fmaxf(v0, 0.f); v1 = fmaxf(v1, 0.f);
                v2 = fmaxf(v2, 0.f); v3 = fmaxf(v3, 0.f);
            }
            *(float2*)&C[(size_t)gr * N + gc]       = make_float2(v0, v1);
            *(float2*)&C[(size_t)(gr + 8) * N + gc] = make_float2(v2, v3);
        }
    }
}

// ---------------------------------------------------------------------------
// fp16 tensor-core GEMM (transformer).  C = A@B^T + bias (+relu).
// A [M,K] fp16 K-major, B [N,K] fp16 K-major (pre-transposed weights).
// 128x128x16 tile, 256 threads, warp tile 64x32, m16n8k16 f16 MMA.
// OHALF: store fp16 u16 output; else fp32.
// ---------------------------------------------------------------------------
#define AH_STRIDE 24   // u16 per smem row (16 data + 8 pad); 12 words -> conflict-free

template <int RELU, int OHALF>
__global__ void __launch_bounds__(256)
fp16_gemm_kernel(const uint16_t* __restrict__ A, const uint16_t* __restrict__ B,
                 const float* __restrict__ bias,
                 float* __restrict__ Cf, uint16_t* __restrict__ Ch,
                 int M, int K, int N) {
    __shared__ __align__(16) uint16_t As[2][128][AH_STRIDE];
    __shared__ __align__(16) uint16_t Bs[2][128][AH_STRIDE];

    int tid  = threadIdx.x;
    int warp = tid >> 5;
    int lane = tid & 31;
    int gid  = lane >> 2;
    int tq   = lane & 3;
    int wm   = warp >> 2;   // 0..1 -> 64-row slice
    int wn   = warp & 3;    // 0..3 -> 32-col slice

    int bm = blockIdx.y * 128;
    int bn = blockIdx.x * 128;

    float acc[4][4][4];
#pragma unroll
    for (int i = 0; i < 4; i++)
#pragma unroll
        for (int j = 0; j < 4; j++)
#pragma unroll
            for (int r = 0; r < 4; r++) acc[i][j][r] = 0.f;

    int nk = K >> 4;
    const uint16_t* Abase = A + (size_t)bm * K;
    const uint16_t* Bbase = B + (size_t)bn * K;

    auto load_stage = [&](int stage, int k0) {
        // A: 128 rows x 32B = 256 cp16; B same.  One of each per thread.
        int row = tid >> 1, c = tid & 1;
        uint32_t da = (uint32_t)__cvta_generic_to_shared(&As[stage][row][c * 8]);
        cp16(da, Abase + (size_t)row * K + k0 + c * 8);
        uint32_t db = (uint32_t)__cvta_generic_to_shared(&Bs[stage][row][c * 8]);
        cp16(db, Bbase + (size_t)row * K + k0 + c * 8);
    };

    load_stage(0, 0);
    asm volatile("cp.async.commit_group;");

    for (int kc = 0; kc < nk; kc++) {
        int cur = kc & 1;
        if (kc + 1 < nk) {
            load_stage(cur ^ 1, (kc + 1) << 4);
            asm volatile("cp.async.commit_group;");
            asm volatile("cp.async.wait_group 1;");
        } else {
            asm volatile("cp.async.wait_group 0;");
        }
        __syncthreads();

        uint32_t af[4][4], bf[4][2];
#pragma unroll
        for (int mt = 0; mt < 4; mt++) {
            int m = wm * 64 + mt * 16;
            af[mt][0] = *(const uint32_t*)&As[cur][m + gid][tq * 2];
            af[mt][1] = *(const uint32_t*)&As[cur][m + gid + 8][tq * 2];
            af[mt][2] = *(const uint32_t*)&As[cur][m + gid][tq * 2 + 8];
            af[mt][3] = *(const uint32_t*)&As[cur][m + gid + 8][tq * 2 + 8];
        }
#pragma unroll
        for (int nt = 0; nt < 4; nt++) {
            int n = wn * 32 + nt * 8;
            bf[nt][0] = *(const uint32_t*)&Bs[cur][n + gid][tq * 2];
            bf[nt][1] = *(const uint32_t*)&Bs[cur][n + gid][tq * 2 + 8];
        }
#pragma unroll
        for (int mt = 0; mt < 4; mt++)
#pragma unroll
            for (int nt = 0; nt < 4; nt++)
                MMA_F16(acc[mt][nt], af[mt], bf[nt]);
        __syncthreads();
    }

#pragma unroll
    for (int mt = 0; mt < 4; mt++) {
        int gr = bm + wm * 64 + mt * 16 + gid;
#pragma unroll
        for (int nt = 0; nt < 4; nt++) {
            int gc = bn + wn * 32 + nt * 8 + tq * 2;
            float2 bv = *(const float2*)&bias[gc];
            float v0 = acc[mt][nt][0] + bv.x;
            float v1 = acc[mt][nt][1] + bv.y;
            float v2 = acc[mt][nt][2] + bv.x;
            float v3 = acc[mt][nt][3] + bv.y;
            if (RELU) {
                v0 = fmaxf(v0, 0.f); v1 = fmaxf(v1, 0.f);
                v2 = fmaxf(v2, 0.f); v3 = fmaxf(v3, 0.f);
            }
            if (OHALF) {
                *(uint32_t*)&Ch[(size_t)gr * N + gc]       = f2h2(v0, v1);
                *(uint32_t*)&Ch[(size_t)(gr + 8) * N + gc] = f2h2(v2, v3);
            } else {
                *(float2*)&Cf[(size_t)gr * N + gc]       = make_float2(v0, v1);
                *(float2*)&Cf[(size_t)(gr + 8) * N + gc] = make_float2(v2, v3);
            }
        }
    }
}

// ---------------------------------------------------------------------------
// Gather (compact rows) + L2-normalize.  grid (PP, NG), block 256.
// Writes att_out (fp32), h (fp32), h_h (fp16).
// ---------------------------------------------------------------------------
__global__ void gather_norm2_kernel(const float* __restrict__ h2c,
                                    float* __restrict__ att_out, float* __restrict__ h,
                                    uint16_t* __restrict__ h_h) {
    int gi = blockIdx.y;
    int t = gi & 15, g = gi >> 4;
    int p = blockIdx.x;
    int f = threadIdx.x;
    float v = h2c[((size_t)gi * PP + p) * 256 + f];
    float s = v * v;
    __shared__ float red[8];
    for (int o = 16; o; o >>= 1) s += __shfl_xor_sync(0xffffffffu, s, o);
    if ((f & 31) == 0) red[f >> 5] = s;
    __syncthreads();
    float tot = red[0] + red[1] + red[2] + red[3] + red[4] + red[5] + red[6] + red[7];
    float norm = fmaxf(sqrtf(tot), 1e-12f);
    v /= norm;
    size_t o = ((size_t)(t * PP + p)) * DM + g * 256 + f;
    att_out[o] = v;
    h[o]       = v;
    h_h[o]     = f2h(v);
}

// ---------------------------------------------------------------------------
// Banded attention: window 4, T=16.  One block per (p, head), 128 threads.
// fp16 qkv input, fp16 output.
// ---------------------------------------------------------------------------
__global__ void attn_kernel(const uint16_t* __restrict__ qkv_h, uint16_t* __restrict__ out_h) {
    int ph = blockIdx.x;
    int p = ph >> 3;
    int h = ph & 7;
    __shared__ float qs[16][64], ks[16][64], vs[16][64];
    int tid = threadIdx.x;
    // 16 rows x 64 floats = 512 half2 per array; 4 per thread per array
    for (int i = tid; i < 512; i += 128) {
        int t = i >> 5, d2 = (i & 31) << 1;
        const __half2* b = (const __half2*)(qkv_h + ((size_t)(t * PP + p)) * 1536 + h * 64 + d2);
        float2 fq = __half22float2(b[0]);
        float2 fk = __half22float2(b[256]);   // +512 u16
        float2 fv = __half22float2(b[512]);   // +1024 u16
        qs[t][d2] = fq.x; qs[t][d2 + 1] = fq.y;
        ks[t][d2] = fk.x; ks[t][d2 + 1] = fk.y;
        vs[t][d2] = fv.x; vs[t][d2 + 1] = fv.y;
    }
    __syncthreads();
    int warp = tid >> 5, lane = tid & 31;
    for (int t = warp; t < 16; t += 4) {
        int s0 = t - 3; if (s0 < 0) s0 = 0;
        int ns = t - s0 + 1;
        float sc[4];
        float mx = -1e30f;
        for (int si = 0; si < ns; si++) {
            int s = s0 + si;
            float d0 = qs[t][lane] * ks[s][lane] + qs[t][lane + 32] * ks[s][lane + 32];
            for (int o = 16; o; o >>= 1) d0 += __shfl_xor_sync(0xffffffffu, d0, o);
            d0 *= 0.125f;
            sc[si] = d0;
            mx = fmaxf(mx, d0);
        }
        float sum = 0.f;
        for (int si = 0; si < ns; si++) { sc[si] = expf(sc[si] - mx); sum += sc[si]; }
        float inv = 1.f / sum;
        float o0 = 0.f, o1 = 0.f;
        for (int si = 0; si < ns; si++) {
            int s = s0 + si;
            o0 += sc[si] * vs[s][lane];
            o1 += sc[si] * vs[s][lane + 32];
        }
        size_t ob = ((size_t)(t * PP + p)) * DM + h * 64;
        out_h[ob + lane]      = f2h(o0 * inv);
        out_h[ob + lane + 32] = f2h(o1 * inv);
    }
}

// ---------------------------------------------------------------------------
// h = LayerNorm(h + delta) * g + b; emits fp16 copy h_h.
// ---------------------------------------------------------------------------
__global__ void resid_ln_kernel(float* __restrict__ h, const float* __restrict__ delta,
                                const float* __restrict__ g, const float* __restrict__ b,
                                uint16_t* __restrict__ h_h) {
    int row = blockIdx.x;
    int tid = threadIdx.x;
    size_t base = (size_t)row * DM;
    float v[4];
    float s = 0.f;
#pragma unroll
    for (int i = 0; i < 4; i++) {
        int c = tid + i * 128;
        float x = h[base + c] + delta[base + c];
        v[i] = x; s += x;
    }
    __shared__ float red[4];
    for (int o = 16; o; o >>= 1) s += __shfl_xor_sync(0xffffffffu, s, o);
    if ((tid & 31) == 0) red[tid >> 5] = s;
    __syncthreads();
    float mean = (red[0] + red[1] + red[2] + red[3]) * (1.f / 512.f);
    __syncthreads();
    float s2 = 0.f;
#pragma unroll
    for (int i = 0; i < 4; i++) { float d = v[i] - mean; s2 += d * d; }
    for (int o = 16; o; o >>= 1) s2 += __shfl_xor_sync(0xffffffffu, s2, o);
    if ((tid & 31) == 0) red[tid >> 5] = s2;
    __syncthreads();
    float var = (red[0] + red[1] + red[2] + red[3]) * (1.f / 512.f);
    float rstd = rsqrtf(var + 1e-5f);
#pragma unroll
    for (int i = 0; i < 4; i++) {
        int c = tid + i * 128;
        float o = (v[i] - mean) * rstd * g[c] + b[c];
        h[base + c]   = o;
        h_h[base + c] = f2h(o);
    }
}

// ---------------------------------------------------------------------------
// FINAL layer: LayerNorm(h + delta)*g + b, then dot with Wout -> scal_out.
// ---------------------------------------------------------------------------
__global__ void resid_ln_out_kernel(const float* __restrict__ h, const float* __restrict__ delta,
                                    const float* __restrict__ g, const float* __restrict__ b,
                                    const float* __restrict__ Wout, float* __restrict__ out) {
    int row = blockIdx.x;
    int tid = threadIdx.x;
    size_t base = (size_t)row * DM;
    float v[4];
    float s = 0.f;
#pragma unroll
    for (int i = 0; i < 4; i++) {
        int c = tid + i * 128;
        float x = h[base + c] + delta[base + c];
        v[i] = x; s += x;
    }
    __shared__ float red[4];
    for (int o = 16; o; o >>= 1) s += __shfl_xor_sync(0xffffffffu, s, o);
    if ((tid & 31) == 0) red[tid >> 5] = s;
    __syncthreads();
    float mean = (red[0] + red[1] + red[2] + red[3]) * (1.f / 512.f);
    __syncthreads();
    float s2 = 0.f;
#pragma unroll
    for (int i = 0; i < 4; i++) { float d = v[i] - mean; s2 += d * d; }
    for (int o = 16; o; o >>= 1) s2 += __shfl_xor_sync(0xffffffffu, s2, o);
    if ((tid & 31) == 0) red[tid >> 5] = s2;
    __syncthreads();
    float var = (red[0] + red[1] + red[2] + red[3]) * (1.f / 512.f);
    float rstd = rsqrtf(var + 1e-5f);
    float dot = 0.f;
#pragma unroll
    for (int i = 0; i < 4; i++) {
        int c = tid + i * 128;
        float o = (v[i] - mean) * rstd * g[c] + b[c];
        dot += o * Wout[c];
    }
    __syncthreads();
    for (int o = 16; o; o >>= 1) dot += __shfl_xor_sync(0xffffffffu, dot, o);
    if ((tid & 31) == 0) red[tid >> 5] = dot;
    __syncthreads();
    if (tid == 0) out[row] = red[0] + red[1] + red[2] + red[3];
}

// ---------------------------------------------------------------------------
// Weight prep
// ---------------------------------------------------------------------------
__global__ void prep_wc_kernel(const float* __restrict__ W1s, const float* __restrict__ W1n,
                               const float* __restrict__ W2s, const float* __restrict__ W2n,
                               float* __restrict__ wc1, float* __restrict__ wc2) {
    int i = blockIdx.x * blockDim.x + threadIdx.x;
    if (i < 256 * 256) {
        int k = i >> 8, c = i & 255;
        wc1[i] = (k < 128) ? W1s[k * 256 + c] : W1n[(k - 128) * 256 + c];
    }
    if (i < 512 * 256) {
        int k = i >> 8, c = i & 255;
        wc2[i] = (k < 256) ? W2s[k * 256 + c] : W2n[(k - 256) * 256 + c];
    }
}

// QKV concat + transpose + fp16: Wq/Wk/Wv [L][512][512] -> T [L][1536][512] fp16
__global__ void prep_wqkvT_kernel(const float* __restrict__ Wq, const float* __restrict__ Wk,
                                  const float* __restrict__ Wv,
                                  const float* __restrict__ bq, const float* __restrict__ bk,
                                  const float* __restrict__ bv,
                                  uint16_t* __restrict__ Th, float* __restrict__ bqkv) {
    long i = (long)blockIdx.x * blockDim.x + threadIdx.x;
    const long tot = 2L * 1536 * 512;
    if (i < tot) {
        int l = (int)(i / (1536L * 512));
        long rem = i % (1536L * 512);
        int n = (int)(rem / 512), k = (int)(rem % 512);
        const float* W = (n < 512) ? Wq : (n < 1024) ? Wk : Wv;
        int nn = n & 511;
        Th[i] = f2h(W[(size_t)l * 512 * 512 + (size_t)k * 512 + nn]);
    }
    if (i < 2 * 1536) {
        int l = (int)(i / 1536), c = (int)(i % 1536);
        float v;
        if (c < 512)       v = bq[l * 512 + c];
        else if (c < 1024) v = bk[l * 512 + c - 512];
        else               v = bv[l * 512 + c - 1024];
        bqkv[i] = v;
    }
}

// transpose + fp16: W [L][K][N] -> T [L][N][K]
__global__ void prep_wT_kernel(const float* __restrict__ W, uint16_t* __restrict__ Th,
                               int K, int N, int L) {
    long i = (long)blockIdx.x * blockDim.x + threadIdx.x;
    long tot = (long)L * K * N;
    if (i >= tot) return;
    long per = (long)K * N;
    int l = (int)(i / per);
    long rem = i % per;
    int n = (int)(rem / K), k = (int)(rem % K);
    Th[i] = f2h(W[(size_t)l * per + (size_t)k * N + n]);
}

// ---------------------------------------------------------------------------
// Host driver
// ---------------------------------------------------------------------------
extern "C" void kernel_launch(void* const* d_in, const int* in_sizes, int n_in,
                              void* d_out, int out_size) {
    const float* x_i   = (const float*)d_in[0];
    const float* x_j   = (const float*)d_in[1];
    const int*   src_i = (const int*)d_in[2];
    const int*   dst_i = (const int*)d_in[3];
    const int*   src_j = (const int*)d_in[4];
    const int*   dst_j = (const int*)d_in[5];
    const int*   idx_i = (const int*)d_in[6];
    const int*   idx_j = (const int*)d_in[7];
    const float* W1s = (const float*)d_in[8];
    const float* W1n = (const float*)d_in[9];
    const float* b1  = (const float*)d_in[10];
    const float* W2s = (const float*)d_in[11];
    const float* W2n = (const float*)d_in[12];
    const float* b2  = (const float*)d_in[13];
    const float* Wq  = (const float*)d_in[14];
    const float* Wk  = (const float*)d_in[15];
    const float* Wv  = (const float*)d_in[16];
    const float* bq  = (const float*)d_in[17];
    const float* bk  = (const float*)d_in[18];
    const float* bv  = (const float*)d_in[19];
    const float* Wo  = (const float*)d_in[20];
    const float* bo  = (const float*)d_in[21];
    const float* Wf1 = (const float*)d_in[22];
    const float* bf1 = (const float*)d_in[23];
    const float* Wf2 = (const float*)d_in[24];
    const float* bf2 = (const float*)d_in[25];
    const float* g1  = (const float*)d_in[26];
    const float* bg1 = (const float*)d_in[27];
    const float* g2  = (const float*)d_in[28];
    const float* bg2 = (const float*)d_in[29];
    const float* Wout= (const float*)d_in[30];

    void* p;
    cudaGetSymbolAddress(&p, g_sage);  float*    SB = (float*)p;
    cudaGetSymbolAddress(&p, g_w);     float*    WB = (float*)p;
    cudaGetSymbolAddress(&p, g_act);   float*    AB = (float*)p;
    cudaGetSymbolAddress(&p, g_h16);   uint16_t* HB = (uint16_t*)p;
    cudaGetSymbolAddress(&p, g_iblob); int*      IB = (int*)p;

    float* h1   = SB + S_H1;
    float* bufA = SB + S_BUFA;
    float* bufB = SB + S_BUFB;
    float* h2   = SB + S_H2;

    float* wc1  = WB + W_WC1;
    float* wc2  = WB + W_WC2;
    float* bqkv = WB + W_BQKV;

    float* hbuf  = AB + A_H;
    float* delta = AB + A_DELTA;

    uint16_t* h_h    = HB + H_HH;
    uint16_t* qkv_h  = HB + H_QKV;
    uint16_t* tmp_h  = HB + H_TMP;
    uint16_t* ffb_h  = HB + H_FFB;
    uint16_t* wqkv_h = HB + H_WQKV;
    uint16_t* wo_h   = HB + H_WO;
    uint16_t* wf1_h  = HB + H_WF1;
    uint16_t* wf2_h  = HB + H_WF2;

    int* deg  = IB + I_DEG;
    int* cur  = IB + I_CUR;
    int* off  = IB + I_OFF;
    int* csrc = IB + I_CSR;

    float* att_out  = (float*)d_out;
    float* scal_out = att_out + (size_t)NTOK * DM;

    // ---- weight prep ----
    prep_wc_kernel<<<(512 * 256 + 255) / 256, 256>>>(W1s, W1n, W2s, W2n, wc1, wc2);
    prep_wqkvT_kernel<<<(2 * 1536 * 512 + 255) / 256, 256>>>(
        Wq, Wk, Wv, bq, bk, bv, wqkv_h, bqkv);
    prep_wT_kernel<<<(2 * 512 * 512 + 255) / 256, 256>>>(Wo, wo_h, 512, 512, 2);
    prep_wT_kernel<<<(2 * 512 * 2048 + 255) / 256, 256>>>(Wf1, wf1_h, 512, 2048, 2);
    prep_wT_kernel<<<(2 * 2048 * 512 + 255) / 256, 256>>>(Wf2, wf2_h, 2048, 512, 2);

    // ---- batched CSR for all NG graphs ----
    cudaMemsetAsync(IB, 0, (size_t)2 * NG * NN * sizeof(int));   // deg + cur
    hist_b_kernel<<<dim3((EE + 255) / 256, NG), 256>>>(dst_i, dst_j, deg);
    scan_b_kernel<<<NG, 1024>>>(deg, off);
    fill_b_kernel<<<dim3((EE + 255) / 256, NG), 256>>>(src_i, src_j, dst_i, dst_j, off, cur, csrc);

    // ---- GraphSAGE, single batched pass; layer 2 only for selected nodes ----
    build_A1_kernel<<<dim3(NN, NG), 128>>>(x_i, x_j, off, csrc, bufA);
    sage_gemm_kernel<1><<<dim3(2, HB1 / 128), 256>>>(bufA, wc1, b1, h1, HB1, 256, 256);
    build_A2_kernel<<<dim3(PP, NG), 256>>>(h1, idx_i, idx_j, off, csrc, bufB);
    sage_gemm_kernel<0><<<dim3(2, HB2 / 128), 256>>>(bufB, wc2, b2, h2, HB2, 512, 256);
    gather_norm2_kernel<<<dim3(PP, NG), 256>>>(h2, att_out, hbuf, h_h);

    // ---- Transformer (fp16 tensor-core GEMMs, fp32 accumulate) ----
    for (int l = 0; l < NLAY; l++) {
        fp16_gemm_kernel<0, 1><<<dim3(12, NTOK / 128), 256>>>(
            h_h, wqkv_h + (size_t)l * 1536 * 512, bqkv + l * 1536,
            nullptr, qkv_h, NTOK, 512, 1536);
        attn_kernel<<<PP * NHEAD, 128>>>(qkv_h, tmp_h);
        fp16_gemm_kernel<0, 0><<<dim3(4, NTOK / 128), 256>>>(
            tmp_h, wo_h + (size_t)l * 512 * 512, bo + l * 512,
            delta, nullptr, NTOK, 512, 512);
        resid_ln_kernel<<<NTOK, 128>>>(hbuf, delta, g1 + l * 512, bg1 + l * 512, h_h);
        fp16_gemm_kernel<1, 1><<<dim3(16, NTOK / 128), 256>>>(
            h_h, wf1_h + (size_t)l * 2048 * 512, bf1 + l * 2048,
            nullptr, ffb_h, NTOK, 512, 2048);
        fp16_gemm_kernel<0, 0><<<dim3(4, NTOK / 128), 256>>>(
            ffb_h, wf2_h + (size_t)l * 512 * 2048, bf2 + l * 512,
            delta, nullptr, NTOK, 2048, 512);
        if (l < NLAY - 1) {
            resid_ln_kernel<<<NTOK, 128>>>(hbuf, delta, g2 + l * 512, bg2 + l * 512, h_h);
        } else {
            resid_ln_out_kernel<<<NTOK, 128>>>(hbuf, delta, g2 + l * 512, bg2 + l * 512,
                                               Wout, scal_out);
        }
    }
}

// round 16
// speedup vs baseline: 1.7421x; 1.0809x over previous
#include <cuda_runtime.h>
#include <cuda_fp16.h>
#include <cstdint>

// ---------------------------------------------------------------------------
// Problem constants
// ---------------------------------------------------------------------------
#define TT     16
#define NN     20000
#define NP     20096            // NN padded to multiple of 128
#define NG     32               // 32 (t, graph) instances, gi = g*16 + t
#define EE     320000
#define PP     4096
#define DIN    128
#define NHEAD  8
#define NLAY   2
#define DM     512
#define NTOK   (TT * PP)     // 65536
#define HB1    (NG * NP)     // 643072 rows (layer-1 GEMM)
#define HB2    (NG * PP)     // 131072 rows (layer-2 GEMM, selected only)

// ---------------------------------------------------------------------------
// Scratch blobs (total .bss ~2.5 GB < 4GB aarch64 ADRP limit)
// ---------------------------------------------------------------------------
constexpr size_t S_H1   = 0;                             // [HB1, 256]
constexpr size_t S_BUFA = (size_t)HB1 * 256;             // [HB1, 256]
constexpr size_t S_BUFB = S_BUFA;                        // [HB2, 512] alias
constexpr size_t S_H2   = S_BUFA + (size_t)HB2 * 512;    // [HB2, 256] alias (disjoint)
constexpr size_t S_TOTAL= (size_t)HB1 * 512;             // ~1.32 GB
__device__ float g_sage[S_TOTAL];

// fp32 weights (SAGE stacked) + transformer biases
constexpr size_t W_WC1   = 0;                          // [256,256]
constexpr size_t W_WC2   = W_WC1  + 256ull * 256;      // [512,256]
constexpr size_t W_BQKV  = W_WC2  + 512ull * 256;      // [2,1536]
constexpr size_t W_TOTAL = W_BQKV + 2ull * 1536;
__device__ float g_w[W_TOTAL];

// fp32 activations (~0.27 GB)
constexpr size_t A_H    = 0;                           // [NTOK,512]  hidden
constexpr size_t A_DELTA= A_H   + (size_t)NTOK * 512;  // [NTOK,512]  GEMM fp32 out
constexpr size_t A_TOTAL= A_DELTA + (size_t)NTOK * 512;
__device__ float g_act[A_TOTAL];

// fp16 operand arrays (u16 raw bits, ~0.62 GB)
constexpr size_t H_HH   = 0;                              // [NTOK,512]  hidden fp16
constexpr size_t H_QKV  = H_HH  + (size_t)NTOK * 512;     // [NTOK,1536]
constexpr size_t H_TMP  = H_QKV + (size_t)NTOK * 1536;    // [NTOK,512]  attn out
constexpr size_t H_FFB  = H_TMP + (size_t)NTOK * 512;     // [NTOK,2048]
constexpr size_t H_WQKV = H_FFB + (size_t)NTOK * 2048;    // [2,1536,512] (transposed)
constexpr size_t H_WO   = H_WQKV + 2ull * 1536 * 512;     // [2,512,512]
constexpr size_t H_WF1  = H_WO   + 2ull * 512 * 512;      // [2,2048,512]
constexpr size_t H_WF2  = H_WF1  + 2ull * 2048 * 512;     // [2,512,2048]
constexpr size_t H_TOTAL= H_WF2  + 2ull * 512 * 2048;
__device__ uint16_t g_h16[H_TOTAL];

// CSR int region (~49 MB)
constexpr size_t I_DEG = 0;
constexpr size_t I_CUR = I_DEG + (size_t)NG * NN;
constexpr size_t I_OFF = I_CUR + (size_t)NG * NN;
constexpr size_t I_CSR = I_OFF + (size_t)NG * (NN + 1);
constexpr size_t I_TOTAL = I_CSR + (size_t)NG * EE;
__device__ int g_iblob[I_TOTAL];

// ---------------------------------------------------------------------------
// numeric helpers
// ---------------------------------------------------------------------------
__device__ __forceinline__ void bf16_split_pack(float v0, float v1,
                                                uint32_t& hi, uint32_t& lo) {
    uint32_t h;
    asm("cvt.rn.bf16x2.f32 %0, %1, %2;" : "=r"(h) : "f"(v1), "f"(v0));
    float h0 = __uint_as_float(h << 16);
    float h1 = __uint_as_float(h & 0xFFFF0000u);
    hi = h;
    asm("cvt.rn.bf16x2.f32 %0, %1, %2;" : "=r"(lo) : "f"(v1 - h1), "f"(v0 - h0));
}

__device__ __forceinline__ uint16_t f2h(float v) {
    uint16_t r;
    asm("cvt.rn.f16.f32 %0, %1;" : "=h"(r) : "f"(v));
    return r;
}

__device__ __forceinline__ uint32_t f2h2(float v0, float v1) {   // low = v0
    uint32_t r;
    asm("cvt.rn.f16x2.f32 %0, %1, %2;" : "=r"(r) : "f"(v1), "f"(v0));
    return r;
}

__device__ __forceinline__ void cp16(uint32_t daddr, const void* src) {
    asm volatile("cp.async.cg.shared.global [%0], [%1], 16;" :: "r"(daddr), "l"(src));
}

// ---------------------------------------------------------------------------
// Batched CSR construction
// ---------------------------------------------------------------------------
__global__ void hist_b_kernel(const int* __restrict__ dst_i, const int* __restrict__ dst_j,
                              int* __restrict__ deg) {
    int gi = blockIdx.y;
    int t = gi & 15, g = gi >> 4;
    const int* dst = (g == 0 ? dst_i : dst_j) + (size_t)t * EE;
    int* d = deg + (size_t)gi * NN;
    int e = blockIdx.x * blockDim.x + threadIdx.x;
    if (e < EE) atomicAdd(&d[dst[e]], 1);
}

__global__ void __launch_bounds__(1024)
scan_b_kernel(const int* __restrict__ deg_all, int* __restrict__ off_all) {
    __shared__ int wsum[32];
    const int CH = 20;
    int gi = blockIdx.x;
    const int* deg = deg_all + (size_t)gi * NN;
    int* off = off_all + (size_t)gi * (NN + 1);
    int tid = threadIdx.x;
    int lane = tid & 31, warp = tid >> 5;
    int base = tid * CH;
    int loc[CH];
    int s = 0;
#pragma unroll
    for (int i = 0; i < CH; i++) {
        int idx = base + i;
        int v = (idx < NN) ? deg[idx] : 0;
        s += v;
        loc[i] = s;
    }
    int ssum = s;
#pragma unroll
    for (int o = 1; o < 32; o <<= 1) {
        int t = __shfl_up_sync(0xffffffffu, ssum, o);
        if (lane >= o) ssum += t;
    }
    if (lane == 31) wsum[warp] = ssum;
    __syncthreads();
    if (warp == 0) {
        int w = wsum[lane];
#pragma unroll
        for (int o = 1; o < 32; o <<= 1) {
            int t = __shfl_up_sync(0xffffffffu, w, o);
            if (lane >= o) w += t;
        }
        wsum[lane] = w;
    }
    __syncthreads();
    int offset = ssum - s + (warp ? wsum[warp - 1] : 0);
    if (tid == 0) off[0] = 0;
#pragma unroll
    for (int i = 0; i < CH; i++) {
        int idx = base + i;
        if (idx < NN) off[idx + 1] = offset + loc[i];
    }
}

__global__ void fill_b_kernel(const int* __restrict__ src_i, const int* __restrict__ src_j,
                              const int* __restrict__ dst_i, const int* __restrict__ dst_j,
                              const int* __restrict__ off_all, int* __restrict__ cur_all,
                              int* __restrict__ csrc_all) {
    int gi = blockIdx.y;
    int t = gi & 15, g = gi >> 4;
    const int* src = (g == 0 ? src_i : src_j) + (size_t)t * EE;
    const int* dst = (g == 0 ? dst_i : dst_j) + (size_t)t * EE;
    const int* off = off_all + (size_t)gi * (NN + 1);
    int* cur = cur_all + (size_t)gi * NN;
    int* csrc = csrc_all + (size_t)gi * EE;
    int e = blockIdx.x * blockDim.x + threadIdx.x;
    if (e < EE) {
        int d = dst[e];
        int p = atomicAdd(&cur[d], 1);
        csrc[off[d] + p] = src[e];
    }
}

// ---------------------------------------------------------------------------
// Layer-1 build A = [self | mean_agg], float4 per lane, warp per node.
// grid (NN/4, NG), block 128 (4 warps = 4 nodes).
// ---------------------------------------------------------------------------
__global__ void build_A1_kernel(const float* __restrict__ x_i, const float* __restrict__ x_j,
                                const int* __restrict__ off_all, const int* __restrict__ csrc_all,
                                float* __restrict__ out_all) {
    int gi = blockIdx.y;
    int t = gi & 15, g = gi >> 4;
    const float* feat = (g == 0 ? x_i : x_j) + (size_t)t * NN * DIN;
    const int* off = off_all + (size_t)gi * (NN + 1);
    const int* csrc = csrc_all + (size_t)gi * EE;
    float* out = out_all + (size_t)gi * NP * 256;

    int warp = threadIdx.x >> 5, lane = threadIdx.x & 31;
    int n = blockIdx.x * 4 + warp;
    int c4 = lane * 4;
    float4 self = *(const float4*)(feat + (size_t)n * DIN + c4);
    int s = off[n], e = off[n + 1];
    float4 acc = make_float4(0.f, 0.f, 0.f, 0.f);
    int i = s;
    for (; i + 4 <= e; i += 4) {
        int a0 = csrc[i], a1 = csrc[i + 1], a2 = csrc[i + 2], a3 = csrc[i + 3];
        float4 v0 = *(const float4*)(feat + (size_t)a0 * DIN + c4);
        float4 v1 = *(const float4*)(feat + (size_t)a1 * DIN + c4);
        float4 v2 = *(const float4*)(feat + (size_t)a2 * DIN + c4);
        float4 v3 = *(const float4*)(feat + (size_t)a3 * DIN + c4);
        acc.x += v0.x + v1.x + v2.x + v3.x;
        acc.y += v0.y + v1.y + v2.y + v3.y;
        acc.z += v0.z + v1.z + v2.z + v3.z;
        acc.w += v0.w + v1.w + v2.w + v3.w;
    }
    for (; i < e; i++) {
        float4 v = *(const float4*)(feat + (size_t)csrc[i] * DIN + c4);
        acc.x += v.x; acc.y += v.y; acc.z += v.z; acc.w += v.w;
    }
    int d = e - s; if (d < 1) d = 1;
    float fd = (float)d;
    float4 m = make_float4(acc.x / fd, acc.y / fd, acc.z / fd, acc.w / fd);
    *(float4*)(out + (size_t)n * 256 + c4)       = self;
    *(float4*)(out + (size_t)n * 256 + 128 + c4) = m;
}

// ---------------------------------------------------------------------------
// Layer-2 build A for SELECTED nodes, float4 per lane, 64 threads per node.
// grid (PP/2, NG), block 128 (2 nodes).
// ---------------------------------------------------------------------------
__global__ void build_A2_kernel(const float* __restrict__ h1_all,
                                const int* __restrict__ idx_i, const int* __restrict__ idx_j,
                                const int* __restrict__ off_all, const int* __restrict__ csrc_all,
                                float* __restrict__ out_all) {
    int gi = blockIdx.y;
    int t = gi & 15, g = gi >> 4;
    const float* feat = h1_all + (size_t)gi * NP * 256;
    const int* off = off_all + (size_t)gi * (NN + 1);
    const int* csrc = csrc_all + (size_t)gi * EE;
    const int* idx = ((g == 0) ? idx_i : idx_j) + (size_t)t * PP;
    float* out = out_all + (size_t)gi * PP * 512;

    int half = threadIdx.x >> 6;          // 0/1 -> node within block
    int st   = threadIdx.x & 63;
    int p = blockIdx.x * 2 + half;
    int n = idx[p];
    int c4 = st * 4;                      // 0..252
    float4 self = *(const float4*)(feat + (size_t)n * 256 + c4);
    int s = off[n], e = off[n + 1];
    float4 acc = make_float4(0.f, 0.f, 0.f, 0.f);
    int i = s;
    for (; i + 4 <= e; i += 4) {
        int a0 = csrc[i], a1 = csrc[i + 1], a2 = csrc[i + 2], a3 = csrc[i + 3];
        float4 v0 = *(const float4*)(feat + (size_t)a0 * 256 + c4);
        float4 v1 = *(const float4*)(feat + (size_t)a1 * 256 + c4);
        float4 v2 = *(const float4*)(feat + (size_t)a2 * 256 + c4);
        float4 v3 = *(const float4*)(feat + (size_t)a3 * 256 + c4);
        acc.x += v0.x + v1.x + v2.x + v3.x;
        acc.y += v0.y + v1.y + v2.y + v3.y;
        acc.z += v0.z + v1.z + v2.z + v3.z;
        acc.w += v0.w + v1.w + v2.w + v3.w;
    }
    for (; i < e; i++) {
        float4 v = *(const float4*)(feat + (size_t)csrc[i] * 256 + c4);
        acc.x += v.x; acc.y += v.y; acc.z += v.z; acc.w += v.w;
    }
    int d = e - s; if (d < 1) d = 1;
    float fd = (float)d;
    float4 m = make_float4(acc.x / fd, acc.y / fd, acc.z / fd, acc.w / fd);
    *(float4*)(out + (size_t)p * 512 + c4)       = self;
    *(float4*)(out + (size_t)p * 512 + 256 + c4) = m;
}

// ---------------------------------------------------------------------------
// SAGE GEMM (bf16 2-way-split, fp32-quality).  128x128x16 tile, dbl-buffered.
// ---------------------------------------------------------------------------
#define AS_STRIDE 20
#define BS_STRIDE 136

#define MMA_BF16(d, a, b)                                                            \
    asm volatile(                                                                    \
        "mma.sync.aligned.m16n8k16.row.col.f32.bf16.bf16.f32 "                       \
        "{%0,%1,%2,%3},{%4,%5,%6,%7},{%8,%9},{%0,%1,%2,%3};"                         \
        : "+f"(d[0]), "+f"(d[1]), "+f"(d[2]), "+f"(d[3])                             \
        : "r"(a[0]), "r"(a[1]), "r"(a[2]), "r"(a[3]), "r"(b[0]), "r"(b[1]))

#define MMA_F16(d, a, b)                                                             \
    asm volatile(                                                                    \
        "mma.sync.aligned.m16n8k16.row.col.f32.f16.f16.f32 "                         \
        "{%0,%1,%2,%3},{%4,%5,%6,%7},{%8,%9},{%0,%1,%2,%3};"                         \
        : "+f"(d[0]), "+f"(d[1]), "+f"(d[2]), "+f"(d[3])                             \
        : "r"(a[0]), "r"(a[1]), "r"(a[2]), "r"(a[3]), "r"(b[0]), "r"(b[1]))

template <int RELU>
__global__ void __launch_bounds__(256)
sage_gemm_kernel(const float* __restrict__ A, const float* __restrict__ B,
                 const float* __restrict__ bias, float* __restrict__ C,
                 int M, int K, int N) {
    __shared__ __align__(16) float As[2][128][AS_STRIDE];
    __shared__ __align__(16) float Bs[2][16][BS_STRIDE];

    int tid  = threadIdx.x;
    int warp = tid >> 5;
    int lane = tid & 31;
    int gid  = lane >> 2;
    int tq   = lane & 3;
    int wm   = warp >> 2;
    int wn   = warp & 3;

    int bm = blockIdx.y * 128;
    int bn = blockIdx.x * 128;

    float acc[4][4][4];
#pragma unroll
    for (int i = 0; i < 4; i++)
#pragma unroll
        for (int j = 0; j < 4; j++)
#pragma unroll
            for (int r = 0; r < 4; r++) acc[i][j][r] = 0.f;

    int nk = K >> 4;
    const float* Abase = A + (size_t)bm * K;
    const float* Bbase = B + bn;

    auto load_stage = [&](int stage, int k0) {
#pragma unroll
        for (int it = 0; it < 2; it++) {
            int i = tid + it * 256;
            int row = i >> 2, c4 = (i & 3) << 2;
            uint32_t d = (uint32_t)__cvta_generic_to_shared(&As[stage][row][c4]);
            cp16(d, Abase + (size_t)row * K + k0 + c4);
        }
#pragma unroll
        for (int it = 0; it < 2; it++) {
            int i = tid + it * 256;
            int row = i >> 5, c4 = (i & 31) << 2;
            uint32_t d = (uint32_t)__cvta_generic_to_shared(&Bs[stage][row][c4]);
            cp16(d, Bbase + (size_t)(k0 + row) * N + c4);
        }
    };

    load_stage(0, 0);
    asm volatile("cp.async.commit_group;");

    for (int kc = 0; kc < nk; kc++) {
        int cur = kc & 1;
        if (kc + 1 < nk) {
            load_stage(cur ^ 1, (kc + 1) << 4);
            asm volatile("cp.async.commit_group;");
            asm volatile("cp.async.wait_group 1;");
        } else {
            asm volatile("cp.async.wait_group 0;");
        }
        __syncthreads();

        uint32_t ahi[4][4], alo[4][4], bhi[4][2], blo[4][2];
#pragma unroll
        for (int mt = 0; mt < 4; mt++) {
            int m = wm * 64 + mt * 16;
            float2 q0 = *(const float2*)&As[cur][m + gid][tq * 2];
            float2 q1 = *(const float2*)&As[cur][m + gid + 8][tq * 2];
            float2 q2 = *(const float2*)&As[cur][m + gid][tq * 2 + 8];
            float2 q3 = *(const float2*)&As[cur][m + gid + 8][tq * 2 + 8];
            bf16_split_pack(q0.x, q0.y, ahi[mt][0], alo[mt][0]);
            bf16_split_pack(q1.x, q1.y, ahi[mt][1], alo[mt][1]);
            bf16_split_pack(q2.x, q2.y, ahi[mt][2], alo[mt][2]);
            bf16_split_pack(q3.x, q3.y, ahi[mt][3], alo[mt][3]);
        }
#pragma unroll
        for (int nt = 0; nt < 4; nt++) {
            int n = wn * 32 + nt * 8;
            float u0 = Bs[cur][tq * 2][n + gid];
            float u1 = Bs[cur][tq * 2 + 1][n + gid];
            float u2 = Bs[cur][tq * 2 + 8][n + gid];
            float u3 = Bs[cur][tq * 2 + 9][n + gid];
            bf16_split_pack(u0, u1, bhi[nt][0], blo[nt][0]);
            bf16_split_pack(u2, u3, bhi[nt][1], blo[nt][1]);
        }
#pragma unroll
        for (int mt = 0; mt < 4; mt++)
#pragma unroll
            for (int nt = 0; nt < 4; nt++) {
                MMA_BF16(acc[mt][nt], ahi[mt], bhi[nt]);
                MMA_BF16(acc[mt][nt], ahi[mt], blo[nt]);
                MMA_BF16(acc[mt][nt], alo[mt], bhi[nt]);
            }
        __syncthreads();
    }

#pragma unroll
    for (int mt = 0; mt < 4; mt++) {
        int gr = bm + wm * 64 + mt * 16 + gid;
#pragma unroll
        for (int nt = 0; nt < 4; nt++) {
            int gc = bn + wn * 32 + nt * 8 + tq * 2;
            float2 bv = *(const float2*)&bias[gc];
            float v0 = acc[mt][nt][0] + bv.x;
            float v1 = acc[mt][nt][1] + bv.y;
            float v2 = acc[mt][nt][2] + bv.x;
            float v3 = acc[mt][nt][3] + bv.y;
            if (RELU) {
                v0 = fmaxf(v0, 0.f); v1 = fmaxf(v1, 0.f);
                v2 = fmaxf(v2, 0.f); v3 = fmaxf(v3, 0.f);
            }
            *(float2*)&C[(size_t)gr * N + gc]       = make_float2(v0, v1);
            *(float2*)&C[(size_t)(gr + 8) * N + gc] = make_float2(v2, v3);
        }
    }
}

// ---------------------------------------------------------------------------
// fp16 tensor-core GEMM (transformer), 3-stage cp.async pipeline.
// C = A@B^T + bias (+relu).  A [M,K] fp16 K-major, B [N,K] fp16 K-major.
// 128x128x16 tile, 256 threads, warp tile 64x32, m16n8k16 f16 MMA.
// ---------------------------------------------------------------------------
#define AH_STRIDE 24   // u16 per smem row; 12 words -> conflict-free

template <int RELU, int OHALF>
__global__ void __launch_bounds__(256)
fp16_gemm_kernel(const uint16_t* __restrict__ A, const uint16_t* __restrict__ B,
                 const float* __restrict__ bias,
                 float* __restrict__ Cf, uint16_t* __restrict__ Ch,
                 int M, int K, int N) {
    __shared__ __align__(16) uint16_t As[3][128][AH_STRIDE];
    __shared__ __align__(16) uint16_t Bs[3][128][AH_STRIDE];

    int tid  = threadIdx.x;
    int warp = tid >> 5;
    int lane = tid & 31;
    int gid  = lane >> 2;
    int tq   = lane & 3;
    int wm   = warp >> 2;   // 0..1 -> 64-row slice
    int wn   = warp & 3;    // 0..3 -> 32-col slice

    int bm = blockIdx.y * 128;
    int bn = blockIdx.x * 128;

    float acc[4][4][4];
#pragma unroll
    for (int i = 0; i < 4; i++)
#pragma unroll
        for (int j = 0; j < 4; j++)
#pragma unroll
            for (int r = 0; r < 4; r++) acc[i][j][r] = 0.f;

    int nk = K >> 4;
    const uint16_t* Abase = A + (size_t)bm * K;
    const uint16_t* Bbase = B + (size_t)bn * K;

    auto load_stage = [&](int stage, int k0) {
        int row = tid >> 1, c = tid & 1;
        uint32_t da = (uint32_t)__cvta_generic_to_shared(&As[stage][row][c * 8]);
        cp16(da, Abase + (size_t)row * K + k0 + c * 8);
        uint32_t db = (uint32_t)__cvta_generic_to_shared(&Bs[stage][row][c * 8]);
        cp16(db, Bbase + (size_t)row * K + k0 + c * 8);
    };

    // prime 2 stages
    load_stage(0, 0);
    asm volatile("cp.async.commit_group;");
    load_stage(1, 16);
    asm volatile("cp.async.commit_group;");

    int cur = 0;
    for (int kc = 0; kc < nk; kc++) {
        if (kc + 2 < nk) {
            int st = cur - 1; if (st < 0) st += 3;   // (cur+2)%3
            load_stage(st, (kc + 2) << 4);
            asm volatile("cp.async.commit_group;");
        }
        int rem = nk - kc - 1;
        if (rem >= 2)      asm volatile("cp.async.wait_group 2;");
        else if (rem == 1) asm volatile("cp.async.wait_group 1;");
        else               asm volatile("cp.async.wait_group 0;");
        __syncthreads();

        uint32_t af[4][4], bf[4][2];
#pragma unroll
        for (int mt = 0; mt < 4; mt++) {
            int m = wm * 64 + mt * 16;
            af[mt][0] = *(const uint32_t*)&As[cur][m + gid][tq * 2];
            af[mt][1] = *(const uint32_t*)&As[cur][m + gid + 8][tq * 2];
            af[mt][2] = *(const uint32_t*)&As[cur][m + gid][tq * 2 + 8];
            af[mt][3] = *(const uint32_t*)&As[cur][m + gid + 8][tq * 2 + 8];
        }
#pragma unroll
        for (int nt = 0; nt < 4; nt++) {
            int n = wn * 32 + nt * 8;
            bf[nt][0] = *(const uint32_t*)&Bs[cur][n + gid][tq * 2];
            bf[nt][1] = *(const uint32_t*)&Bs[cur][n + gid][tq * 2 + 8];
        }
#pragma unroll
        for (int mt = 0; mt < 4; mt++)
#pragma unroll
            for (int nt = 0; nt < 4; nt++)
                MMA_F16(acc[mt][nt], af[mt], bf[nt]);
        __syncthreads();

        cur++; if (cur == 3) cur = 0;
    }

#pragma unroll
    for (int mt = 0; mt < 4; mt++) {
        int gr = bm + wm * 64 + mt * 16 + gid;
#pragma unroll
        for (int nt = 0; nt < 4; nt++) {
            int gc = bn + wn * 32 + nt * 8 + tq * 2;
            float2 bv = *(const float2*)&bias[gc];
            float v0 = acc[mt][nt][0] + bv.x;
            float v1 = acc[mt][nt][1] + bv.y;
            float v2 = acc[mt][nt][2] + bv.x;
            float v3 = acc[mt][nt][3] + bv.y;
            if (RELU) {
                v0 = fmaxf(v0, 0.f); v1 = fmaxf(v1, 0.f);
                v2 = fmaxf(v2, 0.f); v3 = fmaxf(v3, 0.f);
            }
            if (OHALF) {
                *(uint32_t*)&Ch[(size_t)gr * N + gc]       = f2h2(v0, v1);
                *(uint32_t*)&Ch[(size_t)(gr + 8) * N + gc] = f2h2(v2, v3);
            } else {
                *(float2*)&Cf[(size_t)gr * N + gc]       = make_float2(v0, v1);
                *(float2*)&Cf[(size_t)(gr + 8) * N + gc] = make_float2(v2, v3);
            }
        }
    }
}

// ---------------------------------------------------------------------------
// Gather (compact rows) + L2-normalize.  grid (PP, NG), block 256.
// ---------------------------------------------------------------------------
__global__ void gather_norm2_kernel(const float* __restrict__ h2c,
                                    float* __restrict__ att_out, float* __restrict__ h,
                                    uint16_t* __restrict__ h_h) {
    int gi = blockIdx.y;
    int t = gi & 15, g = gi >> 4;
    int p = blockIdx.x;
    int f = threadIdx.x;
    float v = h2c[((size_t)gi * PP + p) * 256 + f];
    float s = v * v;
    __shared__ float red[8];
    for (int o = 16; o; o >>= 1) s += __shfl_xor_sync(0xffffffffu, s, o);
    if ((f & 31) == 0) red[f >> 5] = s;
    __syncthreads();
    float tot = red[0] + red[1] + red[2] + red[3] + red[4] + red[5] + red[6] + red[7];
    float norm = fmaxf(sqrtf(tot), 1e-12f);
    v /= norm;
    size_t o = ((size_t)(t * PP + p)) * DM + g * 256 + f;
    att_out[o] = v;
    h[o]       = v;
    h_h[o]     = f2h(v);
}

// ---------------------------------------------------------------------------
// Banded attention: window 4, T=16.  One block per (p, head), 128 threads.
// ---------------------------------------------------------------------------
__global__ void attn_kernel(const uint16_t* __restrict__ qkv_h, uint16_t* __restrict__ out_h) {
    int ph = blockIdx.x;
    int p = ph >> 3;
    int h = ph & 7;
    __shared__ float qs[16][64], ks[16][64], vs[16][64];
    int tid = threadIdx.x;
    for (int i = tid; i < 512; i += 128) {
        int t = i >> 5, d2 = (i & 31) << 1;
        const __half2* b = (const __half2*)(qkv_h + ((size_t)(t * PP + p)) * 1536 + h * 64 + d2);
        float2 fq = __half22float2(b[0]);
        float2 fk = __half22float2(b[256]);
        float2 fv = __half22float2(b[512]);
        qs[t][d2] = fq.x; qs[t][d2 + 1] = fq.y;
        ks[t][d2] = fk.x; ks[t][d2 + 1] = fk.y;
        vs[t][d2] = fv.x; vs[t][d2 + 1] = fv.y;
    }
    __syncthreads();
    int warp = tid >> 5, lane = tid & 31;
    for (int t = warp; t < 16; t += 4) {
        int s0 = t - 3; if (s0 < 0) s0 = 0;
        int ns = t - s0 + 1;
        float sc[4];
        float mx = -1e30f;
        for (int si = 0; si < ns; si++) {
            int s = s0 + si;
            float d0 = qs[t][lane] * ks[s][lane] + qs[t][lane + 32] * ks[s][lane + 32];
            for (int o = 16; o; o >>= 1) d0 += __shfl_xor_sync(0xffffffffu, d0, o);
            d0 *= 0.125f;
            sc[si] = d0;
            mx = fmaxf(mx, d0);
        }
        float sum = 0.f;
        for (int si = 0; si < ns; si++) { sc[si] = expf(sc[si] - mx); sum += sc[si]; }
        float inv = 1.f / sum;
        float o0 = 0.f, o1 = 0.f;
        for (int si = 0; si < ns; si++) {
            int s = s0 + si;
            o0 += sc[si] * vs[s][lane];
            o1 += sc[si] * vs[s][lane + 32];
        }
        size_t ob = ((size_t)(t * PP + p)) * DM + h * 64;
        out_h[ob + lane]      = f2h(o0 * inv);
        out_h[ob + lane + 32] = f2h(o1 * inv);
    }
}

// ---------------------------------------------------------------------------
// h = LayerNorm(h + delta) * g + b; emits fp16 copy h_h.
// ---------------------------------------------------------------------------
__global__ void resid_ln_kernel(float* __restrict__ h, const float* __restrict__ delta,
                                const float* __restrict__ g, const float* __restrict__ b,
                                uint16_t* __restrict__ h_h) {
    int row = blockIdx.x;
    int tid = threadIdx.x;
    size_t base = (size_t)row * DM;
    float v[4];
    float s = 0.f;
#pragma unroll
    for (int i = 0; i < 4; i++) {
        int c = tid + i * 128;
        float x = h[base + c] + delta[base + c];
        v[i] = x; s += x;
    }
    __shared__ float red[4];
    for (int o = 16; o; o >>= 1) s += __shfl_xor_sync(0xffffffffu, s, o);
    if ((tid & 31) == 0) red[tid >> 5] = s;
    __syncthreads();
    float mean = (red[0] + red[1] + red[2] + red[3]) * (1.f / 512.f);
    __syncthreads();
    float s2 = 0.f;
#pragma unroll
    for (int i = 0; i < 4; i++) { float d = v[i] - mean; s2 += d * d; }
    for (int o = 16; o; o >>= 1) s2 += __shfl_xor_sync(0xffffffffu, s2, o);
    if ((tid & 31) == 0) red[tid >> 5] = s2;
    __syncthreads();
    float var = (red[0] + red[1] + red[2] + red[3]) * (1.f / 512.f);
    float rstd = rsqrtf(var + 1e-5f);
#pragma unroll
    for (int i = 0; i < 4; i++) {
        int c = tid + i * 128;
        float o = (v[i] - mean) * rstd * g[c] + b[c];
        h[base + c]   = o;
        h_h[base + c] = f2h(o);
    }
}

// ---------------------------------------------------------------------------
// FINAL layer: LayerNorm(h + delta)*g + b, then dot with Wout -> scal_out.
// ---------------------------------------------------------------------------
__global__ void resid_ln_out_kernel(const float* __restrict__ h, const float* __restrict__ delta,
                                    const float* __restrict__ g, const float* __restrict__ b,
                                    const float* __restrict__ Wout, float* __restrict__ out) {
    int row = blockIdx.x;
    int tid = threadIdx.x;
    size_t base = (size_t)row * DM;
    float v[4];
    float s = 0.f;
#pragma unroll
    for (int i = 0; i < 4; i++) {
        int c = tid + i * 128;
        float x = h[base + c] + delta[base + c];
        v[i] = x; s += x;
    }
    __shared__ float red[4];
    for (int o = 16; o; o >>= 1) s += __shfl_xor_sync(0xffffffffu, s, o);
    if ((tid & 31) == 0) red[tid >> 5] = s;
    __syncthreads();
    float mean = (red[0] + red[1] + red[2] + red[3]) * (1.f / 512.f);
    __syncthreads();
    float s2 = 0.f;
#pragma unroll
    for (int i = 0; i < 4; i++) { float d = v[i] - mean; s2 += d * d; }
    for (int o = 16; o; o >>= 1) s2 += __shfl_xor_sync(0xffffffffu, s2, o);
    if ((tid & 31) == 0) red[tid >> 5] = s2;
    __syncthreads();
    float var = (red[0] + red[1] + red[2] + red[3]) * (1.f / 512.f);
    float rstd = rsqrtf(var + 1e-5f);
    float dot = 0.f;
#pragma unroll
    for (int i = 0; i < 4; i++) {
        int c = tid + i * 128;
        float o = (v[i] - mean) * rstd * g[c] + b[c];
        dot += o * Wout[c];
    }
    __syncthreads();
    for (int o = 16; o; o >>= 1) dot += __shfl_xor_sync(0xffffffffu, dot, o);
    if ((tid & 31) == 0) red[tid >> 5] = dot;
    __syncthreads();
    if (tid == 0) out[row] = red[0] + red[1] + red[2] + red[3];
}

// ---------------------------------------------------------------------------
// Weight prep
// ---------------------------------------------------------------------------
__global__ void prep_wc_kernel(const float* __restrict__ W1s, const float* __restrict__ W1n,
                               const float* __restrict__ W2s, const float* __restrict__ W2n,
                               float* __restrict__ wc1, float* __restrict__ wc2) {
    int i = blockIdx.x * blockDim.x + threadIdx.x;
    if (i < 256 * 256) {
        int k = i >> 8, c = i & 255;
        wc1[i] = (k < 128) ? W1s[k * 256 + c] : W1n[(k - 128) * 256 + c];
    }
    if (i < 512 * 256) {
        int k = i >> 8, c = i & 255;
        wc2[i] = (k < 256) ? W2s[k * 256 + c] : W2n[(k - 256) * 256 + c];
    }
}

__global__ void prep_wqkvT_kernel(const float* __restrict__ Wq, const float* __restrict__ Wk,
                                  const float* __restrict__ Wv,
                                  const float* __restrict__ bq, const float* __restrict__ bk,
                                  const float* __restrict__ bv,
                                  uint16_t* __restrict__ Th, float* __restrict__ bqkv) {
    long i = (long)blockIdx.x * blockDim.x + threadIdx.x;
    const long tot = 2L * 1536 * 512;
    if (i < tot) {
        int l = (int)(i / (1536L * 512));
        long rem = i % (1536L * 512);
        int n = (int)(rem / 512), k = (int)(rem % 512);
        const float* W = (n < 512) ? Wq : (n < 1024) ? Wk : Wv;
        int nn = n & 511;
        Th[i] = f2h(W[(size_t)l * 512 * 512 + (size_t)k * 512 + nn]);
    }
    if (i < 2 * 1536) {
        int l = (int)(i / 1536), c = (int)(i % 1536);
        float v;
        if (c < 512)       v = bq[l * 512 + c];
        else if (c < 1024) v = bk[l * 512 + c - 512];
        else               v = bv[l * 512 + c - 1024];
        bqkv[i] = v;
    }
}

__global__ void prep_wT_kernel(const float* __restrict__ W, uint16_t* __restrict__ Th,
                               int K, int N, int L) {
    long i = (long)blockIdx.x * blockDim.x + threadIdx.x;
    long tot = (long)L * K * N;
    if (i >= tot) return;
    long per = (long)K * N;
    int l = (int)(i / per);
    long rem = i % per;
    int n = (int)(rem / K), k = (int)(rem % K);
    Th[i] = f2h(W[(size_t)l * per + (size_t)k * N + n]);
}

// ---------------------------------------------------------------------------
// Host driver
// ---------------------------------------------------------------------------
extern "C" void kernel_launch(void* const* d_in, const int* in_sizes, int n_in,
                              void* d_out, int out_size) {
    const float* x_i   = (const float*)d_in[0];
    const float* x_j   = (const float*)d_in[1];
    const int*   src_i = (const int*)d_in[2];
    const int*   dst_i = (const int*)d_in[3];
    const int*   src_j = (const int*)d_in[4];
    const int*   dst_j = (const int*)d_in[5];
    const int*   idx_i = (const int*)d_in[6];
    const int*   idx_j = (const int*)d_in[7];
    const float* W1s = (const float*)d_in[8];
    const float* W1n = (const float*)d_in[9];
    const float* b1  = (const float*)d_in[10];
    const float* W2s = (const float*)d_in[11];
    const float* W2n = (const float*)d_in[12];
    const float* b2  = (const float*)d_in[13];
    const float* Wq  = (const float*)d_in[14];
    const float* Wk  = (const float*)d_in[15];
    const float* Wv  = (const float*)d_in[16];
    const float* bq  = (const float*)d_in[17];
    const float* bk  = (const float*)d_in[18];
    const float* bv  = (const float*)d_in[19];
    const float* Wo  = (const float*)d_in[20];
    const float* bo  = (const float*)d_in[21];
    const float* Wf1 = (const float*)d_in[22];
    const float* bf1 = (const float*)d_in[23];
    const float* Wf2 = (const float*)d_in[24];
    const float* bf2 = (const float*)d_in[25];
    const float* g1  = (const float*)d_in[26];
    const float* bg1 = (const float*)d_in[27];
    const float* g2  = (const float*)d_in[28];
    const float* bg2 = (const float*)d_in[29];
    const float* Wout= (const float*)d_in[30];

    void* p;
    cudaGetSymbolAddress(&p, g_sage);  float*    SB = (float*)p;
    cudaGetSymbolAddress(&p, g_w);     float*    WB = (float*)p;
    cudaGetSymbolAddress(&p, g_act);   float*    AB = (float*)p;
    cudaGetSymbolAddress(&p, g_h16);   uint16_t* HB = (uint16_t*)p;
    cudaGetSymbolAddress(&p, g_iblob); int*      IB = (int*)p;

    float* h1   = SB + S_H1;
    float* bufA = SB + S_BUFA;
    float* bufB = SB + S_BUFB;
    float* h2   = SB + S_H2;

    float* wc1  = WB + W_WC1;
    float* wc2  = WB + W_WC2;
    float* bqkv = WB + W_BQKV;

    float* hbuf  = AB + A_H;
    float* delta = AB + A_DELTA;

    uint16_t* h_h    = HB + H_HH;
    uint16_t* qkv_h  = HB + H_QKV;
    uint16_t* tmp_h  = HB + H_TMP;
    uint16_t* ffb_h  = HB + H_FFB;
    uint16_t* wqkv_h = HB + H_WQKV;
    uint16_t* wo_h   = HB + H_WO;
    uint16_t* wf1_h  = HB + H_WF1;
    uint16_t* wf2_h  = HB + H_WF2;

    int* deg  = IB + I_DEG;
    int* cur  = IB + I_CUR;
    int* off  = IB + I_OFF;
    int* csrc = IB + I_CSR;

    float* att_out  = (float*)d_out;
    float* scal_out = att_out + (size_t)NTOK * DM;

    // ---- weight prep ----
    prep_wc_kernel<<<(512 * 256 + 255) / 256, 256>>>(W1s, W1n, W2s, W2n, wc1, wc2);
    prep_wqkvT_kernel<<<(2 * 1536 * 512 + 255) / 256, 256>>>(
        Wq, Wk, Wv, bq, bk, bv, wqkv_h, bqkv);
    prep_wT_kernel<<<(2 * 512 * 512 + 255) / 256, 256>>>(Wo, wo_h, 512, 512, 2);
    prep_wT_kernel<<<(2 * 512 * 2048 + 255) / 256, 256>>>(Wf1, wf1_h, 512, 2048, 2);
    prep_wT_kernel<<<(2 * 2048 * 512 + 255) / 256, 256>>>(Wf2, wf2_h, 2048, 512, 2);

    // ---- batched CSR for all NG graphs ----
    cudaMemsetAsync(IB, 0, (size_t)2 * NG * NN * sizeof(int));   // deg + cur
    hist_b_kernel<<<dim3((EE + 255) / 256, NG), 256>>>(dst_i, dst_j, deg);
    scan_b_kernel<<<NG, 1024>>>(deg, off);
    fill_b_kernel<<<dim3((EE + 255) / 256, NG), 256>>>(src_i, src_j, dst_i, dst_j, off, cur, csrc);

    // ---- GraphSAGE, single batched pass; layer 2 only for selected nodes ----
    build_A1_kernel<<<dim3(NN / 4, NG), 128>>>(x_i, x_j, off, csrc, bufA);
    sage_gemm_kernel<1><<<dim3(2, HB1 / 128), 256>>>(bufA, wc1, b1, h1, HB1, 256, 256);
    build_A2_kernel<<<dim3(PP / 2, NG), 128>>>(h1, idx_i, idx_j, off, csrc, bufB);
    sage_gemm_kernel<0><<<dim3(2, HB2 / 128), 256>>>(bufB, wc2, b2, h2, HB2, 512, 256);
    gather_norm2_kernel<<<dim3(PP, NG), 256>>>(h2, att_out, hbuf, h_h);

    // ---- Transformer (fp16 tensor-core GEMMs, fp32 accumulate) ----
    for (int l = 0; l < NLAY; l++) {
        fp16_gemm_kernel<0, 1><<<dim3(12, NTOK / 128), 256>>>(
            h_h, wqkv_h + (size_t)l * 1536 * 512, bqkv + l * 1536,
            nullptr, qkv_h, NTOK, 512, 1536);
        attn_kernel<<<PP * NHEAD, 128>>>(qkv_h, tmp_h);
        fp16_gemm_kernel<0, 0><<<dim3(4, NTOK / 128), 256>>>(
            tmp_h, wo_h + (size_t)l * 512 * 512, bo + l * 512,
            delta, nullptr, NTOK, 512, 512);
        resid_ln_kernel<<<NTOK, 128>>>(hbuf, delta, g1 + l * 512, bg1 + l * 512, h_h);
        fp16_gemm_kernel<1, 1><<<dim3(16, NTOK / 128), 256>>>(
            h_h, wf1_h + (size_t)l * 2048 * 512, bf1 + l * 2048,
            nullptr, ffb_h, NTOK, 512, 2048);
        fp16_gemm_kernel<0, 0><<<dim3(4, NTOK / 128), 256>>>(
            ffb_h, wf2_h + (size_t)l * 512 * 2048, bf2 + l * 512,
            delta, nullptr, NTOK, 2048, 512);
        if (l < NLAY - 1) {
            resid_ln_kernel<<<NTOK, 128>>>(hbuf, delta, g2 + l * 512, bg2 + l * 512, h_h);
        } else {
            resid_ln_out_kernel<<<NTOK, 128>>>(hbuf, delta, g2 + l * 512, bg2 + l * 512,
                                               Wout, scal_out);
        }
    }
}

// round 17
// speedup vs baseline: 1.9299x; 1.1077x over previous
#include <cuda_runtime.h>
#include <cuda_fp16.h>
#include <cstdint>

// ---------------------------------------------------------------------------
// Problem constants
// ---------------------------------------------------------------------------
#define TT     16
#define NN     20000
#define NP     20096            // NN padded to multiple of 128
#define NG     32               // 32 (t, graph) instances, gi = g*16 + t
#define EE     320000
#define PP     4096
#define DIN    128
#define NHEAD  8
#define NLAY   2
#define DM     512
#define NTOK   (TT * PP)     // 65536
#define HB1    (NG * NP)     // 643072 rows (layer-1 GEMM)
#define HB2    (NG * PP)     // 131072 rows (layer-2 GEMM, selected only)

// ---------------------------------------------------------------------------
// Scratch blobs (total .bss ~1.8 GB < 4GB aarch64 ADRP limit)
// SAGE fp16 blob with aliasing:
//   bufA [HB1,256] u16 at 0;  h1 [HB1,256] u16 at HB1*256
//   bufB [HB2,512] u16 aliases dead bufA;  h2 (fp32, [HB2,256]) aliases dead h1
// ---------------------------------------------------------------------------
constexpr size_t G_BUFA = 0;
constexpr size_t G_H1   = (size_t)HB1 * 256;
constexpr size_t G_BUFB = 0;                             // alias
constexpr size_t G_TOTAL= (size_t)2 * HB1 * 256;         // ~0.66 GB
__device__ uint16_t g_sg16[G_TOTAL];

// fp32: transformer biases only
__device__ float g_bqkv[2 * 1536];

// fp32 activations (~0.27 GB)
constexpr size_t A_H    = 0;                           // [NTOK,512]  hidden
constexpr size_t A_DELTA= A_H   + (size_t)NTOK * 512;  // [NTOK,512]  GEMM fp32 out
constexpr size_t A_TOTAL= A_DELTA + (size_t)NTOK * 512;
__device__ float g_act[A_TOTAL];

// fp16 operand arrays (u16 raw bits, ~0.62 GB)
constexpr size_t H_HH   = 0;                              // [NTOK,512]  hidden fp16
constexpr size_t H_QKV  = H_HH  + (size_t)NTOK * 512;     // [NTOK,1536]
constexpr size_t H_TMP  = H_QKV + (size_t)NTOK * 1536;    // [NTOK,512]  attn out
constexpr size_t H_FFB  = H_TMP + (size_t)NTOK * 512;     // [NTOK,2048]
constexpr size_t H_WQKV = H_FFB + (size_t)NTOK * 2048;    // [2,1536,512] (transposed)
constexpr size_t H_WO   = H_WQKV + 2ull * 1536 * 512;     // [2,512,512]
constexpr size_t H_WF1  = H_WO   + 2ull * 512 * 512;      // [2,2048,512]
constexpr size_t H_WF2  = H_WF1  + 2ull * 2048 * 512;     // [2,512,2048]
constexpr size_t H_WC1T = H_WF2  + 2ull * 512 * 2048;     // [256,256]  wc1^T fp16
constexpr size_t H_WC2T = H_WC1T + 256ull * 256;          // [256,512]  wc2^T fp16
constexpr size_t H_TOTAL= H_WC2T + 256ull * 512;
__device__ uint16_t g_h16[H_TOTAL];

// CSR int region (~49 MB)
constexpr size_t I_DEG = 0;
constexpr size_t I_CUR = I_DEG + (size_t)NG * NN;
constexpr size_t I_OFF = I_CUR + (size_t)NG * NN;
constexpr size_t I_CSR = I_OFF + (size_t)NG * (NN + 1);
constexpr size_t I_TOTAL = I_CSR + (size_t)NG * EE;
__device__ int g_iblob[I_TOTAL];

// ---------------------------------------------------------------------------
// numeric helpers
// ---------------------------------------------------------------------------
__device__ __forceinline__ uint16_t f2h(float v) {
    uint16_t r;
    asm("cvt.rn.f16.f32 %0, %1;" : "=h"(r) : "f"(v));
    return r;
}

__device__ __forceinline__ uint32_t f2h2(float v0, float v1) {   // low = v0
    uint32_t r;
    asm("cvt.rn.f16x2.f32 %0, %1, %2;" : "=r"(r) : "f"(v1), "f"(v0));
    return r;
}

__device__ __forceinline__ void cp16(uint32_t daddr, const void* src) {
    asm volatile("cp.async.cg.shared.global [%0], [%1], 16;" :: "r"(daddr), "l"(src));
}

// ---------------------------------------------------------------------------
// Batched CSR construction
// ---------------------------------------------------------------------------
__global__ void hist_b_kernel(const int* __restrict__ dst_i, const int* __restrict__ dst_j,
                              int* __restrict__ deg) {
    int gi = blockIdx.y;
    int t = gi & 15, g = gi >> 4;
    const int* dst = (g == 0 ? dst_i : dst_j) + (size_t)t * EE;
    int* d = deg + (size_t)gi * NN;
    int e = blockIdx.x * blockDim.x + threadIdx.x;
    if (e < EE) atomicAdd(&d[dst[e]], 1);
}

__global__ void __launch_bounds__(1024)
scan_b_kernel(const int* __restrict__ deg_all, int* __restrict__ off_all) {
    __shared__ int wsum[32];
    const int CH = 20;
    int gi = blockIdx.x;
    const int* deg = deg_all + (size_t)gi * NN;
    int* off = off_all + (size_t)gi * (NN + 1);
    int tid = threadIdx.x;
    int lane = tid & 31, warp = tid >> 5;
    int base = tid * CH;
    int loc[CH];
    int s = 0;
#pragma unroll
    for (int i = 0; i < CH; i++) {
        int idx = base + i;
        int v = (idx < NN) ? deg[idx] : 0;
        s += v;
        loc[i] = s;
    }
    int ssum = s;
#pragma unroll
    for (int o = 1; o < 32; o <<= 1) {
        int t = __shfl_up_sync(0xffffffffu, ssum, o);
        if (lane >= o) ssum += t;
    }
    if (lane == 31) wsum[warp] = ssum;
    __syncthreads();
    if (warp == 0) {
        int w = wsum[lane];
#pragma unroll
        for (int o = 1; o < 32; o <<= 1) {
            int t = __shfl_up_sync(0xffffffffu, w, o);
            if (lane >= o) w += t;
        }
        wsum[lane] = w;
    }
    __syncthreads();
    int offset = ssum - s + (warp ? wsum[warp - 1] : 0);
    if (tid == 0) off[0] = 0;
#pragma unroll
    for (int i = 0; i < CH; i++) {
        int idx = base + i;
        if (idx < NN) off[idx + 1] = offset + loc[i];
    }
}

__global__ void fill_b_kernel(const int* __restrict__ src_i, const int* __restrict__ src_j,
                              const int* __restrict__ dst_i, const int* __restrict__ dst_j,
                              const int* __restrict__ off_all, int* __restrict__ cur_all,
                              int* __restrict__ csrc_all) {
    int gi = blockIdx.y;
    int t = gi & 15, g = gi >> 4;
    const int* src = (g == 0 ? src_i : src_j) + (size_t)t * EE;
    const int* dst = (g == 0 ? dst_i : dst_j) + (size_t)t * EE;
    const int* off = off_all + (size_t)gi * (NN + 1);
    int* cur = cur_all + (size_t)gi * NN;
    int* csrc = csrc_all + (size_t)gi * EE;
    int e = blockIdx.x * blockDim.x + threadIdx.x;
    if (e < EE) {
        int d = dst[e];
        int p = atomicAdd(&cur[d], 1);
        csrc[off[d] + p] = src[e];
    }
}

// ---------------------------------------------------------------------------
// Layer-1 build A = [self | mean_agg], fp32 in, fp16 out.  warp per node.
// grid (NN/4, NG), block 128.
// ---------------------------------------------------------------------------
__global__ void build_A1_kernel(const float* __restrict__ x_i, const float* __restrict__ x_j,
                                const int* __restrict__ off_all, const int* __restrict__ csrc_all,
                                uint16_t* __restrict__ out_all) {
    int gi = blockIdx.y;
    int t = gi & 15, g = gi >> 4;
    const float* feat = (g == 0 ? x_i : x_j) + (size_t)t * NN * DIN;
    const int* off = off_all + (size_t)gi * (NN + 1);
    const int* csrc = csrc_all + (size_t)gi * EE;
    uint16_t* out = out_all + (size_t)gi * NP * 256;

    int warp = threadIdx.x >> 5, lane = threadIdx.x & 31;
    int n = blockIdx.x * 4 + warp;
    int c4 = lane * 4;
    float4 self = *(const float4*)(feat + (size_t)n * DIN + c4);
    int s = off[n], e = off[n + 1];
    float4 acc = make_float4(0.f, 0.f, 0.f, 0.f);
    int i = s;
    for (; i + 4 <= e; i += 4) {
        int a0 = csrc[i], a1 = csrc[i + 1], a2 = csrc[i + 2], a3 = csrc[i + 3];
        float4 v0 = *(const float4*)(feat + (size_t)a0 * DIN + c4);
        float4 v1 = *(const float4*)(feat + (size_t)a1 * DIN + c4);
        float4 v2 = *(const float4*)(feat + (size_t)a2 * DIN + c4);
        float4 v3 = *(const float4*)(feat + (size_t)a3 * DIN + c4);
        acc.x += v0.x + v1.x + v2.x + v3.x;
        acc.y += v0.y + v1.y + v2.y + v3.y;
        acc.z += v0.z + v1.z + v2.z + v3.z;
        acc.w += v0.w + v1.w + v2.w + v3.w;
    }
    for (; i < e; i++) {
        float4 v = *(const float4*)(feat + (size_t)csrc[i] * DIN + c4);
        acc.x += v.x; acc.y += v.y; acc.z += v.z; acc.w += v.w;
    }
    int d = e - s; if (d < 1) d = 1;
    float fd = (float)d;
    uint2 sv = make_uint2(f2h2(self.x, self.y), f2h2(self.z, self.w));
    uint2 mv = make_uint2(f2h2(acc.x / fd, acc.y / fd), f2h2(acc.z / fd, acc.w / fd));
    *(uint2*)(out + (size_t)n * 256 + c4)       = sv;
    *(uint2*)(out + (size_t)n * 256 + 128 + c4) = mv;
}

// ---------------------------------------------------------------------------
// Layer-2 build A for SELECTED nodes.  fp16 in (h1), fp16 out.
// grid (PP/2, NG), block 128 (2 nodes, 64 threads each).
// ---------------------------------------------------------------------------
__global__ void build_A2_kernel(const uint16_t* __restrict__ h1_all,
                                const int* __restrict__ idx_i, const int* __restrict__ idx_j,
                                const int* __restrict__ off_all, const int* __restrict__ csrc_all,
                                uint16_t* __restrict__ out_all) {
    int gi = blockIdx.y;
    int t = gi & 15, g = gi >> 4;
    const uint16_t* feat = h1_all + (size_t)gi * NP * 256;
    const int* off = off_all + (size_t)gi * (NN + 1);
    const int* csrc = csrc_all + (size_t)gi * EE;
    const int* idx = ((g == 0) ? idx_i : idx_j) + (size_t)t * PP;
    uint16_t* out = out_all + (size_t)gi * PP * 512;

    int half = threadIdx.x >> 6;
    int st   = threadIdx.x & 63;
    int p = blockIdx.x * 2 + half;
    int n = idx[p];
    int c4 = st * 4;                      // 0..252
    uint2 selfu = *(const uint2*)(feat + (size_t)n * 256 + c4);
    int s = off[n], e = off[n + 1];
    float4 acc = make_float4(0.f, 0.f, 0.f, 0.f);
    for (int i = s; i < e; i++) {
        uint2 vu = *(const uint2*)(feat + (size_t)csrc[i] * 256 + c4);
        float2 a = __half22float2(*(__half2*)&vu.x);
        float2 b = __half22float2(*(__half2*)&vu.y);
        acc.x += a.x; acc.y += a.y; acc.z += b.x; acc.w += b.y;
    }
    int d = e - s; if (d < 1) d = 1;
    float fd = (float)d;
    uint2 mv = make_uint2(f2h2(acc.x / fd, acc.y / fd), f2h2(acc.z / fd, acc.w / fd));
    *(uint2*)(out + (size_t)p * 512 + c4)       = selfu;
    *(uint2*)(out + (size_t)p * 512 + 256 + c4) = mv;
}

// ---------------------------------------------------------------------------
// fp16 tensor-core GEMM, 3-stage cp.async pipeline.
// C = A@B^T + bias (+relu).  A [M,K] fp16 K-major, B [N,K] fp16 K-major.
// 128x128x16 tile, 256 threads, warp tile 64x32, m16n8k16 f16 MMA.
// ---------------------------------------------------------------------------
#define AH_STRIDE 24   // u16 per smem row; 12 words -> conflict-free

#define MMA_F16(d, a, b)                                                             \
    asm volatile(                                                                    \
        "mma.sync.aligned.m16n8k16.row.col.f32.f16.f16.f32 "                         \
        "{%0,%1,%2,%3},{%4,%5,%6,%7},{%8,%9},{%0,%1,%2,%3};"                         \
        : "+f"(d[0]), "+f"(d[1]), "+f"(d[2]), "+f"(d[3])                             \
        : "r"(a[0]), "r"(a[1]), "r"(a[2]), "r"(a[3]), "r"(b[0]), "r"(b[1]))

template <int RELU, int OHALF>
__global__ void __launch_bounds__(256)
fp16_gemm_kernel(const uint16_t* __restrict__ A, const uint16_t* __restrict__ B,
                 const float* __restrict__ bias,
                 float* __restrict__ Cf, uint16_t* __restrict__ Ch,
                 int M, int K, int N) {
    __shared__ __align__(16) uint16_t As[3][128][AH_STRIDE];
    __shared__ __align__(16) uint16_t Bs[3][128][AH_STRIDE];

    int tid  = threadIdx.x;
    int warp = tid >> 5;
    int lane = tid & 31;
    int gid  = lane >> 2;
    int tq   = lane & 3;
    int wm   = warp >> 2;
    int wn   = warp & 3;

    int bm = blockIdx.y * 128;
    int bn = blockIdx.x * 128;

    float acc[4][4][4];
#pragma unroll
    for (int i = 0; i < 4; i++)
#pragma unroll
        for (int j = 0; j < 4; j++)
#pragma unroll
            for (int r = 0; r < 4; r++) acc[i][j][r] = 0.f;

    int nk = K >> 4;
    const uint16_t* Abase = A + (size_t)bm * K;
    const uint16_t* Bbase = B + (size_t)bn * K;

    auto load_stage = [&](int stage, int k0) {
        int row = tid >> 1, c = tid & 1;
        uint32_t da = (uint32_t)__cvta_generic_to_shared(&As[stage][row][c * 8]);
        cp16(da, Abase + (size_t)row * K + k0 + c * 8);
        uint32_t db = (uint32_t)__cvta_generic_to_shared(&Bs[stage][row][c * 8]);
        cp16(db, Bbase + (size_t)row * K + k0 + c * 8);
    };

    load_stage(0, 0);
    asm volatile("cp.async.commit_group;");
    load_stage(1, 16);
    asm volatile("cp.async.commit_group;");

    int cur = 0;
    for (int kc = 0; kc < nk; kc++) {
        if (kc + 2 < nk) {
            int st = cur - 1; if (st < 0) st += 3;
            load_stage(st, (kc + 2) << 4);
            asm volatile("cp.async.commit_group;");
        }
        int rem = nk - kc - 1;
        if (rem >= 2)      asm volatile("cp.async.wait_group 2;");
        else if (rem == 1) asm volatile("cp.async.wait_group 1;");
        else               asm volatile("cp.async.wait_group 0;");
        __syncthreads();

        uint32_t af[4][4], bf[4][2];
#pragma unroll
        for (int mt = 0; mt < 4; mt++) {
            int m = wm * 64 + mt * 16;
            af[mt][0] = *(const uint32_t*)&As[cur][m + gid][tq * 2];
            af[mt][1] = *(const uint32_t*)&As[cur][m + gid + 8][tq * 2];
            af[mt][2] = *(const uint32_t*)&As[cur][m + gid][tq * 2 + 8];
            af[mt][3] = *(const uint32_t*)&As[cur][m + gid + 8][tq * 2 + 8];
        }
#pragma unroll
        for (int nt = 0; nt < 4; nt++) {
            int n = wn * 32 + nt * 8;
            bf[nt][0] = *(const uint32_t*)&Bs[cur][n + gid][tq * 2];
            bf[nt][1] = *(const uint32_t*)&Bs[cur][n + gid][tq * 2 + 8];
        }
#pragma unroll
        for (int mt = 0; mt < 4; mt++)
#pragma unroll
            for (int nt = 0; nt < 4; nt++)
                MMA_F16(acc[mt][nt], af[mt], bf[nt]);
        __syncthreads();

        cur++; if (cur == 3) cur = 0;
    }

#pragma unroll
    for (int mt = 0; mt < 4; mt++) {
        int gr = bm + wm * 64 + mt * 16 + gid;
#pragma unroll
        for (int nt = 0; nt < 4; nt++) {
            int gc = bn + wn * 32 + nt * 8 + tq * 2;
            float2 bv = *(const float2*)&bias[gc];
            float v0 = acc[mt][nt][0] + bv.x;
            float v1 = acc[mt][nt][1] + bv.y;
            float v2 = acc[mt][nt][2] + bv.x;
            float v3 = acc[mt][nt][3] + bv.y;
            if (RELU) {
                v0 = fmaxf(v0, 0.f); v1 = fmaxf(v1, 0.f);
                v2 = fmaxf(v2, 0.f); v3 = fmaxf(v3, 0.f);
            }
            if (OHALF) {
                *(uint32_t*)&Ch[(size_t)gr * N + gc]       = f2h2(v0, v1);
                *(uint32_t*)&Ch[(size_t)(gr + 8) * N + gc] = f2h2(v2, v3);
            } else {
                *(float2*)&Cf[(size_t)gr * N + gc]       = make_float2(v0, v1);
                *(float2*)&Cf[(size_t)(gr + 8) * N + gc] = make_float2(v2, v3);
            }
        }
    }
}

// ---------------------------------------------------------------------------
// Gather (compact rows) + L2-normalize.  grid (PP, NG), block 256.
// ---------------------------------------------------------------------------
__global__ void gather_norm2_kernel(const float* __restrict__ h2c,
                                    float* __restrict__ att_out, float* __restrict__ h,
                                    uint16_t* __restrict__ h_h) {
    int gi = blockIdx.y;
    int t = gi & 15, g = gi >> 4;
    int p = blockIdx.x;
    int f = threadIdx.x;
    float v = h2c[((size_t)gi * PP + p) * 256 + f];
    float s = v * v;
    __shared__ float red[8];
    for (int o = 16; o; o >>= 1) s += __shfl_xor_sync(0xffffffffu, s, o);
    if ((f & 31) == 0) red[f >> 5] = s;
    __syncthreads();
    float tot = red[0] + red[1] + red[2] + red[3] + red[4] + red[5] + red[6] + red[7];
    float norm = fmaxf(sqrtf(tot), 1e-12f);
    v /= norm;
    size_t o = ((size_t)(t * PP + p)) * DM + g * 256 + f;
    att_out[o] = v;
    h[o]       = v;
    h_h[o]     = f2h(v);
}

// ---------------------------------------------------------------------------
// Banded attention: window 4, T=16.  One block per (p, head), 128 threads.
// ---------------------------------------------------------------------------
__global__ void attn_kernel(const uint16_t* __restrict__ qkv_h, uint16_t* __restrict__ out_h) {
    int ph = blockIdx.x;
    int p = ph >> 3;
    int h = ph & 7;
    __shared__ float qs[16][64], ks[16][64], vs[16][64];
    int tid = threadIdx.x;
    for (int i = tid; i < 512; i += 128) {
        int t = i >> 5, d2 = (i & 31) << 1;
        const __half2* b = (const __half2*)(qkv_h + ((size_t)(t * PP + p)) * 1536 + h * 64 + d2);
        float2 fq = __half22float2(b[0]);
        float2 fk = __half22float2(b[256]);
        float2 fv = __half22float2(b[512]);
        qs[t][d2] = fq.x; qs[t][d2 + 1] = fq.y;
        ks[t][d2] = fk.x; ks[t][d2 + 1] = fk.y;
        vs[t][d2] = fv.x; vs[t][d2 + 1] = fv.y;
    }
    __syncthreads();
    int warp = tid >> 5, lane = tid & 31;
    for (int t = warp; t < 16; t += 4) {
        int s0 = t - 3; if (s0 < 0) s0 = 0;
        int ns = t - s0 + 1;
        float sc[4];
        float mx = -1e30f;
        for (int si = 0; si < ns; si++) {
            int s = s0 + si;
            float d0 = qs[t][lane] * ks[s][lane] + qs[t][lane + 32] * ks[s][lane + 32];
            for (int o = 16; o; o >>= 1) d0 += __shfl_xor_sync(0xffffffffu, d0, o);
            d0 *= 0.125f;
            sc[si] = d0;
            mx = fmaxf(mx, d0);
        }
        float sum = 0.f;
        for (int si = 0; si < ns; si++) { sc[si] = expf(sc[si] - mx); sum += sc[si]; }
        float inv = 1.f / sum;
        float o0 = 0.f, o1 = 0.f;
        for (int si = 0; si < ns; si++) {
            int s = s0 + si;
            o0 += sc[si] * vs[s][lane];
            o1 += sc[si] * vs[s][lane + 32];
        }
        size_t ob = ((size_t)(t * PP + p)) * DM + h * 64;
        out_h[ob + lane]      = f2h(o0 * inv);
        out_h[ob + lane + 32] = f2h(o1 * inv);
    }
}

// ---------------------------------------------------------------------------
// h = LayerNorm(h + delta) * g + b; emits fp16 copy h_h.
// ---------------------------------------------------------------------------
__global__ void resid_ln_kernel(float* __restrict__ h, const float* __restrict__ delta,
                                const float* __restrict__ g, const float* __restrict__ b,
                                uint16_t* __restrict__ h_h) {
    int row = blockIdx.x;
    int tid = threadIdx.x;
    size_t base = (size_t)row * DM;
    float v[4];
    float s = 0.f;
#pragma unroll
    for (int i = 0; i < 4; i++) {
        int c = tid + i * 128;
        float x = h[base + c] + delta[base + c];
        v[i] = x; s += x;
    }
    __shared__ float red[4];
    for (int o = 16; o; o >>= 1) s += __shfl_xor_sync(0xffffffffu, s, o);
    if ((tid & 31) == 0) red[tid >> 5] = s;
    __syncthreads();
    float mean = (red[0] + red[1] + red[2] + red[3]) * (1.f / 512.f);
    __syncthreads();
    float s2 = 0.f;
#pragma unroll
    for (int i = 0; i < 4; i++) { float d = v[i] - mean; s2 += d * d; }
    for (int o = 16; o; o >>= 1) s2 += __shfl_xor_sync(0xffffffffu, s2, o);
    if ((tid & 31) == 0) red[tid >> 5] = s2;
    __syncthreads();
    float var = (red[0] + red[1] + red[2] + red[3]) * (1.f / 512.f);
    float rstd = rsqrtf(var + 1e-5f);
#pragma unroll
    for (int i = 0; i < 4; i++) {
        int c = tid + i * 128;
        float o = (v[i] - mean) * rstd * g[c] + b[c];
        h[base + c]   = o;
        h_h[base + c] = f2h(o);
    }
}

// ---------------------------------------------------------------------------
// FINAL layer: LayerNorm(h + delta)*g + b, then dot with Wout -> scal_out.
// ---------------------------------------------------------------------------
__global__ void resid_ln_out_kernel(const float* __restrict__ h, const float* __restrict__ delta,
                                    const float* __restrict__ g, const float* __restrict__ b,
                                    const float* __restrict__ Wout, float* __restrict__ out) {
    int row = blockIdx.x;
    int tid = threadIdx.x;
    size_t base = (size_t)row * DM;
    float v[4];
    float s = 0.f;
#pragma unroll
    for (int i = 0; i < 4; i++) {
        int c = tid + i * 128;
        float x = h[base + c] + delta[base + c];
        v[i] = x; s += x;
    }
    __shared__ float red[4];
    for (int o = 16; o; o >>= 1) s += __shfl_xor_sync(0xffffffffu, s, o);
    if ((tid & 31) == 0) red[tid >> 5] = s;
    __syncthreads();
    float mean = (red[0] + red[1] + red[2] + red[3]) * (1.f / 512.f);
    __syncthreads();
    float s2 = 0.f;
#pragma unroll
    for (int i = 0; i < 4; i++) { float d = v[i] - mean; s2 += d * d; }
    for (int o = 16; o; o >>= 1) s2 += __shfl_xor_sync(0xffffffffu, s2, o);
    if ((tid & 31) == 0) red[tid >> 5] = s2;
    __syncthreads();
    float var = (red[0] + red[1] + red[2] + red[3]) * (1.f / 512.f);
    float rstd = rsqrtf(var + 1e-5f);
    float dot = 0.f;
#pragma unroll
    for (int i = 0; i < 4; i++) {
        int c = tid + i * 128;
        float o = (v[i] - mean) * rstd * g[c] + b[c];
        dot += o * Wout[c];
    }
    __syncthreads();
    for (int o = 16; o; o >>= 1) dot += __shfl_xor_sync(0xffffffffu, dot, o);
    if ((tid & 31) == 0) red[tid >> 5] = dot;
    __syncthreads();
    if (tid == 0) out[row] = red[0] + red[1] + red[2] + red[3];
}

// ---------------------------------------------------------------------------
// Weight prep
// ---------------------------------------------------------------------------
// Stacked SAGE weights, transposed to [N][K] fp16.
// wc1T[n][k] (K=256): k<128 -> W1s[k][n], else W1n[k-128][n]
// wc2T[n][k] (K=512): k<256 -> W2s[k][n], else W2n[k-256][n]
__global__ void prep_wcT_kernel(const float* __restrict__ W1s, const float* __restrict__ W1n,
                                const float* __restrict__ W2s, const float* __restrict__ W2n,
                                uint16_t* __restrict__ wc1T, uint16_t* __restrict__ wc2T) {
    int i = blockIdx.x * blockDim.x + threadIdx.x;
    if (i < 256 * 256) {
        int n = i >> 8, k = i & 255;
        float v = (k < 128) ? W1s[k * 256 + n] : W1n[(k - 128) * 256 + n];
        wc1T[(size_t)n * 256 + k] = f2h(v);
    }
    if (i < 256 * 512) {
        int n = i >> 9, k = i & 511;
        float v = (k < 256) ? W2s[k * 256 + n] : W2n[(k - 256) * 256 + n];
        wc2T[(size_t)n * 512 + k] = f2h(v);
    }
}

__global__ void prep_wqkvT_kernel(const float* __restrict__ Wq, const float* __restrict__ Wk,
                                  const float* __restrict__ Wv,
                                  const float* __restrict__ bq, const float* __restrict__ bk,
                                  const float* __restrict__ bv,
                                  uint16_t* __restrict__ Th, float* __restrict__ bqkv) {
    long i = (long)blockIdx.x * blockDim.x + threadIdx.x;
    const long tot = 2L * 1536 * 512;
    if (i < tot) {
        int l = (int)(i / (1536L * 512));
        long rem = i % (1536L * 512);
        int n = (int)(rem / 512), k = (int)(rem % 512);
        const float* W = (n < 512) ? Wq : (n < 1024) ? Wk : Wv;
        int nn = n & 511;
        Th[i] = f2h(W[(size_t)l * 512 * 512 + (size_t)k * 512 + nn]);
    }
    if (i < 2 * 1536) {
        int l = (int)(i / 1536), c = (int)(i % 1536);
        float v;
        if (c < 512)       v = bq[l * 512 + c];
        else if (c < 1024) v = bk[l * 512 + c - 512];
        else               v = bv[l * 512 + c - 1024];
        bqkv[i] = v;
    }
}

__global__ void prep_wT_kernel(const float* __restrict__ W, uint16_t* __restrict__ Th,
                               int K, int N, int L) {
    long i = (long)blockIdx.x * blockDim.x + threadIdx.x;
    long tot = (long)L * K * N;
    if (i >= tot) return;
    long per = (long)K * N;
    int l = (int)(i / per);
    long rem = i % per;
    int n = (int)(rem / K), k = (int)(rem % K);
    Th[i] = f2h(W[(size_t)l * per + (size_t)k * N + n]);
}

// ---------------------------------------------------------------------------
// Host driver
// ---------------------------------------------------------------------------
extern "C" void kernel_launch(void* const* d_in, const int* in_sizes, int n_in,
                              void* d_out, int out_size) {
    const float* x_i   = (const float*)d_in[0];
    const float* x_j   = (const float*)d_in[1];
    const int*   src_i = (const int*)d_in[2];
    const int*   dst_i = (const int*)d_in[3];
    const int*   src_j = (const int*)d_in[4];
    const int*   dst_j = (const int*)d_in[5];
    const int*   idx_i = (const int*)d_in[6];
    const int*   idx_j = (const int*)d_in[7];
    const float* W1s = (const float*)d_in[8];
    const float* W1n = (const float*)d_in[9];
    const float* b1  = (const float*)d_in[10];
    const float* W2s = (const float*)d_in[11];
    const float* W2n = (const float*)d_in[12];
    const float* b2  = (const float*)d_in[13];
    const float* Wq  = (const float*)d_in[14];
    const float* Wk  = (const float*)d_in[15];
    const float* Wv  = (const float*)d_in[16];
    const float* bq  = (const float*)d_in[17];
    const float* bk  = (const float*)d_in[18];
    const float* bv  = (const float*)d_in[19];
    const float* Wo  = (const float*)d_in[20];
    const float* bo  = (const float*)d_in[21];
    const float* Wf1 = (const float*)d_in[22];
    const float* bf1 = (const float*)d_in[23];
    const float* Wf2 = (const float*)d_in[24];
    const float* bf2 = (const float*)d_in[25];
    const float* g1  = (const float*)d_in[26];
    const float* bg1 = (const float*)d_in[27];
    const float* g2  = (const float*)d_in[28];
    const float* bg2 = (const float*)d_in[29];
    const float* Wout= (const float*)d_in[30];

    void* p;
    cudaGetSymbolAddress(&p, g_sg16);  uint16_t* SG = (uint16_t*)p;
    cudaGetSymbolAddress(&p, g_bqkv);  float*    bqkv = (float*)p;
    cudaGetSymbolAddress(&p, g_act);   float*    AB = (float*)p;
    cudaGetSymbolAddress(&p, g_h16);   uint16_t* HB = (uint16_t*)p;
    cudaGetSymbolAddress(&p, g_iblob); int*      IB = (int*)p;

    uint16_t* bufA = SG + G_BUFA;
    uint16_t* h1   = SG + G_H1;
    uint16_t* bufB = SG + G_BUFB;            // alias of bufA (disjoint lifetime)
    float*    h2   = (float*)(SG + G_H1);    // alias of h1 (disjoint lifetime)

    float* hbuf  = AB + A_H;
    float* delta = AB + A_DELTA;

    uint16_t* h_h    = HB + H_HH;
    uint16_t* qkv_h  = HB + H_QKV;
    uint16_t* tmp_h  = HB + H_TMP;
    uint16_t* ffb_h  = HB + H_FFB;
    uint16_t* wqkv_h = HB + H_WQKV;
    uint16_t* wo_h   = HB + H_WO;
    uint16_t* wf1_h  = HB + H_WF1;
    uint16_t* wf2_h  = HB + H_WF2;
    uint16_t* wc1T   = HB + H_WC1T;
    uint16_t* wc2T   = HB + H_WC2T;

    int* deg  = IB + I_DEG;
    int* cur  = IB + I_CUR;
    int* off  = IB + I_OFF;
    int* csrc = IB + I_CSR;

    float* att_out  = (float*)d_out;
    float* scal_out = att_out + (size_t)NTOK * DM;

    // ---- weight prep ----
    prep_wcT_kernel<<<(256 * 512 + 255) / 256, 256>>>(W1s, W1n, W2s, W2n, wc1T, wc2T);
    prep_wqkvT_kernel<<<(2 * 1536 * 512 + 255) / 256, 256>>>(
        Wq, Wk, Wv, bq, bk, bv, wqkv_h, bqkv);
    prep_wT_kernel<<<(2 * 512 * 512 + 255) / 256, 256>>>(Wo, wo_h, 512, 512, 2);
    prep_wT_kernel<<<(2 * 512 * 2048 + 255) / 256, 256>>>(Wf1, wf1_h, 512, 2048, 2);
    prep_wT_kernel<<<(2 * 2048 * 512 + 255) / 256, 256>>>(Wf2, wf2_h, 2048, 512, 2);

    // ---- batched CSR for all NG graphs ----
    cudaMemsetAsync(IB, 0, (size_t)2 * NG * NN * sizeof(int));   // deg + cur
    hist_b_kernel<<<dim3((EE + 255) / 256, NG), 256>>>(dst_i, dst_j, deg);
    scan_b_kernel<<<NG, 1024>>>(deg, off);
    fill_b_kernel<<<dim3((EE + 255) / 256, NG), 256>>>(src_i, src_j, dst_i, dst_j, off, cur, csrc);

    // ---- GraphSAGE (fp16 GEMMs), single batched pass, selected-only layer 2 ----
    build_A1_kernel<<<dim3(NN / 4, NG), 128>>>(x_i, x_j, off, csrc, bufA);
    fp16_gemm_kernel<1, 1><<<dim3(2, HB1 / 128), 256>>>(
        bufA, wc1T, b1, nullptr, h1, HB1, 256, 256);
    build_A2_kernel<<<dim3(PP / 2, NG), 128>>>(h1, idx_i, idx_j, off, csrc, bufB);
    fp16_gemm_kernel<0, 0><<<dim3(2, HB2 / 128), 256>>>(
        bufB, wc2T, b2, h2, nullptr, HB2, 512, 256);
    gather_norm2_kernel<<<dim3(PP, NG), 256>>>(h2, att_out, hbuf, h_h);

    // ---- Transformer (fp16 tensor-core GEMMs, fp32 accumulate) ----
    for (int l = 0; l < NLAY; l++) {
        fp16_gemm_kernel<0, 1><<<dim3(12, NTOK / 128), 256>>>(
            h_h, wqkv_h + (size_t)l * 1536 * 512, bqkv + l * 1536,
            nullptr, qkv_h, NTOK, 512, 1536);
        attn_kernel<<<PP * NHEAD, 128>>>(qkv_h, tmp_h);
        fp16_gemm_kernel<0, 0><<<dim3(4, NTOK / 128), 256>>>(
            tmp_h, wo_h + (size_t)l * 512 * 512, bo + l * 512,
            delta, nullptr, NTOK, 512, 512);
        resid_ln_kernel<<<NTOK, 128>>>(hbuf, delta, g1 + l * 512, bg1 + l * 512, h_h);
        fp16_gemm_kernel<1, 1><<<dim3(16, NTOK / 128), 256>>>(
            h_h, wf1_h + (size_t)l * 2048 * 512, bf1 + l * 2048,
            nullptr, ffb_h, NTOK, 512, 2048);
        fp16_gemm_kernel<0, 0><<<dim3(4, NTOK / 128), 256>>>(
            ffb_h, wf2_h + (size_t)l * 512 * 2048, bf2 + l * 512,
            delta, nullptr, NTOK, 2048, 512);
        if (l < NLAY - 1) {
            resid_ln_kernel<<<NTOK, 128>>>(hbuf, delta, g2 + l * 512, bg2 + l * 512, h_h);
        } else {
            resid_ln_out_kernel<<<NTOK, 128>>>(hbuf, delta, g2 + l * 512, bg2 + l * 512,
                                               Wout, scal_out);
        }
    }
}